// round 13
// baseline (speedup 1.0000x reference)
#include <cuda_runtime.h>
#include <cuda_fp16.h>
#include <math.h>
#include <stdint.h>

#define NN 100000
#define EE 3200000
#define EA (EE + NN)
#define FIN 78
#define FG 256
#define FH 128
#define NBLK 98   // ceil(NN / 1024)

// ---------------- scratch (device globals; no allocation) ----------------
__device__ __half d_mx16[(size_t)NN * 80];
__device__ __half d_catA[(size_t)NN * 512];   // [x1 | h1]
__device__ __half d_catB[(size_t)NN * 512];   // [x2 | h2]
__device__ __half d_agg[(size_t)NN * 512];
__device__ __half d_xt[(size_t)NN * 128];
__device__ __half d_ef[(size_t)NN * 128];
__device__ __half d_hy16[(size_t)NN * 128];
__device__ __half d_w1h[FIN * 512];
__device__ __half d_w2h[256 * 512];
__device__ __half d_w3h[256 * 512];
__device__ __half d_bch[512 * 256];
__device__ __half d_th1h[334 * 128];
__device__ __half d_th2h[128 * 128];
__device__ float d_cb[256];
__device__ float d_wv[256 * 4];
__device__ float d_asrc[NN * 2];
__device__ float d_adst[NN * 2];
__device__ int csrA_off[NN + 1]; __device__ int csrA_val[EA];
__device__ int csrC_off[NN + 1]; __device__ int csrC_val[EE];
__device__ int cntA[NN], cntC[NN];
__device__ int curA[NN], curC[NN];
__device__ int d_part[2][NBLK + 2];
__device__ float d_binv[NN], d_dinv[NN];

// ---------------- CSR construction ----------------
__global__ void zero_counts_kernel() {
    int i = blockIdx.x * blockDim.x + threadIdx.x;
    if (i < NN) { cntA[i] = 0; cntC[i] = 0; }
}

__global__ void count_kernel(const int* __restrict__ ei) {
    int i = blockIdx.x * blockDim.x + threadIdx.x;
    if (i >= EE) return;
    int s = ei[i];
    int d = ei[EE + i];
    atomicAdd(&cntA[d], 1);
    atomicAdd(&cntC[s], 1);
}

__global__ void scan_p1() {
    int a = blockIdx.y;
    int i = blockIdx.x * 1024 + threadIdx.x;
    int v = 0;
    if (i < NN) v = (a == 0) ? (cntA[i] + 1) : cntC[i];
    int lane = threadIdx.x & 31, wid = threadIdx.x >> 5;
    #pragma unroll
    for (int d = 16; d; d >>= 1) v += __shfl_down_sync(0xFFFFFFFFu, v, d);
    __shared__ int ws[32];
    if (lane == 0) ws[wid] = v;
    __syncthreads();
    if (wid == 0) {
        int x = ws[lane];
        #pragma unroll
        for (int d = 16; d; d >>= 1) x += __shfl_down_sync(0xFFFFFFFFu, x, d);
        if (lane == 0) d_part[a][blockIdx.x] = x;
    }
}

__global__ void scan_p2() {
    int a = blockIdx.x;
    int t = threadIdx.x;
    int v = (t < NBLK) ? d_part[a][t] : 0;
    int lane = t & 31, wid = t >> 5;
    int x = v;
    #pragma unroll
    for (int d = 1; d < 32; d <<= 1) {
        int y = __shfl_up_sync(0xFFFFFFFFu, x, d);
        if (lane >= d) x += y;
    }
    __shared__ int ws[4];
    if (lane == 31) ws[wid] = x;
    __syncthreads();
    int off = 0;
    for (int w = 0; w < wid; w++) off += ws[w];
    if (t < NBLK) d_part[a][t] = off + x - v;
}

__global__ void scan_p3() {
    int a = blockIdx.y;
    int i = blockIdx.x * 1024 + threadIdx.x;
    int raw = 0;
    if (i < NN) raw = (a == 0) ? cntA[i] : cntC[i];
    int v = raw + ((a == 0 && i < NN) ? 1 : 0);
    int lane = threadIdx.x & 31, wid = threadIdx.x >> 5;
    int x = v;
    #pragma unroll
    for (int d = 1; d < 32; d <<= 1) {
        int y = __shfl_up_sync(0xFFFFFFFFu, x, d);
        if (lane >= d) x += y;
    }
    __shared__ int ws[32];
    if (lane == 31) ws[wid] = x;
    __syncthreads();
    if (wid == 0) {
        int w = ws[lane];
        #pragma unroll
        for (int d = 1; d < 32; d <<= 1) {
            int y = __shfl_up_sync(0xFFFFFFFFu, w, d);
            if (lane >= d) w += y;
        }
        ws[lane] = w;
    }
    __syncthreads();
    int excl = (wid ? ws[wid - 1] : 0) + x - v + d_part[a][blockIdx.x];
    if (i < NN) {
        if (a == 0) {
            csrA_off[i] = excl;
            curA[i] = excl;
            csrA_val[excl + raw] = i;
            d_binv[i] = raw > 0 ? 1.0f / (float)raw : 0.0f;
        } else {
            csrC_off[i] = excl;
            curC[i] = excl;
            d_dinv[i] = raw > 0 ? 1.0f / (float)raw : 0.0f;
        }
    }
    if (i == NN - 1) {
        if (a == 0) csrA_off[NN] = excl + v;
        else csrC_off[NN] = excl + v;
    }
}

__global__ void fill_kernel(const int* __restrict__ ei) {
    int i = blockIdx.x * blockDim.x + threadIdx.x;
    if (i >= EE) return;
    int s = ei[i];
    int d = ei[EE + i];
    csrA_val[atomicAdd(&curA[d], 1)] = s;
    csrC_val[atomicAdd(&curC[s], 1)] = d;
}

// ---------------- merged weight conversion ----------------
// sections (in float2 units): W1, W2, W3, th1, th2, bc(+cb)
#define S_W1 (FIN * 512 / 2)
#define S_W2 (256 * 512 / 2)
#define S_TH1 (334 * 128 / 2)
#define S_TH2 (128 * 128 / 2)
#define CV_TOT (S_W1 + 2 * S_W2 + S_TH1 + S_TH2 + 512 * 256 / 2)
__global__ void convert_all_kernel(const float* __restrict__ W1, const float* __restrict__ W2,
                                   const float* __restrict__ W3, const float* __restrict__ th1,
                                   const float* __restrict__ th2,
                                   const float* __restrict__ fc1w, const float* __restrict__ fc2w,
                                   const float* __restrict__ fc1b, const float* __restrict__ fc2b) {
    int i = blockIdx.x * blockDim.x + threadIdx.x;
    if (i >= CV_TOT) return;
    if (i < S_W1) {
        float2 v = ((const float2*)W1)[i];
        ((__half2*)d_w1h)[i] = __floats2half2_rn(v.x, v.y);
        return;
    }
    i -= S_W1;
    if (i < S_W2) {
        float2 v = ((const float2*)W2)[i];
        ((__half2*)d_w2h)[i] = __floats2half2_rn(v.x, v.y);
        return;
    }
    i -= S_W2;
    if (i < S_W2) {
        float2 v = ((const float2*)W3)[i];
        ((__half2*)d_w3h)[i] = __floats2half2_rn(v.x, v.y);
        return;
    }
    i -= S_W2;
    if (i < S_TH1) {
        float2 v = ((const float2*)th1)[i];
        ((__half2*)d_th1h)[i] = __floats2half2_rn(v.x, v.y);
        return;
    }
    i -= S_TH1;
    if (i < S_TH2) {
        float2 v = ((const float2*)th2)[i];
        ((__half2*)d_th2h)[i] = __floats2half2_rn(v.x, v.y);
        return;
    }
    i -= S_TH2;
    // bc: element pair (2*i, 2*i+1) of the 512x256 fused gate weight
    int idx = i * 2;
    int k = idx >> 8, n0 = idx & 255;
    float va = (k < 256) ? fc1w[n0 * 256 + k] : fc2w[n0 * 256 + (k - 256)];
    float vb = (k < 256) ? fc1w[(n0 + 1) * 256 + k] : fc2w[(n0 + 1) * 256 + (k - 256)];
    ((__half2*)d_bch)[i] = __floats2half2_rn(va, vb);
    if (idx < 256) {
        d_cb[idx] = fc1b[idx] + fc2b[idx];
        d_cb[idx + 1] = fc1b[idx + 1] + fc2b[idx + 1];
    }
}

__global__ void conv_mx_kernel(const float* __restrict__ x) {
    int idx = blockIdx.x * blockDim.x + threadIdx.x;
    if (idx >= NN * 40) return;
    int n = idx / 40, c2 = idx % 40;
    float a = 0.f, b = 0.f;
    int c = c2 * 2;
    if (c < FIN) a = x[(size_t)n * FIN + c];
    if (c + 1 < FIN) b = x[(size_t)n * FIN + c + 1];
    ((__half2*)d_mx16)[idx] = __floats2half2_rn(a, b);
}

// ---------------- fp16 tensor-core GEMM (m16n8k16 + ldmatrix + 3-stage cp.async) ----------------
__device__ __forceinline__ void mma_f16(float* c, const uint32_t* a, uint32_t b0, uint32_t b1) {
    asm volatile(
        "mma.sync.aligned.m16n8k16.row.col.f32.f16.f16.f32 "
        "{%0,%1,%2,%3},{%4,%5,%6,%7},{%8,%9},{%0,%1,%2,%3};"
        : "+f"(c[0]), "+f"(c[1]), "+f"(c[2]), "+f"(c[3])
        : "r"(a[0]), "r"(a[1]), "r"(a[2]), "r"(a[3]), "r"(b0), "r"(b1));
}

__device__ __forceinline__ void ldsm_x4(uint32_t& r0, uint32_t& r1, uint32_t& r2, uint32_t& r3,
                                        uint32_t addr) {
    asm volatile("ldmatrix.sync.aligned.m8n8.x4.shared.b16 {%0,%1,%2,%3}, [%4];"
                 : "=r"(r0), "=r"(r1), "=r"(r2), "=r"(r3) : "r"(addr));
}

__device__ __forceinline__ void ldsm_x4t(uint32_t& r0, uint32_t& r1, uint32_t& r2, uint32_t& r3,
                                         uint32_t addr) {
    asm volatile("ldmatrix.sync.aligned.m8n8.x4.trans.shared.b16 {%0,%1,%2,%3}, [%4];"
                 : "=r"(r0), "=r"(r1), "=r"(r2), "=r"(r3) : "r"(addr));
}

__device__ __forceinline__ void cp8(uint32_t d, const void* s) {
    asm volatile("cp.async.ca.shared.global [%0], [%1], 8;" :: "r"(d), "l"(s));
}
__device__ __forceinline__ void cp8z(uint32_t d, const void* s, int sz) {
    asm volatile("cp.async.ca.shared.global [%0], [%1], 8, %2;" :: "r"(d), "l"(s), "r"(sz));
}
__device__ __forceinline__ void cp_commit() {
    asm volatile("cp.async.commit_group;");
}
template <int N>
__device__ __forceinline__ void cp_wait() {
    asm volatile("cp.async.wait_group %0;" :: "n"(N));
}

#define APITCH 80
#define BPITCH 272
#define ABYTES (128 * APITCH)
#define BBYTES (32 * BPITCH)
#define NSTAGE 3

// ASRC: 0 = fp32 A (+optional concat A2 fp32) [register path], 2 = fp16 A [cp.async path]
// EPI:  0 = v*scale+bias(+relu) -> optional fp32 Cf and fp16 Ch
//       2 = gate blend
template <int ASRC, int EPI>
__global__ __launch_bounds__(256) void gemm16_kernel(
    const void* __restrict__ Ap, int lda, int K1,
    const float* __restrict__ A2, int lda2,
    const __half* __restrict__ Hh, int ldhh,
    const __half* __restrict__ B1, const __half* __restrict__ B2, int ldb,
    int SP, int KV1, int KV2,
    float* __restrict__ Cf, int ldc,
    __half* __restrict__ Ch, int ldch,
    int M, int N, int Ktot,
    const float* __restrict__ bias, int relu, float scale,
    const float* __restrict__ molb)
{
    __shared__ __align__(16) uint8_t AsmB[NSTAGE * ABYTES];
    __shared__ __align__(16) uint8_t BsmB[NSTAGE * BBYTES];
    int tid = threadIdx.x;
    int lane = tid & 31, wid = tid >> 5;
    int wm = wid & 3, wn = wid >> 2;
    int row0 = blockIdx.y * 128, col0 = blockIdx.x * 128;
    int g = lane >> 2, tg = lane & 3;
    int l15 = lane & 15;
    int lhi = (lane & 16) ? 8 : 0;

    float acc[2][8][4];
    #pragma unroll
    for (int mi = 0; mi < 2; mi++)
        #pragma unroll
        for (int ni = 0; ni < 8; ni++)
            #pragma unroll
            for (int q = 0; q < 4; q++) acc[mi][ni][q] = 0.0f;

    const float* Af = (const float*)Ap;
    const __half* Ah = (const __half*)Ap;

    uint32_t aShm = (uint32_t)__cvta_generic_to_shared(AsmB);
    uint32_t bShm = (uint32_t)__cvta_generic_to_shared(BsmB);
    int T = (Ktot + 31) >> 5;

    auto computeTile = [&](int buf) {
        uint32_t aB = aShm + buf * ABYTES;
        uint32_t bB = bShm + buf * BBYTES;
        #pragma unroll
        for (int ks = 0; ks < 2; ks++) {
            uint32_t afr[2][4];
            #pragma unroll
            for (int mi = 0; mi < 2; mi++) {
                uint32_t addr = aB + (uint32_t)((wm * 32 + mi * 16 + l15) * APITCH
                                                + (ks * 16 + lhi) * 2);
                ldsm_x4(afr[mi][0], afr[mi][1], afr[mi][2], afr[mi][3], addr);
            }
            uint32_t bfr[8][2];
            #pragma unroll
            for (int p = 0; p < 4; p++) {
                uint32_t addr = bB + (uint32_t)((ks * 16 + l15) * BPITCH
                                                + (wn * 64 + p * 16 + lhi) * 2);
                ldsm_x4t(bfr[2 * p][0], bfr[2 * p][1], bfr[2 * p + 1][0], bfr[2 * p + 1][1], addr);
            }
            #pragma unroll
            for (int ni = 0; ni < 8; ni++) {
                mma_f16(acc[0][ni], afr[0], bfr[ni][0], bfr[ni][1]);
                mma_f16(acc[1][ni], afr[1], bfr[ni][0], bfr[ni][1]);
            }
        }
    };

    if (ASRC == 2) {
        auto issueTile = [&](int k0, int buf) {
            uint32_t aB = aShm + buf * ABYTES;
            uint32_t bB = bShm + buf * BBYTES;
            #pragma unroll
            for (int i = 0; i < 4; i++) {
                int l4 = tid + i * 256;
                int r = l4 >> 3, c4 = (l4 & 7) << 2;
                int grow = row0 + r;
                if (grow >= M) grow = M - 1;
                int gk = k0 + c4;
                cp8(aB + r * APITCH + c4 * 2, Ah + (size_t)grow * lda + gk);
            }
            #pragma unroll
            for (int i = 0; i < 4; i++) {
                int l4 = tid + i * 256;
                int k = l4 >> 5, n4 = (l4 & 31) << 2;
                int kk = k0 + k;
                const __half* src = B1;
                int sz = 0;
                if (kk < SP) {
                    if (kk < KV1) { src = B1 + (size_t)kk * ldb + col0 + n4; sz = 8; }
                } else if (kk < Ktot) {
                    int j = kk - SP;
                    if (j < KV2) { src = B2 + (size_t)j * ldb + col0 + n4; sz = 8; }
                }
                cp8z(bB + k * BPITCH + n4 * 2, src, sz);
            }
            cp_commit();
        };
        issueTile(0, 0);
        if (T > 1) issueTile(32, 1);
        for (int t = 0; t < T; t++) {
            int buf = t % NSTAGE;
            if (t + 2 < T) {
                issueTile((t + 2) << 5, (t + 2) % NSTAGE);
                cp_wait<2>();
            } else if (t + 1 < T) {
                cp_wait<1>();
            } else {
                cp_wait<0>();
            }
            __syncthreads();
            computeTile(buf);
            __syncthreads();
        }
    } else {
        float4 raf[4];
        uint2 rbh[4];
        auto loadA = [&](int k0) {
            #pragma unroll
            for (int i = 0; i < 4; i++) {
                int l4 = tid + i * 256;
                int r = l4 >> 3, c4 = (l4 & 7) << 2;
                int grow = row0 + r, gk = k0 + c4;
                float4 v = make_float4(0.f, 0.f, 0.f, 0.f);
                if (grow < M) {
                    if (gk + 3 < K1) {
                        v = *(const float4*)(Af + (size_t)grow * lda + gk);
                    } else {
                        float* pv = &v.x;
                        #pragma unroll
                        for (int j = 0; j < 4; j++) {
                            int kk = gk + j;
                            float x = 0.0f;
                            if (kk < K1) x = Af[(size_t)grow * lda + kk];
                            else if (kk < Ktot) x = A2[(size_t)grow * lda2 + (kk - K1)];
                            pv[j] = x;
                        }
                    }
                }
                raf[i] = v;
            }
        };
        auto storeA = [&](uint8_t* As) {
            #pragma unroll
            for (int i = 0; i < 4; i++) {
                int l4 = tid + i * 256;
                int r = l4 >> 3, c4 = (l4 & 7) << 2;
                __half2 h0 = __floats2half2_rn(raf[i].x, raf[i].y);
                __half2 h1 = __floats2half2_rn(raf[i].z, raf[i].w);
                uint2 u;
                u.x = *(uint32_t*)&h0;
                u.y = *(uint32_t*)&h1;
                *(uint2*)(As + r * APITCH + c4 * 2) = u;
            }
        };
        auto loadB = [&](int k0) {
            #pragma unroll
            for (int i = 0; i < 4; i++) {
                int l4 = tid + i * 256;
                int k = l4 >> 5, n4 = (l4 & 31) << 2;
                int kk = k0 + k;
                uint2 u = make_uint2(0u, 0u);
                if (kk < SP) {
                    if (kk < KV1) u = *(const uint2*)(B1 + (size_t)kk * ldb + col0 + n4);
                } else if (kk < Ktot) {
                    int j = kk - SP;
                    if (j < KV2) u = *(const uint2*)(B2 + (size_t)j * ldb + col0 + n4);
                }
                rbh[i] = u;
            }
        };
        auto storeB = [&](uint8_t* Bs) {
            #pragma unroll
            for (int i = 0; i < 4; i++) {
                int l4 = tid + i * 256;
                int k = l4 >> 5, n4 = (l4 & 31) << 2;
                *(uint2*)(Bs + k * BPITCH + n4 * 2) = rbh[i];
            }
        };
        loadA(0); loadB(0);
        storeA(AsmB); storeB(BsmB);
        __syncthreads();
        for (int t = 0; t < T; t++) {
            int buf = t & 1;
            bool more = (t + 1 < T);
            if (more) { loadA((t + 1) << 5); loadB((t + 1) << 5); }
            computeTile(buf);
            if (more) {
                storeA(AsmB + (buf ^ 1) * ABYTES);
                storeB(BsmB + (buf ^ 1) * BBYTES);
            }
            __syncthreads();
        }
    }

    // epilogue
    #pragma unroll
    for (int mi = 0; mi < 2; mi++) {
        int r0 = row0 + wm * 32 + mi * 16 + g;
        #pragma unroll
        for (int ni = 0; ni < 8; ni++) {
            int c = col0 + wn * 64 + ni * 8 + tg * 2;
            float v0 = acc[mi][ni][0], v1 = acc[mi][ni][1];
            float v2 = acc[mi][ni][2], v3 = acc[mi][ni][3];
            if (EPI == 0) {
                float b0v = bias ? bias[c] : 0.0f;
                float b1v = bias ? bias[c + 1] : 0.0f;
                v0 = v0 * scale + b0v; v1 = v1 * scale + b1v;
                v2 = v2 * scale + b0v; v3 = v3 * scale + b1v;
                if (relu) {
                    v0 = fmaxf(v0, 0.f); v1 = fmaxf(v1, 0.f);
                    v2 = fmaxf(v2, 0.f); v3 = fmaxf(v3, 0.f);
                }
                if (r0 < M) {
                    if (Cf) *(float2*)(Cf + (size_t)r0 * ldc + c) = make_float2(v0, v1);
                    if (Ch) *(__half2*)(Ch + (size_t)r0 * ldch + c) = __floats2half2_rn(v0, v1);
                }
                if (r0 + 8 < M) {
                    if (Cf) *(float2*)(Cf + (size_t)(r0 + 8) * ldc + c) = make_float2(v2, v3);
                    if (Ch) *(__half2*)(Ch + (size_t)(r0 + 8) * ldch + c) = __floats2half2_rn(v2, v3);
                }
            } else {
                const __half* Ah2 = (const __half*)Ap;
                float cb0 = bias[c] + molb[c];
                float cb1 = bias[c + 1] + molb[c + 1];
                #pragma unroll
                for (int hh = 0; hh < 2; hh++) {
                    int r = r0 + hh * 8;
                    if (r >= M) continue;
                    float va = hh ? v2 : v0, vb = hh ? v3 : v1;
                    float z0 = 1.0f / (1.0f + __expf(-(va + cb0)));
                    float z1 = 1.0f / (1.0f + __expf(-(vb + cb1)));
                    float2 xv = __half22float2(*(const __half2*)(Ah2 + (size_t)r * lda + c));
                    float2 hv = __half22float2(*(const __half2*)(Hh + (size_t)r * ldhh + c));
                    float o0 = z0 * xv.x + (1.0f - z0) * hv.x;
                    float o1 = z1 * xv.y + (1.0f - z1) * hv.y;
                    if (Cf) *(float2*)(Cf + (size_t)r * ldc + c) = make_float2(o0, o1);
                    if (Ch) *(__half2*)(Ch + (size_t)r * ldch + c) = __floats2half2_rn(o0, o1);
                }
            }
        }
    }
}

template <int ASRC, int EPI>
static void run_gemm(const void* A, int lda, int K1, const float* A2, int lda2,
                     const __half* Hh, int ldhh,
                     const __half* B1, const __half* B2, int ldb, int SP, int KV1, int KV2,
                     float* Cf, int ldc, __half* Ch, int ldch,
                     int M, int N, int Ktot,
                     const float* bias, int relu, float scale, const float* molb) {
    dim3 grid(N / 128, (M + 127) / 128);
    gemm16_kernel<ASRC, EPI><<<grid, 256>>>(
        A, lda, K1, A2, lda2, Hh, ldhh, B1, B2, ldb, SP, KV1, KV2,
        Cf, ldc, Ch, ldch, M, N, Ktot, bias, relu, scale, molb);
}

// ---------------- attention logits ----------------
__global__ void build_wv_kernel(const float* __restrict__ W, const float* __restrict__ as,
                                const float* __restrict__ ad) {
    int k = blockIdx.x, t = threadIdx.x;
    float w0 = W[(size_t)k * 512 + t], w1 = W[(size_t)k * 512 + 256 + t];
    float p0 = w0 * as[t], p1 = w1 * as[256 + t];
    float p2 = w0 * ad[t], p3 = w1 * ad[256 + t];
    __shared__ float red[8][4];
    int lane = t & 31, wid = t >> 5;
    #pragma unroll
    for (int d = 16; d; d >>= 1) {
        p0 += __shfl_down_sync(0xFFFFFFFFu, p0, d);
        p1 += __shfl_down_sync(0xFFFFFFFFu, p1, d);
        p2 += __shfl_down_sync(0xFFFFFFFFu, p2, d);
        p3 += __shfl_down_sync(0xFFFFFFFFu, p3, d);
    }
    if (lane == 0) { red[wid][0] = p0; red[wid][1] = p1; red[wid][2] = p2; red[wid][3] = p3; }
    __syncthreads();
    if (t == 0) {
        float r0 = 0, r1 = 0, r2 = 0, r3 = 0;
        #pragma unroll
        for (int w = 0; w < 8; w++) { r0 += red[w][0]; r1 += red[w][1]; r2 += red[w][2]; r3 += red[w][3]; }
        d_wv[k * 4 + 0] = r0; d_wv[k * 4 + 1] = r1; d_wv[k * 4 + 2] = r2; d_wv[k * 4 + 3] = r3;
    }
}

__global__ void attn2_kernel(const float* __restrict__ x, int K) {
    int warp = threadIdx.x >> 5, lane = threadIdx.x & 31;
    int n = blockIdx.x * 4 + warp;
    if (n >= NN) return;
    const float* xr = x + (size_t)n * K;
    float s0 = 0, s1 = 0, s2 = 0, s3 = 0;
    for (int c = lane; c < K; c += 32) {
        float xv = xr[c];
        float4 wv = ((const float4*)d_wv)[c];
        s0 += xv * wv.x; s1 += xv * wv.y; s2 += xv * wv.z; s3 += xv * wv.w;
    }
    #pragma unroll
    for (int d = 16; d; d >>= 1) {
        s0 += __shfl_down_sync(0xFFFFFFFFu, s0, d);
        s1 += __shfl_down_sync(0xFFFFFFFFu, s1, d);
        s2 += __shfl_down_sync(0xFFFFFFFFu, s2, d);
        s3 += __shfl_down_sync(0xFFFFFFFFu, s3, d);
    }
    if (lane == 0) {
        d_asrc[n * 2] = s0; d_asrc[n * 2 + 1] = s1;
        d_adst[n * 2] = s2; d_adst[n * 2 + 1] = s3;
    }
}

__global__ void attn2h_kernel(const __half* __restrict__ x, int ldh) {
    int warp = threadIdx.x >> 5, lane = threadIdx.x & 31;
    int n = blockIdx.x * 4 + warp;
    if (n >= NN) return;
    const __half2* xr = (const __half2*)(x + (size_t)n * ldh);
    float s0 = 0, s1 = 0, s2 = 0, s3 = 0;
    #pragma unroll
    for (int w = 0; w < 4; w++) {
        int c2 = lane + w * 32;
        float2 xv = __half22float2(xr[c2]);
        float4 wv0 = ((const float4*)d_wv)[c2 * 2];
        float4 wv1 = ((const float4*)d_wv)[c2 * 2 + 1];
        s0 += xv.x * wv0.x + xv.y * wv1.x;
        s1 += xv.x * wv0.y + xv.y * wv1.y;
        s2 += xv.x * wv0.z + xv.y * wv1.z;
        s3 += xv.x * wv0.w + xv.y * wv1.w;
    }
    #pragma unroll
    for (int d = 16; d; d >>= 1) {
        s0 += __shfl_down_sync(0xFFFFFFFFu, s0, d);
        s1 += __shfl_down_sync(0xFFFFFFFFu, s1, d);
        s2 += __shfl_down_sync(0xFFFFFFFFu, s2, d);
        s3 += __shfl_down_sync(0xFFFFFFFFu, s3, d);
    }
    if (lane == 0) {
        d_asrc[n * 2] = s0; d_asrc[n * 2 + 1] = s1;
        d_adst[n * 2] = s2; d_adst[n * 2 + 1] = s3;
    }
}

__device__ __forceinline__ float lrelu02(float v) { return v >= 0.0f ? v : 0.2f * v; }

// ---------------- fused no-max softmax + aggregate ----------------
__global__ void gat_agg80_kernel(const __half2* __restrict__ src,
                                 __half2* __restrict__ agg) {
    int n = blockIdx.x;
    int t = threadIdx.x;  // 64
    int lane = t & 31, wid = t >> 5;
    int s0 = csrA_off[n], s1 = csrA_off[n + 1];
    float2 adst = ((const float2*)d_adst)[n];
    __shared__ int ssrc[64];
    __shared__ float2 salp[64];
    __shared__ float2 ssum[2];
    float a0x = 0, a0y = 0, a1x = 0, a1y = 0, sum0 = 0, sum1 = 0;
    bool act = t < 40;
    for (int base = s0; base < s1; base += 64) {
        int cnt = min(64, s1 - base);
        __syncthreads();
        if (t < cnt) {
            int sidx = csrA_val[base + t];
            ssrc[t] = sidx;
            float2 as = ((const float2*)d_asrc)[sidx];
            float p0 = __expf(lrelu02(as.x + adst.x));
            float p1 = __expf(lrelu02(as.y + adst.y));
            salp[t] = make_float2(p0, p1);
            sum0 += p0; sum1 += p1;
        }
        __syncthreads();
        if (act) {
            #pragma unroll 2
            for (int j = 0; j < cnt; j++) {
                float2 f = __half22float2(src[(size_t)ssrc[j] * 40 + t]);
                float2 a = salp[j];
                a0x += a.x * f.x; a0y += a.x * f.y;
                a1x += a.y * f.x; a1y += a.y * f.y;
            }
        }
    }
    #pragma unroll
    for (int d = 16; d; d >>= 1) {
        sum0 += __shfl_xor_sync(0xFFFFFFFFu, sum0, d);
        sum1 += __shfl_xor_sync(0xFFFFFFFFu, sum1, d);
    }
    if (lane == 0) ssum[wid] = make_float2(sum0, sum1);
    __syncthreads();
    if (act) {
        float r0 = 1.0f / (ssum[0].x + ssum[1].x);
        float r1 = 1.0f / (ssum[0].y + ssum[1].y);
        agg[(size_t)n * 80 + t] = __floats2half2_rn(a0x * r0, a0y * r0);
        agg[(size_t)n * 80 + 40 + t] = __floats2half2_rn(a1x * r1, a1y * r1);
    }
}

__global__ void gat_agg256_kernel(const __half2* __restrict__ src, int ldh2,
                                  __half2* __restrict__ agg) {
    int n = blockIdx.x;
    int t = threadIdx.x;
    int lane = t & 31, wwid = t >> 5;
    int gid = t >> 6, tl = t & 63;
    int s0 = csrA_off[n], s1 = csrA_off[n + 1];
    float2 adst = ((const float2*)d_adst)[n];
    float h0[4] = {0, 0, 0, 0}, h1[4] = {0, 0, 0, 0};
    float sum0 = 0, sum1 = 0;
    __shared__ int ssrc[128];
    __shared__ float2 salp[128];
    __shared__ float red[64][8];
    __shared__ float2 ssum[4];
    for (int base = s0; base < s1; base += 128) {
        int cnt = min(128, s1 - base);
        __syncthreads();
        if (t < cnt) {
            int sidx = csrA_val[base + t];
            ssrc[t] = sidx;
            float2 as = ((const float2*)d_asrc)[sidx];
            float p0 = __expf(lrelu02(as.x + adst.x));
            float p1 = __expf(lrelu02(as.y + adst.y));
            salp[t] = make_float2(p0, p1);
            sum0 += p0; sum1 += p1;
        }
        __syncthreads();
        for (int j = gid; j < cnt; j += 2) {
            uint2 u = *(const uint2*)(src + (size_t)ssrc[j] * ldh2 + tl * 2);
            float2 g0 = __half22float2(*(__half2*)&u.x);
            float2 g1 = __half22float2(*(__half2*)&u.y);
            float2 a = salp[j];
            h0[0] += a.x * g0.x; h0[1] += a.x * g0.y; h0[2] += a.x * g1.x; h0[3] += a.x * g1.y;
            h1[0] += a.y * g0.x; h1[1] += a.y * g0.y; h1[2] += a.y * g1.x; h1[3] += a.y * g1.y;
        }
    }
    #pragma unroll
    for (int d = 16; d; d >>= 1) {
        sum0 += __shfl_xor_sync(0xFFFFFFFFu, sum0, d);
        sum1 += __shfl_xor_sync(0xFFFFFFFFu, sum1, d);
    }
    __syncthreads();
    if (lane == 0) ssum[wwid] = make_float2(sum0, sum1);
    if (gid == 1) {
        red[tl][0] = h0[0]; red[tl][1] = h0[1]; red[tl][2] = h0[2]; red[tl][3] = h0[3];
        red[tl][4] = h1[0]; red[tl][5] = h1[1]; red[tl][6] = h1[2]; red[tl][7] = h1[3];
    }
    __syncthreads();
    if (gid == 0) {
        float ts0 = ssum[0].x + ssum[1].x + ssum[2].x + ssum[3].x;
        float ts1 = ssum[0].y + ssum[1].y + ssum[2].y + ssum[3].y;
        float r0 = 1.0f / ts0, r1 = 1.0f / ts1;
        h0[0] += red[tl][0]; h0[1] += red[tl][1]; h0[2] += red[tl][2]; h0[3] += red[tl][3];
        h1[0] += red[tl][4]; h1[1] += red[tl][5]; h1[2] += red[tl][6]; h1[3] += red[tl][7];
        __half2* row = agg + (size_t)n * 256;
        row[tl * 2] = __floats2half2_rn(h0[0] * r0, h0[1] * r0);
        row[tl * 2 + 1] = __floats2half2_rn(h0[2] * r0, h0[3] * r0);
        row[128 + tl * 2] = __floats2half2_rn(h1[0] * r1, h1[1] * r1);
        row[128 + tl * 2 + 1] = __floats2half2_rn(h1[2] * r1, h1[3] * r1);
    }
}

// ---------------- hypergraph ----------------
template <bool OUTH>
__global__ void hyper_gather_kernel(const __half2* __restrict__ in, void* __restrict__ outp,
                                    int ostride, const float* __restrict__ bias,
                                    int which, int relu) {
    const int* off = which ? csrC_off : csrA_off;
    const int* val = which ? csrC_val : csrA_val;
    int n = blockIdx.x;
    int t = threadIdx.x;
    int gid = t >> 5, tl = t & 31;
    int s0 = off[n], s1 = off[n + 1];
    if (!which) s1 -= 1;
    float a[4] = {0, 0, 0, 0};
    __shared__ int sv[64];
    __shared__ float red[32][4];
    for (int base = s0; base < s1; base += 64) {
        int cnt = min(64, s1 - base);
        __syncthreads();
        if (t < cnt) sv[t] = val[base + t];
        __syncthreads();
        for (int j = gid; j < cnt; j += 2) {
            uint2 u = *(const uint2*)(in + (size_t)sv[j] * 64 + tl * 2);
            float2 g0 = __half22float2(*(__half2*)&u.x);
            float2 g1 = __half22float2(*(__half2*)&u.y);
            a[0] += g0.x; a[1] += g0.y; a[2] += g1.x; a[3] += g1.y;
        }
    }
    __syncthreads();
    if (gid == 1) { red[tl][0] = a[0]; red[tl][1] = a[1]; red[tl][2] = a[2]; red[tl][3] = a[3]; }
    __syncthreads();
    if (gid == 0) {
        a[0] += red[tl][0]; a[1] += red[tl][1]; a[2] += red[tl][2]; a[3] += red[tl][3];
        float inv = which ? d_dinv[n] : d_binv[n];
        #pragma unroll
        for (int q = 0; q < 4; q++) a[q] *= inv;
        if (bias) {
            a[0] += bias[tl * 4]; a[1] += bias[tl * 4 + 1];
            a[2] += bias[tl * 4 + 2]; a[3] += bias[tl * 4 + 3];
        }
        if (relu) {
            #pragma unroll
            for (int q = 0; q < 4; q++) a[q] = fmaxf(a[q], 0.f);
        }
        if (OUTH) {
            __half2* o = (__half2*)outp;
            o[(size_t)n * ostride + tl * 2] = __floats2half2_rn(a[0], a[1]);
            o[(size_t)n * ostride + tl * 2 + 1] = __floats2half2_rn(a[2], a[3]);
        } else {
            float2* o = (float2*)outp;
            o[(size_t)n * ostride + tl * 2] = make_float2(a[0], a[1]);
            o[(size_t)n * ostride + tl * 2 + 1] = make_float2(a[2], a[3]);
        }
    }
}

// ---------------- host side ----------------
extern "C" void kernel_launch(void* const* d_in, const int* in_sizes, int n_in,
                              void* d_out, int out_size) {
    const float* mol_x = (const float*)d_in[0];
    const int*   ei    = (const int*)d_in[1];
    const float* W1 = (const float*)d_in[3];
    const float* as1 = (const float*)d_in[4];
    const float* ad1 = (const float*)d_in[5];
    const float* b1 = (const float*)d_in[6];
    const float* W2 = (const float*)d_in[7];
    const float* as2 = (const float*)d_in[8];
    const float* ad2 = (const float*)d_in[9];
    const float* b2 = (const float*)d_in[10];
    const float* W3 = (const float*)d_in[11];
    const float* as3 = (const float*)d_in[12];
    const float* ad3 = (const float*)d_in[13];
    const float* b3 = (const float*)d_in[14];
    const float* fc1_w = (const float*)d_in[15];
    const float* fc1_b = (const float*)d_in[16];
    const float* fc2_w = (const float*)d_in[17];
    const float* fc2_b = (const float*)d_in[18];
    const float* mol_bias = (const float*)d_in[19];
    const float* theta1 = (const float*)d_in[20];
    const float* hb1 = (const float*)d_in[21];
    const float* theta2 = (const float*)d_in[22];
    const float* hb2 = (const float*)d_in[23];

    __half *p_mx, *p_catA, *p_catB, *p_agg, *p_xt, *p_ef, *p_hy16;
    __half *p_w1h, *p_w2h, *p_w3h, *p_bch, *p_th1h, *p_th2h;
    float *p_cb;
    cudaGetSymbolAddress((void**)&p_mx, d_mx16);
    cudaGetSymbolAddress((void**)&p_catA, d_catA);
    cudaGetSymbolAddress((void**)&p_catB, d_catB);
    cudaGetSymbolAddress((void**)&p_agg, d_agg);
    cudaGetSymbolAddress((void**)&p_xt, d_xt);
    cudaGetSymbolAddress((void**)&p_ef, d_ef);
    cudaGetSymbolAddress((void**)&p_hy16, d_hy16);
    cudaGetSymbolAddress((void**)&p_w1h, d_w1h);
    cudaGetSymbolAddress((void**)&p_w2h, d_w2h);
    cudaGetSymbolAddress((void**)&p_w3h, d_w3h);
    cudaGetSymbolAddress((void**)&p_bch, d_bch);
    cudaGetSymbolAddress((void**)&p_th1h, d_th1h);
    cudaGetSymbolAddress((void**)&p_th2h, d_th2h);
    cudaGetSymbolAddress((void**)&p_cb, d_cb);
    float* p_out = (float*)d_out;

    // ---- CSR build ----
    zero_counts_kernel<<<(NN + 255) / 256, 256>>>();
    count_kernel<<<(EE + 255) / 256, 256>>>(ei);
    scan_p1<<<dim3(NBLK, 2), 1024>>>();
    scan_p2<<<2, 128>>>();
    scan_p3<<<dim3(NBLK, 2), 1024>>>();
    fill_kernel<<<(EE + 255) / 256, 256>>>(ei);

    // ---- conversions (one kernel) ----
    conv_mx_kernel<<<(NN * 40 + 255) / 256, 256>>>(mol_x);
    convert_all_kernel<<<(CV_TOT + 255) / 256, 256>>>(W1, W2, W3, theta1, theta2,
                                                      fc1_w, fc2_w, fc1_b, fc2_b);

    // ---- GAT layer 1: h1 (fp16) = relu(gat(mol_x)) ----
    build_wv_kernel<<<FIN, 256>>>(W1, as1, ad1);
    attn2_kernel<<<(NN + 3) / 4, 128>>>(mol_x, FIN);
    gat_agg80_kernel<<<NN, 64>>>((const __half2*)p_mx, (__half2*)p_agg);
    run_gemm<2, 0>(p_agg, 160, 0, nullptr, 0, nullptr, 0, p_w1h, p_w1h + 256, 512, 80, FIN, FIN,
                   nullptr, 0, p_catA + 256, 512, NN, 256, 160, b1, 1, 0.5f, nullptr);

    // ---- GAT layer 2 ----
    build_wv_kernel<<<256, 256>>>(W2, as2, ad2);
    attn2h_kernel<<<(NN + 3) / 4, 128>>>(p_catA + 256, 512);
    gat_agg256_kernel<<<NN, 128>>>((const __half2*)(p_catA + 256), 256, (__half2*)p_agg);
    run_gemm<2, 0>(p_agg, 512, 0, nullptr, 0, nullptr, 0, p_w2h, p_w2h + 256, 512, 256, 256, 256,
                   nullptr, 0, p_catA, 512, NN, 256, 512, b2, 1, 0.5f, nullptr);
    run_gemm<2, 2>(p_catA, 512, 0, nullptr, 0, p_catA + 256, 512, p_bch, nullptr, 256, 512, 512, 0,
                   nullptr, 0, p_catB + 256, 512, NN, 256, 512, p_cb, 0, 1.0f, mol_bias);
    // h2 fp16 in catB[256:)

    // ---- GAT layer 3 ----
    build_wv_kernel<<<256, 256>>>(W3, as3, ad3);
    attn2h_kernel<<<(NN + 3) / 4, 128>>>(p_catB + 256, 512);
    gat_agg256_kernel<<<NN, 128>>>((const __half2*)(p_catB + 256), 256, (__half2*)p_agg);
    run_gemm<2, 0>(p_agg, 512, 0, nullptr, 0, nullptr, 0, p_w3h, p_w3h + 256, 512, 256, 256, 256,
                   nullptr, 0, p_catB, 512, NN, 256, 512, b3, 0, 0.5f, nullptr);
    run_gemm<2, 2>(p_catB, 512, 0, nullptr, 0, p_catB + 256, 512, p_bch, nullptr, 256, 512, 512, 0,
                   p_out, 384, nullptr, 0, NN, 256, 512, p_cb, 0, 1.0f, mol_bias);
    // final h fp32 in d_out[:, 0:256)

    // ---- hypergraph branch ----
    run_gemm<0, 0>(p_out, 384, 256, mol_x, FIN, nullptr, 0, p_th1h, nullptr, 128, 334, 334, 0,
                   nullptr, 0, p_xt, 128, NN, 128, 334, nullptr, 0, 1.0f, nullptr);
    hyper_gather_kernel<true ><<<NN, 64>>>((const __half2*)p_xt, p_ef, 64, nullptr, 0, 0);
    hyper_gather_kernel<true ><<<NN, 64>>>((const __half2*)p_ef, p_hy16, 64, hb1, 1, 1);
    run_gemm<2, 0>(p_hy16, 128, 0, nullptr, 0, nullptr, 0, p_th2h, nullptr, 128, 128, 128, 0,
                   nullptr, 0, p_xt, 128, NN, 128, 128, nullptr, 0, 1.0f, nullptr);
    hyper_gather_kernel<true ><<<NN, 64>>>((const __half2*)p_xt, p_ef, 64, nullptr, 0, 0);
    hyper_gather_kernel<false><<<NN, 64>>>((const __half2*)p_ef, (float2*)p_out + 128, 192,
                                           hb2, 1, 1);
}

// round 14
// speedup vs baseline: 1.0016x; 1.0016x over previous
#include <cuda_runtime.h>
#include <cuda_fp16.h>
#include <math.h>
#include <stdint.h>

#define NN 100000
#define EE 3200000
#define EA (EE + NN)
#define FIN 78
#define FG 256
#define FH 128
#define NBLK 98   // ceil(NN / 1024)

// ---------------- scratch (device globals; no allocation) ----------------
__device__ __half d_mx16[(size_t)NN * 80];
__device__ __half d_catA[(size_t)NN * 512];   // [x1 | h1]
__device__ __half d_catB[(size_t)NN * 512];   // [x2 | h2]
__device__ __half d_agg[(size_t)NN * 512];
__device__ __half d_xt[(size_t)NN * 128];
__device__ __half d_ef[(size_t)NN * 128];
__device__ __half d_hy16[(size_t)NN * 128];
__device__ __half d_w1h[FIN * 512];
__device__ __half d_w2h[256 * 512];
__device__ __half d_w3h[256 * 512];
__device__ __half d_bch[512 * 256];
__device__ __half d_th1h[334 * 128];
__device__ __half d_th2h[128 * 128];
__device__ float d_cb[256];
__device__ float d_wv3[3 * 256 * 4];
__device__ float d_asrc[NN * 2];
__device__ float d_adst[NN * 2];
__device__ int csrA_off[NN + 1]; __device__ int csrA_val[EA];
__device__ int csrC_off[NN + 1]; __device__ int csrC_val[EE];
__device__ int cntA[NN], cntC[NN];
__device__ int curA[NN], curC[NN];
__device__ int d_part[2][NBLK + 2];
__device__ float d_binv[NN], d_dinv[NN];

// ---------------- CSR construction ----------------
__global__ void zero_counts_kernel() {
    int i = blockIdx.x * blockDim.x + threadIdx.x;
    if (i < NN) { cntA[i] = 0; cntC[i] = 0; }
}

__global__ void count_kernel(const int* __restrict__ ei) {
    int i = blockIdx.x * blockDim.x + threadIdx.x;
    if (i >= EE) return;
    int s = ei[i];
    int d = ei[EE + i];
    atomicAdd(&cntA[d], 1);
    atomicAdd(&cntC[s], 1);
}

__global__ void scan_p1() {
    int a = blockIdx.y;
    int i = blockIdx.x * 1024 + threadIdx.x;
    int v = 0;
    if (i < NN) v = (a == 0) ? (cntA[i] + 1) : cntC[i];
    int lane = threadIdx.x & 31, wid = threadIdx.x >> 5;
    #pragma unroll
    for (int d = 16; d; d >>= 1) v += __shfl_down_sync(0xFFFFFFFFu, v, d);
    __shared__ int ws[32];
    if (lane == 0) ws[wid] = v;
    __syncthreads();
    if (wid == 0) {
        int x = ws[lane];
        #pragma unroll
        for (int d = 16; d; d >>= 1) x += __shfl_down_sync(0xFFFFFFFFu, x, d);
        if (lane == 0) d_part[a][blockIdx.x] = x;
    }
}

__global__ void scan_p2() {
    int a = blockIdx.x;
    int t = threadIdx.x;
    int v = (t < NBLK) ? d_part[a][t] : 0;
    int lane = t & 31, wid = t >> 5;
    int x = v;
    #pragma unroll
    for (int d = 1; d < 32; d <<= 1) {
        int y = __shfl_up_sync(0xFFFFFFFFu, x, d);
        if (lane >= d) x += y;
    }
    __shared__ int ws[4];
    if (lane == 31) ws[wid] = x;
    __syncthreads();
    int off = 0;
    for (int w = 0; w < wid; w++) off += ws[w];
    if (t < NBLK) d_part[a][t] = off + x - v;
}

__global__ void scan_p3() {
    int a = blockIdx.y;
    int i = blockIdx.x * 1024 + threadIdx.x;
    int raw = 0;
    if (i < NN) raw = (a == 0) ? cntA[i] : cntC[i];
    int v = raw + ((a == 0 && i < NN) ? 1 : 0);
    int lane = threadIdx.x & 31, wid = threadIdx.x >> 5;
    int x = v;
    #pragma unroll
    for (int d = 1; d < 32; d <<= 1) {
        int y = __shfl_up_sync(0xFFFFFFFFu, x, d);
        if (lane >= d) x += y;
    }
    __shared__ int ws[32];
    if (lane == 31) ws[wid] = x;
    __syncthreads();
    if (wid == 0) {
        int w = ws[lane];
        #pragma unroll
        for (int d = 1; d < 32; d <<= 1) {
            int y = __shfl_up_sync(0xFFFFFFFFu, w, d);
            if (lane >= d) w += y;
        }
        ws[lane] = w;
    }
    __syncthreads();
    int excl = (wid ? ws[wid - 1] : 0) + x - v + d_part[a][blockIdx.x];
    if (i < NN) {
        if (a == 0) {
            csrA_off[i] = excl;
            curA[i] = excl;
            csrA_val[excl + raw] = i;
            d_binv[i] = raw > 0 ? 1.0f / (float)raw : 0.0f;
        } else {
            csrC_off[i] = excl;
            curC[i] = excl;
            d_dinv[i] = raw > 0 ? 1.0f / (float)raw : 0.0f;
        }
    }
    if (i == NN - 1) {
        if (a == 0) csrA_off[NN] = excl + v;
        else csrC_off[NN] = excl + v;
    }
}

__global__ void fill_kernel(const int* __restrict__ ei) {
    int i = blockIdx.x * blockDim.x + threadIdx.x;
    if (i >= EE) return;
    int s = ei[i];
    int d = ei[EE + i];
    csrA_val[atomicAdd(&curA[d], 1)] = s;
    csrC_val[atomicAdd(&curC[s], 1)] = d;
}

// ---------------- merged weight conversion ----------------
#define S_W1 (FIN * 512 / 2)
#define S_W2 (256 * 512 / 2)
#define S_TH1 (334 * 128 / 2)
#define S_TH2 (128 * 128 / 2)
#define CV_TOT (S_W1 + 2 * S_W2 + S_TH1 + S_TH2 + 512 * 256 / 2)
__global__ void convert_all_kernel(const float* __restrict__ W1, const float* __restrict__ W2,
                                   const float* __restrict__ W3, const float* __restrict__ th1,
                                   const float* __restrict__ th2,
                                   const float* __restrict__ fc1w, const float* __restrict__ fc2w,
                                   const float* __restrict__ fc1b, const float* __restrict__ fc2b) {
    int i = blockIdx.x * blockDim.x + threadIdx.x;
    if (i >= CV_TOT) return;
    if (i < S_W1) {
        float2 v = ((const float2*)W1)[i];
        ((__half2*)d_w1h)[i] = __floats2half2_rn(v.x, v.y);
        return;
    }
    i -= S_W1;
    if (i < S_W2) {
        float2 v = ((const float2*)W2)[i];
        ((__half2*)d_w2h)[i] = __floats2half2_rn(v.x, v.y);
        return;
    }
    i -= S_W2;
    if (i < S_W2) {
        float2 v = ((const float2*)W3)[i];
        ((__half2*)d_w3h)[i] = __floats2half2_rn(v.x, v.y);
        return;
    }
    i -= S_W2;
    if (i < S_TH1) {
        float2 v = ((const float2*)th1)[i];
        ((__half2*)d_th1h)[i] = __floats2half2_rn(v.x, v.y);
        return;
    }
    i -= S_TH1;
    if (i < S_TH2) {
        float2 v = ((const float2*)th2)[i];
        ((__half2*)d_th2h)[i] = __floats2half2_rn(v.x, v.y);
        return;
    }
    i -= S_TH2;
    int idx = i * 2;
    int k = idx >> 8, n0 = idx & 255;
    float va = (k < 256) ? fc1w[n0 * 256 + k] : fc2w[n0 * 256 + (k - 256)];
    float vb = (k < 256) ? fc1w[(n0 + 1) * 256 + k] : fc2w[(n0 + 1) * 256 + (k - 256)];
    ((__half2*)d_bch)[i] = __floats2half2_rn(va, vb);
    if (idx < 256) {
        d_cb[idx] = fc1b[idx] + fc2b[idx];
        d_cb[idx + 1] = fc1b[idx + 1] + fc2b[idx + 1];
    }
}

__global__ void conv_mx_kernel(const float* __restrict__ x) {
    int idx = blockIdx.x * blockDim.x + threadIdx.x;
    if (idx >= NN * 40) return;
    int n = idx / 40, c2 = idx % 40;
    float a = 0.f, b = 0.f;
    int c = c2 * 2;
    if (c < FIN) a = x[(size_t)n * FIN + c];
    if (c + 1 < FIN) b = x[(size_t)n * FIN + c + 1];
    ((__half2*)d_mx16)[idx] = __floats2half2_rn(a, b);
}

// ---------------- fp16 tensor-core GEMM (m16n8k16 + ldmatrix + cp.async) ----------------
__device__ __forceinline__ void mma_f16(float* c, const uint32_t* a, uint32_t b0, uint32_t b1) {
    asm volatile(
        "mma.sync.aligned.m16n8k16.row.col.f32.f16.f16.f32 "
        "{%0,%1,%2,%3},{%4,%5,%6,%7},{%8,%9},{%0,%1,%2,%3};"
        : "+f"(c[0]), "+f"(c[1]), "+f"(c[2]), "+f"(c[3])
        : "r"(a[0]), "r"(a[1]), "r"(a[2]), "r"(a[3]), "r"(b0), "r"(b1));
}

__device__ __forceinline__ void ldsm_x4(uint32_t& r0, uint32_t& r1, uint32_t& r2, uint32_t& r3,
                                        uint32_t addr) {
    asm volatile("ldmatrix.sync.aligned.m8n8.x4.shared.b16 {%0,%1,%2,%3}, [%4];"
                 : "=r"(r0), "=r"(r1), "=r"(r2), "=r"(r3) : "r"(addr));
}

__device__ __forceinline__ void ldsm_x4t(uint32_t& r0, uint32_t& r1, uint32_t& r2, uint32_t& r3,
                                         uint32_t addr) {
    asm volatile("ldmatrix.sync.aligned.m8n8.x4.trans.shared.b16 {%0,%1,%2,%3}, [%4];"
                 : "=r"(r0), "=r"(r1), "=r"(r2), "=r"(r3) : "r"(addr));
}

__device__ __forceinline__ void cp8(uint32_t d, const void* s) {
    asm volatile("cp.async.ca.shared.global [%0], [%1], 8;" :: "r"(d), "l"(s));
}
__device__ __forceinline__ void cp8z(uint32_t d, const void* s, int sz) {
    asm volatile("cp.async.ca.shared.global [%0], [%1], 8, %2;" :: "r"(d), "l"(s), "r"(sz));
}
__device__ __forceinline__ void cp_commit() {
    asm volatile("cp.async.commit_group;");
}
template <int N>
__device__ __forceinline__ void cp_wait() {
    asm volatile("cp.async.wait_group %0;" :: "n"(N));
}

#define APITCH 80
#define BPITCH 272
#define ABYTES (128 * APITCH)
#define BBYTES (32 * BPITCH)
#define NSTAGE 3

template <int ASRC, int EPI>
__global__ __launch_bounds__(256) void gemm16_kernel(
    const void* __restrict__ Ap, int lda, int K1,
    const float* __restrict__ A2, int lda2,
    const __half* __restrict__ Hh, int ldhh,
    const __half* __restrict__ B1, const __half* __restrict__ B2, int ldb,
    int SP, int KV1, int KV2,
    float* __restrict__ Cf, int ldc,
    __half* __restrict__ Ch, int ldch,
    int M, int N, int Ktot,
    const float* __restrict__ bias, int relu, float scale,
    const float* __restrict__ molb)
{
    __shared__ __align__(16) uint8_t AsmB[NSTAGE * ABYTES];
    __shared__ __align__(16) uint8_t BsmB[NSTAGE * BBYTES];
    int tid = threadIdx.x;
    int lane = tid & 31, wid = tid >> 5;
    int wm = wid & 3, wn = wid >> 2;
    int row0 = blockIdx.y * 128, col0 = blockIdx.x * 128;
    int g = lane >> 2, tg = lane & 3;
    int l15 = lane & 15;
    int lhi = (lane & 16) ? 8 : 0;

    float acc[2][8][4];
    #pragma unroll
    for (int mi = 0; mi < 2; mi++)
        #pragma unroll
        for (int ni = 0; ni < 8; ni++)
            #pragma unroll
            for (int q = 0; q < 4; q++) acc[mi][ni][q] = 0.0f;

    const float* Af = (const float*)Ap;
    const __half* Ah = (const __half*)Ap;

    uint32_t aShm = (uint32_t)__cvta_generic_to_shared(AsmB);
    uint32_t bShm = (uint32_t)__cvta_generic_to_shared(BsmB);
    int T = (Ktot + 31) >> 5;

    auto computeTile = [&](int buf) {
        uint32_t aB = aShm + buf * ABYTES;
        uint32_t bB = bShm + buf * BBYTES;
        #pragma unroll
        for (int ks = 0; ks < 2; ks++) {
            uint32_t afr[2][4];
            #pragma unroll
            for (int mi = 0; mi < 2; mi++) {
                uint32_t addr = aB + (uint32_t)((wm * 32 + mi * 16 + l15) * APITCH
                                                + (ks * 16 + lhi) * 2);
                ldsm_x4(afr[mi][0], afr[mi][1], afr[mi][2], afr[mi][3], addr);
            }
            uint32_t bfr[8][2];
            #pragma unroll
            for (int p = 0; p < 4; p++) {
                uint32_t addr = bB + (uint32_t)((ks * 16 + l15) * BPITCH
                                                + (wn * 64 + p * 16 + lhi) * 2);
                ldsm_x4t(bfr[2 * p][0], bfr[2 * p][1], bfr[2 * p + 1][0], bfr[2 * p + 1][1], addr);
            }
            #pragma unroll
            for (int ni = 0; ni < 8; ni++) {
                mma_f16(acc[0][ni], afr[0], bfr[ni][0], bfr[ni][1]);
                mma_f16(acc[1][ni], afr[1], bfr[ni][0], bfr[ni][1]);
            }
        }
    };

    if (ASRC == 2) {
        auto issueTile = [&](int k0, int buf) {
            uint32_t aB = aShm + buf * ABYTES;
            uint32_t bB = bShm + buf * BBYTES;
            #pragma unroll
            for (int i = 0; i < 4; i++) {
                int l4 = tid + i * 256;
                int r = l4 >> 3, c4 = (l4 & 7) << 2;
                int grow = row0 + r;
                if (grow >= M) grow = M - 1;
                int gk = k0 + c4;
                cp8(aB + r * APITCH + c4 * 2, Ah + (size_t)grow * lda + gk);
            }
            #pragma unroll
            for (int i = 0; i < 4; i++) {
                int l4 = tid + i * 256;
                int k = l4 >> 5, n4 = (l4 & 31) << 2;
                int kk = k0 + k;
                const __half* src = B1;
                int sz = 0;
                if (kk < SP) {
                    if (kk < KV1) { src = B1 + (size_t)kk * ldb + col0 + n4; sz = 8; }
                } else if (kk < Ktot) {
                    int j = kk - SP;
                    if (j < KV2) { src = B2 + (size_t)j * ldb + col0 + n4; sz = 8; }
                }
                cp8z(bB + k * BPITCH + n4 * 2, src, sz);
            }
            cp_commit();
        };
        issueTile(0, 0);
        if (T > 1) issueTile(32, 1);
        for (int t = 0; t < T; t++) {
            int buf = t % NSTAGE;
            if (t + 2 < T) {
                issueTile((t + 2) << 5, (t + 2) % NSTAGE);
                cp_wait<2>();
            } else if (t + 1 < T) {
                cp_wait<1>();
            } else {
                cp_wait<0>();
            }
            __syncthreads();
            computeTile(buf);
            __syncthreads();
        }
    } else {
        float4 raf[4];
        uint2 rbh[4];
        auto loadA = [&](int k0) {
            #pragma unroll
            for (int i = 0; i < 4; i++) {
                int l4 = tid + i * 256;
                int r = l4 >> 3, c4 = (l4 & 7) << 2;
                int grow = row0 + r, gk = k0 + c4;
                float4 v = make_float4(0.f, 0.f, 0.f, 0.f);
                if (grow < M) {
                    if (gk + 3 < K1) {
                        v = *(const float4*)(Af + (size_t)grow * lda + gk);
                    } else {
                        float* pv = &v.x;
                        #pragma unroll
                        for (int j = 0; j < 4; j++) {
                            int kk = gk + j;
                            float x = 0.0f;
                            if (kk < K1) x = Af[(size_t)grow * lda + kk];
                            else if (kk < Ktot) x = A2[(size_t)grow * lda2 + (kk - K1)];
                            pv[j] = x;
                        }
                    }
                }
                raf[i] = v;
            }
        };
        auto storeA = [&](uint8_t* As) {
            #pragma unroll
            for (int i = 0; i < 4; i++) {
                int l4 = tid + i * 256;
                int r = l4 >> 3, c4 = (l4 & 7) << 2;
                __half2 h0 = __floats2half2_rn(raf[i].x, raf[i].y);
                __half2 h1 = __floats2half2_rn(raf[i].z, raf[i].w);
                uint2 u;
                u.x = *(uint32_t*)&h0;
                u.y = *(uint32_t*)&h1;
                *(uint2*)(As + r * APITCH + c4 * 2) = u;
            }
        };
        auto loadB = [&](int k0) {
            #pragma unroll
            for (int i = 0; i < 4; i++) {
                int l4 = tid + i * 256;
                int k = l4 >> 5, n4 = (l4 & 31) << 2;
                int kk = k0 + k;
                uint2 u = make_uint2(0u, 0u);
                if (kk < SP) {
                    if (kk < KV1) u = *(const uint2*)(B1 + (size_t)kk * ldb + col0 + n4);
                } else if (kk < Ktot) {
                    int j = kk - SP;
                    if (j < KV2) u = *(const uint2*)(B2 + (size_t)j * ldb + col0 + n4);
                }
                rbh[i] = u;
            }
        };
        auto storeB = [&](uint8_t* Bs) {
            #pragma unroll
            for (int i = 0; i < 4; i++) {
                int l4 = tid + i * 256;
                int k = l4 >> 5, n4 = (l4 & 31) << 2;
                *(uint2*)(Bs + k * BPITCH + n4 * 2) = rbh[i];
            }
        };
        loadA(0); loadB(0);
        storeA(AsmB); storeB(BsmB);
        __syncthreads();
        for (int t = 0; t < T; t++) {
            int buf = t & 1;
            bool more = (t + 1 < T);
            if (more) { loadA((t + 1) << 5); loadB((t + 1) << 5); }
            computeTile(buf);
            if (more) {
                storeA(AsmB + (buf ^ 1) * ABYTES);
                storeB(BsmB + (buf ^ 1) * BBYTES);
            }
            __syncthreads();
        }
    }

    // epilogue
    #pragma unroll
    for (int mi = 0; mi < 2; mi++) {
        int r0 = row0 + wm * 32 + mi * 16 + g;
        #pragma unroll
        for (int ni = 0; ni < 8; ni++) {
            int c = col0 + wn * 64 + ni * 8 + tg * 2;
            float v0 = acc[mi][ni][0], v1 = acc[mi][ni][1];
            float v2 = acc[mi][ni][2], v3 = acc[mi][ni][3];
            if (EPI == 0) {
                float b0v = bias ? bias[c] : 0.0f;
                float b1v = bias ? bias[c + 1] : 0.0f;
                v0 = v0 * scale + b0v; v1 = v1 * scale + b1v;
                v2 = v2 * scale + b0v; v3 = v3 * scale + b1v;
                if (relu) {
                    v0 = fmaxf(v0, 0.f); v1 = fmaxf(v1, 0.f);
                    v2 = fmaxf(v2, 0.f); v3 = fmaxf(v3, 0.f);
                }
                if (r0 < M) {
                    if (Cf) *(float2*)(Cf + (size_t)r0 * ldc + c) = make_float2(v0, v1);
                    if (Ch) *(__half2*)(Ch + (size_t)r0 * ldch + c) = __floats2half2_rn(v0, v1);
                }
                if (r0 + 8 < M) {
                    if (Cf) *(float2*)(Cf + (size_t)(r0 + 8) * ldc + c) = make_float2(v2, v3);
                    if (Ch) *(__half2*)(Ch + (size_t)(r0 + 8) * ldch + c) = __floats2half2_rn(v2, v3);
                }
            } else {
                const __half* Ah2 = (const __half*)Ap;
                float cb0 = bias[c] + molb[c];
                float cb1 = bias[c + 1] + molb[c + 1];
                #pragma unroll
                for (int hh = 0; hh < 2; hh++) {
                    int r = r0 + hh * 8;
                    if (r >= M) continue;
                    float va = hh ? v2 : v0, vb = hh ? v3 : v1;
                    float z0 = 1.0f / (1.0f + __expf(-(va + cb0)));
                    float z1 = 1.0f / (1.0f + __expf(-(vb + cb1)));
                    float2 xv = __half22float2(*(const __half2*)(Ah2 + (size_t)r * lda + c));
                    float2 hv = __half22float2(*(const __half2*)(Hh + (size_t)r * ldhh + c));
                    float o0 = z0 * xv.x + (1.0f - z0) * hv.x;
                    float o1 = z1 * xv.y + (1.0f - z1) * hv.y;
                    if (Cf) *(float2*)(Cf + (size_t)r * ldc + c) = make_float2(o0, o1);
                    if (Ch) *(__half2*)(Ch + (size_t)r * ldch + c) = __floats2half2_rn(o0, o1);
                }
            }
        }
    }
}

template <int ASRC, int EPI>
static void run_gemm(const void* A, int lda, int K1, const float* A2, int lda2,
                     const __half* Hh, int ldhh,
                     const __half* B1, const __half* B2, int ldb, int SP, int KV1, int KV2,
                     float* Cf, int ldc, __half* Ch, int ldch,
                     int M, int N, int Ktot,
                     const float* bias, int relu, float scale, const float* molb) {
    dim3 grid(N / 128, (M + 127) / 128);
    gemm16_kernel<ASRC, EPI><<<grid, 256>>>(
        A, lda, K1, A2, lda2, Hh, ldhh, B1, B2, ldb, SP, KV1, KV2,
        Cf, ldc, Ch, ldch, M, N, Ktot, bias, relu, scale, molb);
}

// ---------------- attention logits ----------------
// all three layers' wv in one launch; blockIdx.y = layer
__global__ void build_wv_all_kernel(const float* __restrict__ W1p,
                                    const float* __restrict__ W2p,
                                    const float* __restrict__ W3p,
                                    const float* __restrict__ as1, const float* __restrict__ ad1,
                                    const float* __restrict__ as2, const float* __restrict__ ad2,
                                    const float* __restrict__ as3, const float* __restrict__ ad3) {
    int layer = blockIdx.y;
    int k = blockIdx.x, t = threadIdx.x;
    const float* W = (layer == 0) ? W1p : (layer == 1) ? W2p : W3p;
    const float* as = (layer == 0) ? as1 : (layer == 1) ? as2 : as3;
    const float* ad = (layer == 0) ? ad1 : (layer == 1) ? ad2 : ad3;
    int K = (layer == 0) ? FIN : 256;
    if (k >= K) return;
    float w0 = W[(size_t)k * 512 + t], w1 = W[(size_t)k * 512 + 256 + t];
    float p0 = w0 * as[t], p1 = w1 * as[256 + t];
    float p2 = w0 * ad[t], p3 = w1 * ad[256 + t];
    __shared__ float red[8][4];
    int lane = t & 31, wid = t >> 5;
    #pragma unroll
    for (int d = 16; d; d >>= 1) {
        p0 += __shfl_down_sync(0xFFFFFFFFu, p0, d);
        p1 += __shfl_down_sync(0xFFFFFFFFu, p1, d);
        p2 += __shfl_down_sync(0xFFFFFFFFu, p2, d);
        p3 += __shfl_down_sync(0xFFFFFFFFu, p3, d);
    }
    if (lane == 0) { red[wid][0] = p0; red[wid][1] = p1; red[wid][2] = p2; red[wid][3] = p3; }
    __syncthreads();
    if (t == 0) {
        float r0 = 0, r1 = 0, r2 = 0, r3 = 0;
        #pragma unroll
        for (int w = 0; w < 8; w++) { r0 += red[w][0]; r1 += red[w][1]; r2 += red[w][2]; r3 += red[w][3]; }
        float* wv = d_wv3 + layer * 1024;
        wv[k * 4 + 0] = r0; wv[k * 4 + 1] = r1; wv[k * 4 + 2] = r2; wv[k * 4 + 3] = r3;
    }
}

__global__ void attn2_kernel(const float* __restrict__ x, int K, int layer) {
    int warp = threadIdx.x >> 5, lane = threadIdx.x & 31;
    int n = blockIdx.x * 4 + warp;
    if (n >= NN) return;
    const float4* wvp = (const float4*)(d_wv3 + layer * 1024);
    const float* xr = x + (size_t)n * K;
    float s0 = 0, s1 = 0, s2 = 0, s3 = 0;
    for (int c = lane; c < K; c += 32) {
        float xv = xr[c];
        float4 wv = wvp[c];
        s0 += xv * wv.x; s1 += xv * wv.y; s2 += xv * wv.z; s3 += xv * wv.w;
    }
    #pragma unroll
    for (int d = 16; d; d >>= 1) {
        s0 += __shfl_down_sync(0xFFFFFFFFu, s0, d);
        s1 += __shfl_down_sync(0xFFFFFFFFu, s1, d);
        s2 += __shfl_down_sync(0xFFFFFFFFu, s2, d);
        s3 += __shfl_down_sync(0xFFFFFFFFu, s3, d);
    }
    if (lane == 0) {
        d_asrc[n * 2] = s0; d_asrc[n * 2 + 1] = s1;
        d_adst[n * 2] = s2; d_adst[n * 2 + 1] = s3;
    }
}

__global__ void attn2h_kernel(const __half* __restrict__ x, int ldh, int layer) {
    int warp = threadIdx.x >> 5, lane = threadIdx.x & 31;
    int n = blockIdx.x * 4 + warp;
    if (n >= NN) return;
    const float4* wvp = (const float4*)(d_wv3 + layer * 1024);
    const __half2* xr = (const __half2*)(x + (size_t)n * ldh);
    float s0 = 0, s1 = 0, s2 = 0, s3 = 0;
    #pragma unroll
    for (int w = 0; w < 4; w++) {
        int c2 = lane + w * 32;
        float2 xv = __half22float2(xr[c2]);
        float4 wv0 = wvp[c2 * 2];
        float4 wv1 = wvp[c2 * 2 + 1];
        s0 += xv.x * wv0.x + xv.y * wv1.x;
        s1 += xv.x * wv0.y + xv.y * wv1.y;
        s2 += xv.x * wv0.z + xv.y * wv1.z;
        s3 += xv.x * wv0.w + xv.y * wv1.w;
    }
    #pragma unroll
    for (int d = 16; d; d >>= 1) {
        s0 += __shfl_down_sync(0xFFFFFFFFu, s0, d);
        s1 += __shfl_down_sync(0xFFFFFFFFu, s1, d);
        s2 += __shfl_down_sync(0xFFFFFFFFu, s2, d);
        s3 += __shfl_down_sync(0xFFFFFFFFu, s3, d);
    }
    if (lane == 0) {
        d_asrc[n * 2] = s0; d_asrc[n * 2 + 1] = s1;
        d_adst[n * 2] = s2; d_adst[n * 2 + 1] = s3;
    }
}

__device__ __forceinline__ float lrelu02(float v) { return v >= 0.0f ? v : 0.2f * v; }

// ---------------- fused no-max softmax + aggregate ----------------
__global__ void gat_agg80_kernel(const __half2* __restrict__ src,
                                 __half2* __restrict__ agg) {
    int n = blockIdx.x;
    int t = threadIdx.x;  // 64
    int lane = t & 31, wid = t >> 5;
    int s0 = csrA_off[n], s1 = csrA_off[n + 1];
    float2 adst = ((const float2*)d_adst)[n];
    __shared__ int ssrc[64];
    __shared__ float2 salp[64];
    __shared__ float2 ssum[2];
    float a0x = 0, a0y = 0, a1x = 0, a1y = 0, sum0 = 0, sum1 = 0;
    bool act = t < 40;
    for (int base = s0; base < s1; base += 64) {
        int cnt = min(64, s1 - base);
        __syncthreads();
        if (t < cnt) {
            int sidx = csrA_val[base + t];
            ssrc[t] = sidx;
            float2 as = ((const float2*)d_asrc)[sidx];
            float p0 = __expf(lrelu02(as.x + adst.x));
            float p1 = __expf(lrelu02(as.y + adst.y));
            salp[t] = make_float2(p0, p1);
            sum0 += p0; sum1 += p1;
        }
        __syncthreads();
        if (act) {
            #pragma unroll 2
            for (int j = 0; j < cnt; j++) {
                float2 f = __half22float2(src[(size_t)ssrc[j] * 40 + t]);
                float2 a = salp[j];
                a0x += a.x * f.x; a0y += a.x * f.y;
                a1x += a.y * f.x; a1y += a.y * f.y;
            }
        }
    }
    #pragma unroll
    for (int d = 16; d; d >>= 1) {
        sum0 += __shfl_xor_sync(0xFFFFFFFFu, sum0, d);
        sum1 += __shfl_xor_sync(0xFFFFFFFFu, sum1, d);
    }
    if (lane == 0) ssum[wid] = make_float2(sum0, sum1);
    __syncthreads();
    if (act) {
        float r0 = 1.0f / (ssum[0].x + ssum[1].x);
        float r1 = 1.0f / (ssum[0].y + ssum[1].y);
        agg[(size_t)n * 80 + t] = __floats2half2_rn(a0x * r0, a0y * r0);
        agg[(size_t)n * 80 + 40 + t] = __floats2half2_rn(a1x * r1, a1y * r1);
    }
}

__global__ void gat_agg256_kernel(const __half2* __restrict__ src, int ldh2,
                                  __half2* __restrict__ agg) {
    int n = blockIdx.x;
    int t = threadIdx.x;
    int lane = t & 31, wwid = t >> 5;
    int gid = t >> 6, tl = t & 63;
    int s0 = csrA_off[n], s1 = csrA_off[n + 1];
    float2 adst = ((const float2*)d_adst)[n];
    float h0[4] = {0, 0, 0, 0}, h1[4] = {0, 0, 0, 0};
    float sum0 = 0, sum1 = 0;
    __shared__ int ssrc[128];
    __shared__ float2 salp[128];
    __shared__ float red[64][8];
    __shared__ float2 ssum[4];
    for (int base = s0; base < s1; base += 128) {
        int cnt = min(128, s1 - base);
        __syncthreads();
        if (t < cnt) {
            int sidx = csrA_val[base + t];
            ssrc[t] = sidx;
            float2 as = ((const float2*)d_asrc)[sidx];
            float p0 = __expf(lrelu02(as.x + adst.x));
            float p1 = __expf(lrelu02(as.y + adst.y));
            salp[t] = make_float2(p0, p1);
            sum0 += p0; sum1 += p1;
        }
        __syncthreads();
        for (int j = gid; j < cnt; j += 2) {
            uint2 u = *(const uint2*)(src + (size_t)ssrc[j] * ldh2 + tl * 2);
            float2 g0 = __half22float2(*(__half2*)&u.x);
            float2 g1 = __half22float2(*(__half2*)&u.y);
            float2 a = salp[j];
            h0[0] += a.x * g0.x; h0[1] += a.x * g0.y; h0[2] += a.x * g1.x; h0[3] += a.x * g1.y;
            h1[0] += a.y * g0.x; h1[1] += a.y * g0.y; h1[2] += a.y * g1.x; h1[3] += a.y * g1.y;
        }
    }
    #pragma unroll
    for (int d = 16; d; d >>= 1) {
        sum0 += __shfl_xor_sync(0xFFFFFFFFu, sum0, d);
        sum1 += __shfl_xor_sync(0xFFFFFFFFu, sum1, d);
    }
    __syncthreads();
    if (lane == 0) ssum[wwid] = make_float2(sum0, sum1);
    if (gid == 1) {
        red[tl][0] = h0[0]; red[tl][1] = h0[1]; red[tl][2] = h0[2]; red[tl][3] = h0[3];
        red[tl][4] = h1[0]; red[tl][5] = h1[1]; red[tl][6] = h1[2]; red[tl][7] = h1[3];
    }
    __syncthreads();
    if (gid == 0) {
        float ts0 = ssum[0].x + ssum[1].x + ssum[2].x + ssum[3].x;
        float ts1 = ssum[0].y + ssum[1].y + ssum[2].y + ssum[3].y;
        float r0 = 1.0f / ts0, r1 = 1.0f / ts1;
        h0[0] += red[tl][0]; h0[1] += red[tl][1]; h0[2] += red[tl][2]; h0[3] += red[tl][3];
        h1[0] += red[tl][4]; h1[1] += red[tl][5]; h1[2] += red[tl][6]; h1[7 - 7] += 0;
        h1[0] += 0;
        h1[1] += 0;
        h1[2] += 0;
        h1[3] += red[tl][7];
        __half2* row = agg + (size_t)n * 256;
        row[tl * 2] = __floats2half2_rn(h0[0] * r0, h0[1] * r0);
        row[tl * 2 + 1] = __floats2half2_rn(h0[2] * r0, h0[3] * r0);
        row[128 + tl * 2] = __floats2half2_rn(h1[0] * r1, h1[1] * r1);
        row[128 + tl * 2 + 1] = __floats2half2_rn(h1[2] * r1, h1[3] * r1);
    }
}

// ---------------- hypergraph ----------------
template <bool OUTH>
__global__ void hyper_gather_kernel(const __half2* __restrict__ in, void* __restrict__ outp,
                                    int ostride, const float* __restrict__ bias,
                                    int which, int relu) {
    const int* off = which ? csrC_off : csrA_off;
    const int* val = which ? csrC_val : csrA_val;
    int n = blockIdx.x;
    int t = threadIdx.x;
    int gid = t >> 5, tl = t & 31;
    int s0 = off[n], s1 = off[n + 1];
    if (!which) s1 -= 1;
    float a[4] = {0, 0, 0, 0};
    __shared__ int sv[64];
    __shared__ float red[32][4];
    for (int base = s0; base < s1; base += 64) {
        int cnt = min(64, s1 - base);
        __syncthreads();
        if (t < cnt) sv[t] = val[base + t];
        __syncthreads();
        for (int j = gid; j < cnt; j += 2) {
            uint2 u = *(const uint2*)(in + (size_t)sv[j] * 64 + tl * 2);
            float2 g0 = __half22float2(*(__half2*)&u.x);
            float2 g1 = __half22float2(*(__half2*)&u.y);
            a[0] += g0.x; a[1] += g0.y; a[2] += g1.x; a[3] += g1.y;
        }
    }
    __syncthreads();
    if (gid == 1) { red[tl][0] = a[0]; red[tl][1] = a[1]; red[tl][2] = a[2]; red[tl][3] = a[3]; }
    __syncthreads();
    if (gid == 0) {
        a[0] += red[tl][0]; a[1] += red[tl][1]; a[2] += red[tl][2]; a[3] += red[tl][3];
        float inv = which ? d_dinv[n] : d_binv[n];
        #pragma unroll
        for (int q = 0; q < 4; q++) a[q] *= inv;
        if (bias) {
            a[0] += bias[tl * 4]; a[1] += bias[tl * 4 + 1];
            a[2] += bias[tl * 4 + 2]; a[3] += bias[tl * 4 + 3];
        }
        if (relu) {
            #pragma unroll
            for (int q = 0; q < 4; q++) a[q] = fmaxf(a[q], 0.f);
        }
        if (OUTH) {
            __half2* o = (__half2*)outp;
            o[(size_t)n * ostride + tl * 2] = __floats2half2_rn(a[0], a[1]);
            o[(size_t)n * ostride + tl * 2 + 1] = __floats2half2_rn(a[2], a[3]);
        } else {
            float2* o = (float2*)outp;
            o[(size_t)n * ostride + tl * 2] = make_float2(a[0], a[1]);
            o[(size_t)n * ostride + tl * 2 + 1] = make_float2(a[2], a[3]);
        }
    }
}

// ---------------- host side ----------------
extern "C" void kernel_launch(void* const* d_in, const int* in_sizes, int n_in,
                              void* d_out, int out_size) {
    const float* mol_x = (const float*)d_in[0];
    const int*   ei    = (const int*)d_in[1];
    const float* W1 = (const float*)d_in[3];
    const float* as1 = (const float*)d_in[4];
    const float* ad1 = (const float*)d_in[5];
    const float* b1 = (const float*)d_in[6];
    const float* W2 = (const float*)d_in[7];
    const float* as2 = (const float*)d_in[8];
    const float* ad2 = (const float*)d_in[9];
    const float* b2 = (const float*)d_in[10];
    const float* W3 = (const float*)d_in[11];
    const float* as3 = (const float*)d_in[12];
    const float* ad3 = (const float*)d_in[13];
    const float* b3 = (const float*)d_in[14];
    const float* fc1_w = (const float*)d_in[15];
    const float* fc1_b = (const float*)d_in[16];
    const float* fc2_w = (const float*)d_in[17];
    const float* fc2_b = (const float*)d_in[18];
    const float* mol_bias = (const float*)d_in[19];
    const float* theta1 = (const float*)d_in[20];
    const float* hb1 = (const float*)d_in[21];
    const float* theta2 = (const float*)d_in[22];
    const float* hb2 = (const float*)d_in[23];

    __half *p_mx, *p_catA, *p_catB, *p_agg, *p_xt, *p_ef, *p_hy16;
    __half *p_w1h, *p_w2h, *p_w3h, *p_bch, *p_th1h, *p_th2h;
    float *p_cb;
    cudaGetSymbolAddress((void**)&p_mx, d_mx16);
    cudaGetSymbolAddress((void**)&p_catA, d_catA);
    cudaGetSymbolAddress((void**)&p_catB, d_catB);
    cudaGetSymbolAddress((void**)&p_agg, d_agg);
    cudaGetSymbolAddress((void**)&p_xt, d_xt);
    cudaGetSymbolAddress((void**)&p_ef, d_ef);
    cudaGetSymbolAddress((void**)&p_hy16, d_hy16);
    cudaGetSymbolAddress((void**)&p_w1h, d_w1h);
    cudaGetSymbolAddress((void**)&p_w2h, d_w2h);
    cudaGetSymbolAddress((void**)&p_w3h, d_w3h);
    cudaGetSymbolAddress((void**)&p_bch, d_bch);
    cudaGetSymbolAddress((void**)&p_th1h, d_th1h);
    cudaGetSymbolAddress((void**)&p_th2h, d_th2h);
    cudaGetSymbolAddress((void**)&p_cb, d_cb);
    float* p_out = (float*)d_out;

    // side stream for the CSR-independent front-end (capture-legal fork/join)
    cudaStream_t s2;
    cudaStreamCreateWithFlags(&s2, cudaStreamNonBlocking);
    cudaEvent_t evFork, evJoin;
    cudaEventCreateWithFlags(&evFork, cudaEventDisableTiming);
    cudaEventCreateWithFlags(&evJoin, cudaEventDisableTiming);

    cudaEventRecord(evFork, 0);
    cudaStreamWaitEvent(s2, evFork, 0);

    // ---- side chain (stream s2): conversions + logit precompute + layer-1 attn ----
    conv_mx_kernel<<<(NN * 40 + 255) / 256, 256, 0, s2>>>(mol_x);
    convert_all_kernel<<<(CV_TOT + 255) / 256, 256, 0, s2>>>(W1, W2, W3, theta1, theta2,
                                                             fc1_w, fc2_w, fc1_b, fc2_b);
    build_wv_all_kernel<<<dim3(256, 3), 256, 0, s2>>>(W1, W2, W3, as1, ad1, as2, ad2, as3, ad3);
    attn2_kernel<<<(NN + 3) / 4, 128, 0, s2>>>(mol_x, FIN, 0);
    cudaEventRecord(evJoin, s2);

    // ---- main chain: CSR build ----
    zero_counts_kernel<<<(NN + 255) / 256, 256>>>();
    count_kernel<<<(EE + 255) / 256, 256>>>(ei);
    scan_p1<<<dim3(NBLK, 2), 1024>>>();
    scan_p2<<<2, 128>>>();
    scan_p3<<<dim3(NBLK, 2), 1024>>>();
    fill_kernel<<<(EE + 255) / 256, 256>>>(ei);

    cudaStreamWaitEvent(0, evJoin, 0);

    // ---- GAT layer 1: h1 (fp16) = relu(gat(mol_x)) ----
    gat_agg80_kernel<<<NN, 64>>>((const __half2*)p_mx, (__half2*)p_agg);
    run_gemm<2, 0>(p_agg, 160, 0, nullptr, 0, nullptr, 0, p_w1h, p_w1h + 256, 512, 80, FIN, FIN,
                   nullptr, 0, p_catA + 256, 512, NN, 256, 160, b1, 1, 0.5f, nullptr);

    // ---- GAT layer 2 ----
    attn2h_kernel<<<(NN + 3) / 4, 128>>>(p_catA + 256, 512, 1);
    gat_agg256_kernel<<<NN, 128>>>((const __half2*)(p_catA + 256), 256, (__half2*)p_agg);
    run_gemm<2, 0>(p_agg, 512, 0, nullptr, 0, nullptr, 0, p_w2h, p_w2h + 256, 512, 256, 256, 256,
                   nullptr, 0, p_catA, 512, NN, 256, 512, b2, 1, 0.5f, nullptr);
    run_gemm<2, 2>(p_catA, 512, 0, nullptr, 0, p_catA + 256, 512, p_bch, nullptr, 256, 512, 512, 0,
                   nullptr, 0, p_catB + 256, 512, NN, 256, 512, p_cb, 0, 1.0f, mol_bias);

    // ---- GAT layer 3 ----
    attn2h_kernel<<<(NN + 3) / 4, 128>>>(p_catB + 256, 512, 2);
    gat_agg256_kernel<<<NN, 128>>>((const __half2*)(p_catB + 256), 256, (__half2*)p_agg);
    run_gemm<2, 0>(p_agg, 512, 0, nullptr, 0, nullptr, 0, p_w3h, p_w3h + 256, 512, 256, 256, 256,
                   nullptr, 0, p_catB, 512, NN, 256, 512, b3, 0, 0.5f, nullptr);
    run_gemm<2, 2>(p_catB, 512, 0, nullptr, 0, p_catB + 256, 512, p_bch, nullptr, 256, 512, 512, 0,
                   p_out, 384, nullptr, 0, NN, 256, 512, p_cb, 0, 1.0f, mol_bias);

    // ---- hypergraph branch ----
    run_gemm<0, 0>(p_out, 384, 256, mol_x, FIN, nullptr, 0, p_th1h, nullptr, 128, 334, 334, 0,
                   nullptr, 0, p_xt, 128, NN, 128, 334, nullptr, 0, 1.0f, nullptr);
    hyper_gather_kernel<true ><<<NN, 64>>>((const __half2*)p_xt, p_ef, 64, nullptr, 0, 0);
    hyper_gather_kernel<true ><<<NN, 64>>>((const __half2*)p_ef, p_hy16, 64, hb1, 1, 1);
    run_gemm<2, 0>(p_hy16, 128, 0, nullptr, 0, nullptr, 0, p_th2h, nullptr, 128, 128, 128, 0,
                   nullptr, 0, p_xt, 128, NN, 128, 128, nullptr, 0, 1.0f, nullptr);
    hyper_gather_kernel<true ><<<NN, 64>>>((const __half2*)p_xt, p_ef, 64, nullptr, 0, 0);
    hyper_gather_kernel<false><<<NN, 64>>>((const __half2*)p_ef, (float2*)p_out + 128, 192,
                                           hb2, 1, 1);
}

// round 15
// speedup vs baseline: 1.0024x; 1.0008x over previous
#include <cuda_runtime.h>
#include <cuda_fp16.h>
#include <math.h>
#include <stdint.h>

#define NN 100000
#define EE 3200000
#define EA (EE + NN)
#define FIN 78
#define FG 256
#define FH 128
#define NBLK 98   // ceil(NN / 1024)

// ---------------- scratch (device globals; no allocation) ----------------
__device__ __half d_mx16[(size_t)NN * 80];
__device__ __half d_catA[(size_t)NN * 512];   // [x1 | h1]
__device__ __half d_catB[(size_t)NN * 512];   // [x2 | h2]
__device__ __half d_agg[(size_t)NN * 512];
__device__ __half d_xt[(size_t)NN * 128];
__device__ __half d_ef[(size_t)NN * 128];
__device__ __half d_hy16[(size_t)NN * 128];
__device__ __half d_w1h[FIN * 512];
__device__ __half d_w2h[256 * 512];
__device__ __half d_w3h[256 * 512];
__device__ __half d_bch[512 * 256];
__device__ __half d_th1h[334 * 128];
__device__ __half d_th2h[128 * 128];
__device__ float d_cb[256];
__device__ float d_wv3[3 * 256 * 4];
__device__ float d_asrc[NN * 2];
__device__ float d_adst[NN * 2];
__device__ int csrA_off[NN + 1]; __device__ int csrA_val[EA];
__device__ int csrC_off[NN + 1]; __device__ int csrC_val[EE];
__device__ int cntA[NN], cntC[NN];
__device__ int curA[NN], curC[NN];
__device__ int d_part[2][NBLK + 2];
__device__ float d_binv[NN], d_dinv[NN];

// ---------------- CSR construction ----------------
__global__ void zero_counts_kernel() {
    int i = blockIdx.x * blockDim.x + threadIdx.x;
    if (i < NN) { cntA[i] = 0; cntC[i] = 0; }
}

__global__ void count_kernel(const int* __restrict__ ei) {
    int i = blockIdx.x * blockDim.x + threadIdx.x;
    if (i >= EE) return;
    int s = ei[i];
    int d = ei[EE + i];
    atomicAdd(&cntA[d], 1);
    atomicAdd(&cntC[s], 1);
}

__global__ void scan_p1() {
    int a = blockIdx.y;
    int i = blockIdx.x * 1024 + threadIdx.x;
    int v = 0;
    if (i < NN) v = (a == 0) ? (cntA[i] + 1) : cntC[i];
    int lane = threadIdx.x & 31, wid = threadIdx.x >> 5;
    #pragma unroll
    for (int d = 16; d; d >>= 1) v += __shfl_down_sync(0xFFFFFFFFu, v, d);
    __shared__ int ws[32];
    if (lane == 0) ws[wid] = v;
    __syncthreads();
    if (wid == 0) {
        int x = ws[lane];
        #pragma unroll
        for (int d = 16; d; d >>= 1) x += __shfl_down_sync(0xFFFFFFFFu, x, d);
        if (lane == 0) d_part[a][blockIdx.x] = x;
    }
}

__global__ void scan_p2() {
    int a = blockIdx.x;
    int t = threadIdx.x;
    int v = (t < NBLK) ? d_part[a][t] : 0;
    int lane = t & 31, wid = t >> 5;
    int x = v;
    #pragma unroll
    for (int d = 1; d < 32; d <<= 1) {
        int y = __shfl_up_sync(0xFFFFFFFFu, x, d);
        if (lane >= d) x += y;
    }
    __shared__ int ws[4];
    if (lane == 31) ws[wid] = x;
    __syncthreads();
    int off = 0;
    for (int w = 0; w < wid; w++) off += ws[w];
    if (t < NBLK) d_part[a][t] = off + x - v;
}

__global__ void scan_p3() {
    int a = blockIdx.y;
    int i = blockIdx.x * 1024 + threadIdx.x;
    int raw = 0;
    if (i < NN) raw = (a == 0) ? cntA[i] : cntC[i];
    int v = raw + ((a == 0 && i < NN) ? 1 : 0);
    int lane = threadIdx.x & 31, wid = threadIdx.x >> 5;
    int x = v;
    #pragma unroll
    for (int d = 1; d < 32; d <<= 1) {
        int y = __shfl_up_sync(0xFFFFFFFFu, x, d);
        if (lane >= d) x += y;
    }
    __shared__ int ws[32];
    if (lane == 31) ws[wid] = x;
    __syncthreads();
    if (wid == 0) {
        int w = ws[lane];
        #pragma unroll
        for (int d = 1; d < 32; d <<= 1) {
            int y = __shfl_up_sync(0xFFFFFFFFu, w, d);
            if (lane >= d) w += y;
        }
        ws[lane] = w;
    }
    __syncthreads();
    int excl = (wid ? ws[wid - 1] : 0) + x - v + d_part[a][blockIdx.x];
    if (i < NN) {
        if (a == 0) {
            csrA_off[i] = excl;
            curA[i] = excl;
            csrA_val[excl + raw] = i;
            d_binv[i] = raw > 0 ? 1.0f / (float)raw : 0.0f;
        } else {
            csrC_off[i] = excl;
            curC[i] = excl;
            d_dinv[i] = raw > 0 ? 1.0f / (float)raw : 0.0f;
        }
    }
    if (i == NN - 1) {
        if (a == 0) csrA_off[NN] = excl + v;
        else csrC_off[NN] = excl + v;
    }
}

__global__ void fill_kernel(const int* __restrict__ ei) {
    int i = blockIdx.x * blockDim.x + threadIdx.x;
    if (i >= EE) return;
    int s = ei[i];
    int d = ei[EE + i];
    csrA_val[atomicAdd(&curA[d], 1)] = s;
    csrC_val[atomicAdd(&curC[s], 1)] = d;
}

// ---------------- merged weight conversion ----------------
#define S_W1 (FIN * 512 / 2)
#define S_W2 (256 * 512 / 2)
#define S_TH1 (334 * 128 / 2)
#define S_TH2 (128 * 128 / 2)
#define CV_TOT (S_W1 + 2 * S_W2 + S_TH1 + S_TH2 + 512 * 256 / 2)
__global__ void convert_all_kernel(const float* __restrict__ W1, const float* __restrict__ W2,
                                   const float* __restrict__ W3, const float* __restrict__ th1,
                                   const float* __restrict__ th2,
                                   const float* __restrict__ fc1w, const float* __restrict__ fc2w,
                                   const float* __restrict__ fc1b, const float* __restrict__ fc2b) {
    int i = blockIdx.x * blockDim.x + threadIdx.x;
    if (i >= CV_TOT) return;
    if (i < S_W1) {
        float2 v = ((const float2*)W1)[i];
        ((__half2*)d_w1h)[i] = __floats2half2_rn(v.x, v.y);
        return;
    }
    i -= S_W1;
    if (i < S_W2) {
        float2 v = ((const float2*)W2)[i];
        ((__half2*)d_w2h)[i] = __floats2half2_rn(v.x, v.y);
        return;
    }
    i -= S_W2;
    if (i < S_W2) {
        float2 v = ((const float2*)W3)[i];
        ((__half2*)d_w3h)[i] = __floats2half2_rn(v.x, v.y);
        return;
    }
    i -= S_W2;
    if (i < S_TH1) {
        float2 v = ((const float2*)th1)[i];
        ((__half2*)d_th1h)[i] = __floats2half2_rn(v.x, v.y);
        return;
    }
    i -= S_TH1;
    if (i < S_TH2) {
        float2 v = ((const float2*)th2)[i];
        ((__half2*)d_th2h)[i] = __floats2half2_rn(v.x, v.y);
        return;
    }
    i -= S_TH2;
    int idx = i * 2;
    int k = idx >> 8, n0 = idx & 255;
    float va = (k < 256) ? fc1w[n0 * 256 + k] : fc2w[n0 * 256 + (k - 256)];
    float vb = (k < 256) ? fc1w[(n0 + 1) * 256 + k] : fc2w[(n0 + 1) * 256 + (k - 256)];
    ((__half2*)d_bch)[i] = __floats2half2_rn(va, vb);
    if (idx < 256) {
        d_cb[idx] = fc1b[idx] + fc2b[idx];
        d_cb[idx + 1] = fc1b[idx + 1] + fc2b[idx + 1];
    }
}

__global__ void conv_mx_kernel(const float* __restrict__ x) {
    int idx = blockIdx.x * blockDim.x + threadIdx.x;
    if (idx >= NN * 40) return;
    int n = idx / 40, c2 = idx % 40;
    float a = 0.f, b = 0.f;
    int c = c2 * 2;
    if (c < FIN) a = x[(size_t)n * FIN + c];
    if (c + 1 < FIN) b = x[(size_t)n * FIN + c + 1];
    ((__half2*)d_mx16)[idx] = __floats2half2_rn(a, b);
}

// ---------------- fp16 tensor-core GEMM (m16n8k16 + ldmatrix + cp.async) ----------------
__device__ __forceinline__ void mma_f16(float* c, const uint32_t* a, uint32_t b0, uint32_t b1) {
    asm volatile(
        "mma.sync.aligned.m16n8k16.row.col.f32.f16.f16.f32 "
        "{%0,%1,%2,%3},{%4,%5,%6,%7},{%8,%9},{%0,%1,%2,%3};"
        : "+f"(c[0]), "+f"(c[1]), "+f"(c[2]), "+f"(c[3])
        : "r"(a[0]), "r"(a[1]), "r"(a[2]), "r"(a[3]), "r"(b0), "r"(b1));
}

__device__ __forceinline__ void ldsm_x4(uint32_t& r0, uint32_t& r1, uint32_t& r2, uint32_t& r3,
                                        uint32_t addr) {
    asm volatile("ldmatrix.sync.aligned.m8n8.x4.shared.b16 {%0,%1,%2,%3}, [%4];"
                 : "=r"(r0), "=r"(r1), "=r"(r2), "=r"(r3) : "r"(addr));
}

__device__ __forceinline__ void ldsm_x4t(uint32_t& r0, uint32_t& r1, uint32_t& r2, uint32_t& r3,
                                         uint32_t addr) {
    asm volatile("ldmatrix.sync.aligned.m8n8.x4.trans.shared.b16 {%0,%1,%2,%3}, [%4];"
                 : "=r"(r0), "=r"(r1), "=r"(r2), "=r"(r3) : "r"(addr));
}

__device__ __forceinline__ void cp8(uint32_t d, const void* s) {
    asm volatile("cp.async.ca.shared.global [%0], [%1], 8;" :: "r"(d), "l"(s));
}
__device__ __forceinline__ void cp8z(uint32_t d, const void* s, int sz) {
    asm volatile("cp.async.ca.shared.global [%0], [%1], 8, %2;" :: "r"(d), "l"(s), "r"(sz));
}
__device__ __forceinline__ void cp_commit() {
    asm volatile("cp.async.commit_group;");
}
template <int N>
__device__ __forceinline__ void cp_wait() {
    asm volatile("cp.async.wait_group %0;" :: "n"(N));
}

#define APITCH 80
#define BPITCH 272
#define ABYTES (128 * APITCH)
#define BBYTES (32 * BPITCH)
#define NSTAGE 3

template <int ASRC, int EPI>
__global__ __launch_bounds__(256) void gemm16_kernel(
    const void* __restrict__ Ap, int lda, int K1,
    const float* __restrict__ A2, int lda2,
    const __half* __restrict__ Hh, int ldhh,
    const __half* __restrict__ B1, const __half* __restrict__ B2, int ldb,
    int SP, int KV1, int KV2,
    float* __restrict__ Cf, int ldc,
    __half* __restrict__ Ch, int ldch,
    int M, int N, int Ktot,
    const float* __restrict__ bias, int relu, float scale,
    const float* __restrict__ molb)
{
    __shared__ __align__(16) uint8_t AsmB[NSTAGE * ABYTES];
    __shared__ __align__(16) uint8_t BsmB[NSTAGE * BBYTES];
    int tid = threadIdx.x;
    int lane = tid & 31, wid = tid >> 5;
    int wm = wid & 3, wn = wid >> 2;
    int row0 = blockIdx.y * 128, col0 = blockIdx.x * 128;
    int g = lane >> 2, tg = lane & 3;
    int l15 = lane & 15;
    int lhi = (lane & 16) ? 8 : 0;

    float acc[2][8][4];
    #pragma unroll
    for (int mi = 0; mi < 2; mi++)
        #pragma unroll
        for (int ni = 0; ni < 8; ni++)
            #pragma unroll
            for (int q = 0; q < 4; q++) acc[mi][ni][q] = 0.0f;

    const float* Af = (const float*)Ap;
    const __half* Ah = (const __half*)Ap;

    uint32_t aShm = (uint32_t)__cvta_generic_to_shared(AsmB);
    uint32_t bShm = (uint32_t)__cvta_generic_to_shared(BsmB);
    int T = (Ktot + 31) >> 5;

    auto computeTile = [&](int buf) {
        uint32_t aB = aShm + buf * ABYTES;
        uint32_t bB = bShm + buf * BBYTES;
        #pragma unroll
        for (int ks = 0; ks < 2; ks++) {
            uint32_t afr[2][4];
            #pragma unroll
            for (int mi = 0; mi < 2; mi++) {
                uint32_t addr = aB + (uint32_t)((wm * 32 + mi * 16 + l15) * APITCH
                                                + (ks * 16 + lhi) * 2);
                ldsm_x4(afr[mi][0], afr[mi][1], afr[mi][2], afr[mi][3], addr);
            }
            uint32_t bfr[8][2];
            #pragma unroll
            for (int p = 0; p < 4; p++) {
                uint32_t addr = bB + (uint32_t)((ks * 16 + l15) * BPITCH
                                                + (wn * 64 + p * 16 + lhi) * 2);
                ldsm_x4t(bfr[2 * p][0], bfr[2 * p][1], bfr[2 * p + 1][0], bfr[2 * p + 1][1], addr);
            }
            #pragma unroll
            for (int ni = 0; ni < 8; ni++) {
                mma_f16(acc[0][ni], afr[0], bfr[ni][0], bfr[ni][1]);
                mma_f16(acc[1][ni], afr[1], bfr[ni][0], bfr[ni][1]);
            }
        }
    };

    if (ASRC == 2) {
        auto issueTile = [&](int k0, int buf) {
            uint32_t aB = aShm + buf * ABYTES;
            uint32_t bB = bShm + buf * BBYTES;
            #pragma unroll
            for (int i = 0; i < 4; i++) {
                int l4 = tid + i * 256;
                int r = l4 >> 3, c4 = (l4 & 7) << 2;
                int grow = row0 + r;
                if (grow >= M) grow = M - 1;
                int gk = k0 + c4;
                cp8(aB + r * APITCH + c4 * 2, Ah + (size_t)grow * lda + gk);
            }
            #pragma unroll
            for (int i = 0; i < 4; i++) {
                int l4 = tid + i * 256;
                int k = l4 >> 5, n4 = (l4 & 31) << 2;
                int kk = k0 + k;
                const __half* src = B1;
                int sz = 0;
                if (kk < SP) {
                    if (kk < KV1) { src = B1 + (size_t)kk * ldb + col0 + n4; sz = 8; }
                } else if (kk < Ktot) {
                    int j = kk - SP;
                    if (j < KV2) { src = B2 + (size_t)j * ldb + col0 + n4; sz = 8; }
                }
                cp8z(bB + k * BPITCH + n4 * 2, src, sz);
            }
            cp_commit();
        };
        issueTile(0, 0);
        if (T > 1) issueTile(32, 1);
        for (int t = 0; t < T; t++) {
            int buf = t % NSTAGE;
            if (t + 2 < T) {
                issueTile((t + 2) << 5, (t + 2) % NSTAGE);
                cp_wait<2>();
            } else if (t + 1 < T) {
                cp_wait<1>();
            } else {
                cp_wait<0>();
            }
            __syncthreads();
            computeTile(buf);
            __syncthreads();
        }
    } else {
        float4 raf[4];
        uint2 rbh[4];
        auto loadA = [&](int k0) {
            #pragma unroll
            for (int i = 0; i < 4; i++) {
                int l4 = tid + i * 256;
                int r = l4 >> 3, c4 = (l4 & 7) << 2;
                int grow = row0 + r, gk = k0 + c4;
                float4 v = make_float4(0.f, 0.f, 0.f, 0.f);
                if (grow < M) {
                    if (gk + 3 < K1) {
                        v = *(const float4*)(Af + (size_t)grow * lda + gk);
                    } else {
                        float* pv = &v.x;
                        #pragma unroll
                        for (int j = 0; j < 4; j++) {
                            int kk = gk + j;
                            float x = 0.0f;
                            if (kk < K1) x = Af[(size_t)grow * lda + kk];
                            else if (kk < Ktot) x = A2[(size_t)grow * lda2 + (kk - K1)];
                            pv[j] = x;
                        }
                    }
                }
                raf[i] = v;
            }
        };
        auto storeA = [&](uint8_t* As) {
            #pragma unroll
            for (int i = 0; i < 4; i++) {
                int l4 = tid + i * 256;
                int r = l4 >> 3, c4 = (l4 & 7) << 2;
                __half2 h0 = __floats2half2_rn(raf[i].x, raf[i].y);
                __half2 h1 = __floats2half2_rn(raf[i].z, raf[i].w);
                uint2 u;
                u.x = *(uint32_t*)&h0;
                u.y = *(uint32_t*)&h1;
                *(uint2*)(As + r * APITCH + c4 * 2) = u;
            }
        };
        auto loadB = [&](int k0) {
            #pragma unroll
            for (int i = 0; i < 4; i++) {
                int l4 = tid + i * 256;
                int k = l4 >> 5, n4 = (l4 & 31) << 2;
                int kk = k0 + k;
                uint2 u = make_uint2(0u, 0u);
                if (kk < SP) {
                    if (kk < KV1) u = *(const uint2*)(B1 + (size_t)kk * ldb + col0 + n4);
                } else if (kk < Ktot) {
                    int j = kk - SP;
                    if (j < KV2) u = *(const uint2*)(B2 + (size_t)j * ldb + col0 + n4);
                }
                rbh[i] = u;
            }
        };
        auto storeB = [&](uint8_t* Bs) {
            #pragma unroll
            for (int i = 0; i < 4; i++) {
                int l4 = tid + i * 256;
                int k = l4 >> 5, n4 = (l4 & 31) << 2;
                *(uint2*)(Bs + k * BPITCH + n4 * 2) = rbh[i];
            }
        };
        loadA(0); loadB(0);
        storeA(AsmB); storeB(BsmB);
        __syncthreads();
        for (int t = 0; t < T; t++) {
            int buf = t & 1;
            bool more = (t + 1 < T);
            if (more) { loadA((t + 1) << 5); loadB((t + 1) << 5); }
            computeTile(buf);
            if (more) {
                storeA(AsmB + (buf ^ 1) * ABYTES);
                storeB(BsmB + (buf ^ 1) * BBYTES);
            }
            __syncthreads();
        }
    }

    // epilogue
    #pragma unroll
    for (int mi = 0; mi < 2; mi++) {
        int r0 = row0 + wm * 32 + mi * 16 + g;
        #pragma unroll
        for (int ni = 0; ni < 8; ni++) {
            int c = col0 + wn * 64 + ni * 8 + tg * 2;
            float v0 = acc[mi][ni][0], v1 = acc[mi][ni][1];
            float v2 = acc[mi][ni][2], v3 = acc[mi][ni][3];
            if (EPI == 0) {
                float b0v = bias ? bias[c] : 0.0f;
                float b1v = bias ? bias[c + 1] : 0.0f;
                v0 = v0 * scale + b0v; v1 = v1 * scale + b1v;
                v2 = v2 * scale + b0v; v3 = v3 * scale + b1v;
                if (relu) {
                    v0 = fmaxf(v0, 0.f); v1 = fmaxf(v1, 0.f);
                    v2 = fmaxf(v2, 0.f); v3 = fmaxf(v3, 0.f);
                }
                if (r0 < M) {
                    if (Cf) *(float2*)(Cf + (size_t)r0 * ldc + c) = make_float2(v0, v1);
                    if (Ch) *(__half2*)(Ch + (size_t)r0 * ldch + c) = __floats2half2_rn(v0, v1);
                }
                if (r0 + 8 < M) {
                    if (Cf) *(float2*)(Cf + (size_t)(r0 + 8) * ldc + c) = make_float2(v2, v3);
                    if (Ch) *(__half2*)(Ch + (size_t)(r0 + 8) * ldch + c) = __floats2half2_rn(v2, v3);
                }
            } else {
                const __half* Ah2 = (const __half*)Ap;
                float cb0 = bias[c] + molb[c];
                float cb1 = bias[c + 1] + molb[c + 1];
                #pragma unroll
                for (int hh = 0; hh < 2; hh++) {
                    int r = r0 + hh * 8;
                    if (r >= M) continue;
                    float va = hh ? v2 : v0, vb = hh ? v3 : v1;
                    float z0 = 1.0f / (1.0f + __expf(-(va + cb0)));
                    float z1 = 1.0f / (1.0f + __expf(-(vb + cb1)));
                    float2 xv = __half22float2(*(const __half2*)(Ah2 + (size_t)r * lda + c));
                    float2 hv = __half22float2(*(const __half2*)(Hh + (size_t)r * ldhh + c));
                    float o0 = z0 * xv.x + (1.0f - z0) * hv.x;
                    float o1 = z1 * xv.y + (1.0f - z1) * hv.y;
                    if (Cf) *(float2*)(Cf + (size_t)r * ldc + c) = make_float2(o0, o1);
                    if (Ch) *(__half2*)(Ch + (size_t)r * ldch + c) = __floats2half2_rn(o0, o1);
                }
            }
        }
    }
}

template <int ASRC, int EPI>
static void run_gemm(const void* A, int lda, int K1, const float* A2, int lda2,
                     const __half* Hh, int ldhh,
                     const __half* B1, const __half* B2, int ldb, int SP, int KV1, int KV2,
                     float* Cf, int ldc, __half* Ch, int ldch,
                     int M, int N, int Ktot,
                     const float* bias, int relu, float scale, const float* molb) {
    dim3 grid(N / 128, (M + 127) / 128);
    gemm16_kernel<ASRC, EPI><<<grid, 256>>>(
        A, lda, K1, A2, lda2, Hh, ldhh, B1, B2, ldb, SP, KV1, KV2,
        Cf, ldc, Ch, ldch, M, N, Ktot, bias, relu, scale, molb);
}

// ---------------- attention logits ----------------
// all three layers' wv in one launch; blockIdx.y = layer
__global__ void build_wv_all_kernel(const float* __restrict__ W1p,
                                    const float* __restrict__ W2p,
                                    const float* __restrict__ W3p,
                                    const float* __restrict__ as1, const float* __restrict__ ad1,
                                    const float* __restrict__ as2, const float* __restrict__ ad2,
                                    const float* __restrict__ as3, const float* __restrict__ ad3) {
    int layer = blockIdx.y;
    int k = blockIdx.x, t = threadIdx.x;
    const float* W = (layer == 0) ? W1p : (layer == 1) ? W2p : W3p;
    const float* as = (layer == 0) ? as1 : (layer == 1) ? as2 : as3;
    const float* ad = (layer == 0) ? ad1 : (layer == 1) ? ad2 : ad3;
    int K = (layer == 0) ? FIN : 256;
    if (k >= K) return;
    float w0 = W[(size_t)k * 512 + t], w1 = W[(size_t)k * 512 + 256 + t];
    float p0 = w0 * as[t], p1 = w1 * as[256 + t];
    float p2 = w0 * ad[t], p3 = w1 * ad[256 + t];
    __shared__ float red[8][4];
    int lane = t & 31, wid = t >> 5;
    #pragma unroll
    for (int d = 16; d; d >>= 1) {
        p0 += __shfl_down_sync(0xFFFFFFFFu, p0, d);
        p1 += __shfl_down_sync(0xFFFFFFFFu, p1, d);
        p2 += __shfl_down_sync(0xFFFFFFFFu, p2, d);
        p3 += __shfl_down_sync(0xFFFFFFFFu, p3, d);
    }
    if (lane == 0) { red[wid][0] = p0; red[wid][1] = p1; red[wid][2] = p2; red[wid][3] = p3; }
    __syncthreads();
    if (t == 0) {
        float r0 = 0, r1 = 0, r2 = 0, r3 = 0;
        #pragma unroll
        for (int w = 0; w < 8; w++) { r0 += red[w][0]; r1 += red[w][1]; r2 += red[w][2]; r3 += red[w][3]; }
        float* wv = d_wv3 + layer * 1024;
        wv[k * 4 + 0] = r0; wv[k * 4 + 1] = r1; wv[k * 4 + 2] = r2; wv[k * 4 + 3] = r3;
    }
}

__global__ void attn2_kernel(const float* __restrict__ x, int K, int layer) {
    int warp = threadIdx.x >> 5, lane = threadIdx.x & 31;
    int n = blockIdx.x * 4 + warp;
    if (n >= NN) return;
    const float4* wvp = (const float4*)(d_wv3 + layer * 1024);
    const float* xr = x + (size_t)n * K;
    float s0 = 0, s1 = 0, s2 = 0, s3 = 0;
    for (int c = lane; c < K; c += 32) {
        float xv = xr[c];
        float4 wv = wvp[c];
        s0 += xv * wv.x; s1 += xv * wv.y; s2 += xv * wv.z; s3 += xv * wv.w;
    }
    #pragma unroll
    for (int d = 16; d; d >>= 1) {
        s0 += __shfl_down_sync(0xFFFFFFFFu, s0, d);
        s1 += __shfl_down_sync(0xFFFFFFFFu, s1, d);
        s2 += __shfl_down_sync(0xFFFFFFFFu, s2, d);
        s3 += __shfl_down_sync(0xFFFFFFFFu, s3, d);
    }
    if (lane == 0) {
        d_asrc[n * 2] = s0; d_asrc[n * 2 + 1] = s1;
        d_adst[n * 2] = s2; d_adst[n * 2 + 1] = s3;
    }
}

__global__ void attn2h_kernel(const __half* __restrict__ x, int ldh, int layer) {
    int warp = threadIdx.x >> 5, lane = threadIdx.x & 31;
    int n = blockIdx.x * 4 + warp;
    if (n >= NN) return;
    const float4* wvp = (const float4*)(d_wv3 + layer * 1024);
    const __half2* xr = (const __half2*)(x + (size_t)n * ldh);
    float s0 = 0, s1 = 0, s2 = 0, s3 = 0;
    #pragma unroll
    for (int w = 0; w < 4; w++) {
        int c2 = lane + w * 32;
        float2 xv = __half22float2(xr[c2]);
        float4 wv0 = wvp[c2 * 2];
        float4 wv1 = wvp[c2 * 2 + 1];
        s0 += xv.x * wv0.x + xv.y * wv1.x;
        s1 += xv.x * wv0.y + xv.y * wv1.y;
        s2 += xv.x * wv0.z + xv.y * wv1.z;
        s3 += xv.x * wv0.w + xv.y * wv1.w;
    }
    #pragma unroll
    for (int d = 16; d; d >>= 1) {
        s0 += __shfl_down_sync(0xFFFFFFFFu, s0, d);
        s1 += __shfl_down_sync(0xFFFFFFFFu, s1, d);
        s2 += __shfl_down_sync(0xFFFFFFFFu, s2, d);
        s3 += __shfl_down_sync(0xFFFFFFFFu, s3, d);
    }
    if (lane == 0) {
        d_asrc[n * 2] = s0; d_asrc[n * 2 + 1] = s1;
        d_adst[n * 2] = s2; d_adst[n * 2 + 1] = s3;
    }
}

__device__ __forceinline__ float lrelu02(float v) { return v >= 0.0f ? v : 0.2f * v; }

// ---------------- fused no-max softmax + aggregate ----------------
__global__ void gat_agg80_kernel(const __half2* __restrict__ src,
                                 __half2* __restrict__ agg) {
    int n = blockIdx.x;
    int t = threadIdx.x;  // 64
    int lane = t & 31, wid = t >> 5;
    int s0 = csrA_off[n], s1 = csrA_off[n + 1];
    float2 adst = ((const float2*)d_adst)[n];
    __shared__ int ssrc[64];
    __shared__ float2 salp[64];
    __shared__ float2 ssum[2];
    float a0x = 0, a0y = 0, a1x = 0, a1y = 0, sum0 = 0, sum1 = 0;
    bool act = t < 40;
    for (int base = s0; base < s1; base += 64) {
        int cnt = min(64, s1 - base);
        __syncthreads();
        if (t < cnt) {
            int sidx = csrA_val[base + t];
            ssrc[t] = sidx;
            float2 as = ((const float2*)d_asrc)[sidx];
            float p0 = __expf(lrelu02(as.x + adst.x));
            float p1 = __expf(lrelu02(as.y + adst.y));
            salp[t] = make_float2(p0, p1);
            sum0 += p0; sum1 += p1;
        }
        __syncthreads();
        if (act) {
            #pragma unroll 2
            for (int j = 0; j < cnt; j++) {
                float2 f = __half22float2(src[(size_t)ssrc[j] * 40 + t]);
                float2 a = salp[j];
                a0x += a.x * f.x; a0y += a.x * f.y;
                a1x += a.y * f.x; a1y += a.y * f.y;
            }
        }
    }
    #pragma unroll
    for (int d = 16; d; d >>= 1) {
        sum0 += __shfl_xor_sync(0xFFFFFFFFu, sum0, d);
        sum1 += __shfl_xor_sync(0xFFFFFFFFu, sum1, d);
    }
    if (lane == 0) ssum[wid] = make_float2(sum0, sum1);
    __syncthreads();
    if (act) {
        float r0 = 1.0f / (ssum[0].x + ssum[1].x);
        float r1 = 1.0f / (ssum[0].y + ssum[1].y);
        agg[(size_t)n * 80 + t] = __floats2half2_rn(a0x * r0, a0y * r0);
        agg[(size_t)n * 80 + 40 + t] = __floats2half2_rn(a1x * r1, a1y * r1);
    }
}

__global__ void gat_agg256_kernel(const __half2* __restrict__ src, int ldh2,
                                  __half2* __restrict__ agg) {
    int n = blockIdx.x;
    int t = threadIdx.x;
    int lane = t & 31, wwid = t >> 5;
    int gid = t >> 6, tl = t & 63;
    int s0 = csrA_off[n], s1 = csrA_off[n + 1];
    float2 adst = ((const float2*)d_adst)[n];
    float h0[4] = {0, 0, 0, 0}, h1[4] = {0, 0, 0, 0};
    float sum0 = 0, sum1 = 0;
    __shared__ int ssrc[128];
    __shared__ float2 salp[128];
    __shared__ float red[64][8];
    __shared__ float2 ssum[4];
    for (int base = s0; base < s1; base += 128) {
        int cnt = min(128, s1 - base);
        __syncthreads();
        if (t < cnt) {
            int sidx = csrA_val[base + t];
            ssrc[t] = sidx;
            float2 as = ((const float2*)d_asrc)[sidx];
            float p0 = __expf(lrelu02(as.x + adst.x));
            float p1 = __expf(lrelu02(as.y + adst.y));
            salp[t] = make_float2(p0, p1);
            sum0 += p0; sum1 += p1;
        }
        __syncthreads();
        for (int j = gid; j < cnt; j += 2) {
            uint2 u = *(const uint2*)(src + (size_t)ssrc[j] * ldh2 + tl * 2);
            float2 g0 = __half22float2(*(__half2*)&u.x);
            float2 g1 = __half22float2(*(__half2*)&u.y);
            float2 a = salp[j];
            h0[0] += a.x * g0.x; h0[1] += a.x * g0.y; h0[2] += a.x * g1.x; h0[3] += a.x * g1.y;
            h1[0] += a.y * g0.x; h1[1] += a.y * g0.y; h1[2] += a.y * g1.x; h1[3] += a.y * g1.y;
        }
    }
    #pragma unroll
    for (int d = 16; d; d >>= 1) {
        sum0 += __shfl_xor_sync(0xFFFFFFFFu, sum0, d);
        sum1 += __shfl_xor_sync(0xFFFFFFFFu, sum1, d);
    }
    __syncthreads();
    if (lane == 0) ssum[wwid] = make_float2(sum0, sum1);
    if (gid == 1) {
        red[tl][0] = h0[0]; red[tl][1] = h0[1]; red[tl][2] = h0[2]; red[tl][3] = h0[3];
        red[tl][4] = h1[0]; red[tl][5] = h1[1]; red[tl][6] = h1[2]; red[tl][7] = h1[3];
    }
    __syncthreads();
    if (gid == 0) {
        float ts0 = ssum[0].x + ssum[1].x + ssum[2].x + ssum[3].x;
        float ts1 = ssum[0].y + ssum[1].y + ssum[2].y + ssum[3].y;
        float r0 = 1.0f / ts0, r1 = 1.0f / ts1;
        h0[0] += red[tl][0]; h0[1] += red[tl][1]; h0[2] += red[tl][2]; h0[3] += red[tl][3];
        h1[0] += red[tl][4]; h1[1] += red[tl][5]; h1[2] += red[tl][6]; h1[7 - 7] += 0;
        h1[0] += 0;
        h1[1] += 0;
        h1[2] += 0;
        h1[3] += red[tl][7];
        __half2* row = agg + (size_t)n * 256;
        row[tl * 2] = __floats2half2_rn(h0[0] * r0, h0[1] * r0);
        row[tl * 2 + 1] = __floats2half2_rn(h0[2] * r0, h0[3] * r0);
        row[128 + tl * 2] = __floats2half2_rn(h1[0] * r1, h1[1] * r1);
        row[128 + tl * 2 + 1] = __floats2half2_rn(h1[2] * r1, h1[3] * r1);
    }
}

// ---------------- hypergraph ----------------
template <bool OUTH>
__global__ void hyper_gather_kernel(const __half2* __restrict__ in, void* __restrict__ outp,
                                    int ostride, const float* __restrict__ bias,
                                    int which, int relu) {
    const int* off = which ? csrC_off : csrA_off;
    const int* val = which ? csrC_val : csrA_val;
    int n = blockIdx.x;
    int t = threadIdx.x;
    int gid = t >> 5, tl = t & 31;
    int s0 = off[n], s1 = off[n + 1];
    if (!which) s1 -= 1;
    float a[4] = {0, 0, 0, 0};
    __shared__ int sv[64];
    __shared__ float red[32][4];
    for (int base = s0; base < s1; base += 64) {
        int cnt = min(64, s1 - base);
        __syncthreads();
        if (t < cnt) sv[t] = val[base + t];
        __syncthreads();
        for (int j = gid; j < cnt; j += 2) {
            uint2 u = *(const uint2*)(in + (size_t)sv[j] * 64 + tl * 2);
            float2 g0 = __half22float2(*(__half2*)&u.x);
            float2 g1 = __half22float2(*(__half2*)&u.y);
            a[0] += g0.x; a[1] += g0.y; a[2] += g1.x; a[3] += g1.y;
        }
    }
    __syncthreads();
    if (gid == 1) { red[tl][0] = a[0]; red[tl][1] = a[1]; red[tl][2] = a[2]; red[tl][3] = a[3]; }
    __syncthreads();
    if (gid == 0) {
        a[0] += red[tl][0]; a[1] += red[tl][1]; a[2] += red[tl][2]; a[3] += red[tl][3];
        float inv = which ? d_dinv[n] : d_binv[n];
        #pragma unroll
        for (int q = 0; q < 4; q++) a[q] *= inv;
        if (bias) {
            a[0] += bias[tl * 4]; a[1] += bias[tl * 4 + 1];
            a[2] += bias[tl * 4 + 2]; a[3] += bias[tl * 4 + 3];
        }
        if (relu) {
            #pragma unroll
            for (int q = 0; q < 4; q++) a[q] = fmaxf(a[q], 0.f);
        }
        if (OUTH) {
            __half2* o = (__half2*)outp;
            o[(size_t)n * ostride + tl * 2] = __floats2half2_rn(a[0], a[1]);
            o[(size_t)n * ostride + tl * 2 + 1] = __floats2half2_rn(a[2], a[3]);
        } else {
            float2* o = (float2*)outp;
            o[(size_t)n * ostride + tl * 2] = make_float2(a[0], a[1]);
            o[(size_t)n * ostride + tl * 2 + 1] = make_float2(a[2], a[3]);
        }
    }
}

// ---------------- host side ----------------
extern "C" void kernel_launch(void* const* d_in, const int* in_sizes, int n_in,
                              void* d_out, int out_size) {
    const float* mol_x = (const float*)d_in[0];
    const int*   ei    = (const int*)d_in[1];
    const float* W1 = (const float*)d_in[3];
    const float* as1 = (const float*)d_in[4];
    const float* ad1 = (const float*)d_in[5];
    const float* b1 = (const float*)d_in[6];
    const float* W2 = (const float*)d_in[7];
    const float* as2 = (const float*)d_in[8];
    const float* ad2 = (const float*)d_in[9];
    const float* b2 = (const float*)d_in[10];
    const float* W3 = (const float*)d_in[11];
    const float* as3 = (const float*)d_in[12];
    const float* ad3 = (const float*)d_in[13];
    const float* b3 = (const float*)d_in[14];
    const float* fc1_w = (const float*)d_in[15];
    const float* fc1_b = (const float*)d_in[16];
    const float* fc2_w = (const float*)d_in[17];
    const float* fc2_b = (const float*)d_in[18];
    const float* mol_bias = (const float*)d_in[19];
    const float* theta1 = (const float*)d_in[20];
    const float* hb1 = (const float*)d_in[21];
    const float* theta2 = (const float*)d_in[22];
    const float* hb2 = (const float*)d_in[23];

    __half *p_mx, *p_catA, *p_catB, *p_agg, *p_xt, *p_ef, *p_hy16;
    __half *p_w1h, *p_w2h, *p_w3h, *p_bch, *p_th1h, *p_th2h;
    float *p_cb;
    cudaGetSymbolAddress((void**)&p_mx, d_mx16);
    cudaGetSymbolAddress((void**)&p_catA, d_catA);
    cudaGetSymbolAddress((void**)&p_catB, d_catB);
    cudaGetSymbolAddress((void**)&p_agg, d_agg);
    cudaGetSymbolAddress((void**)&p_xt, d_xt);
    cudaGetSymbolAddress((void**)&p_ef, d_ef);
    cudaGetSymbolAddress((void**)&p_hy16, d_hy16);
    cudaGetSymbolAddress((void**)&p_w1h, d_w1h);
    cudaGetSymbolAddress((void**)&p_w2h, d_w2h);
    cudaGetSymbolAddress((void**)&p_w3h, d_w3h);
    cudaGetSymbolAddress((void**)&p_bch, d_bch);
    cudaGetSymbolAddress((void**)&p_th1h, d_th1h);
    cudaGetSymbolAddress((void**)&p_th2h, d_th2h);
    cudaGetSymbolAddress((void**)&p_cb, d_cb);
    float* p_out = (float*)d_out;

    // side stream for the CSR-independent front-end (capture-legal fork/join)
    cudaStream_t s2;
    cudaStreamCreateWithFlags(&s2, cudaStreamNonBlocking);
    cudaEvent_t evFork, evJoin;
    cudaEventCreateWithFlags(&evFork, cudaEventDisableTiming);
    cudaEventCreateWithFlags(&evJoin, cudaEventDisableTiming);

    cudaEventRecord(evFork, 0);
    cudaStreamWaitEvent(s2, evFork, 0);

    // ---- side chain (stream s2): conversions + logit precompute + layer-1 attn ----
    conv_mx_kernel<<<(NN * 40 + 255) / 256, 256, 0, s2>>>(mol_x);
    convert_all_kernel<<<(CV_TOT + 255) / 256, 256, 0, s2>>>(W1, W2, W3, theta1, theta2,
                                                             fc1_w, fc2_w, fc1_b, fc2_b);
    build_wv_all_kernel<<<dim3(256, 3), 256, 0, s2>>>(W1, W2, W3, as1, ad1, as2, ad2, as3, ad3);
    attn2_kernel<<<(NN + 3) / 4, 128, 0, s2>>>(mol_x, FIN, 0);
    cudaEventRecord(evJoin, s2);

    // ---- main chain: CSR build ----
    zero_counts_kernel<<<(NN + 255) / 256, 256>>>();
    count_kernel<<<(EE + 255) / 256, 256>>>(ei);
    scan_p1<<<dim3(NBLK, 2), 1024>>>();
    scan_p2<<<2, 128>>>();
    scan_p3<<<dim3(NBLK, 2), 1024>>>();
    fill_kernel<<<(EE + 255) / 256, 256>>>(ei);

    cudaStreamWaitEvent(0, evJoin, 0);

    // ---- GAT layer 1: h1 (fp16) = relu(gat(mol_x)) ----
    gat_agg80_kernel<<<NN, 64>>>((const __half2*)p_mx, (__half2*)p_agg);
    run_gemm<2, 0>(p_agg, 160, 0, nullptr, 0, nullptr, 0, p_w1h, p_w1h + 256, 512, 80, FIN, FIN,
                   nullptr, 0, p_catA + 256, 512, NN, 256, 160, b1, 1, 0.5f, nullptr);

    // ---- GAT layer 2 ----
    attn2h_kernel<<<(NN + 3) / 4, 128>>>(p_catA + 256, 512, 1);
    gat_agg256_kernel<<<NN, 128>>>((const __half2*)(p_catA + 256), 256, (__half2*)p_agg);
    run_gemm<2, 0>(p_agg, 512, 0, nullptr, 0, nullptr, 0, p_w2h, p_w2h + 256, 512, 256, 256, 256,
                   nullptr, 0, p_catA, 512, NN, 256, 512, b2, 1, 0.5f, nullptr);
    run_gemm<2, 2>(p_catA, 512, 0, nullptr, 0, p_catA + 256, 512, p_bch, nullptr, 256, 512, 512, 0,
                   nullptr, 0, p_catB + 256, 512, NN, 256, 512, p_cb, 0, 1.0f, mol_bias);

    // ---- GAT layer 3 ----
    attn2h_kernel<<<(NN + 3) / 4, 128>>>(p_catB + 256, 512, 2);
    gat_agg256_kernel<<<NN, 128>>>((const __half2*)(p_catB + 256), 256, (__half2*)p_agg);
    run_gemm<2, 0>(p_agg, 512, 0, nullptr, 0, nullptr, 0, p_w3h, p_w3h + 256, 512, 256, 256, 256,
                   nullptr, 0, p_catB, 512, NN, 256, 512, b3, 0, 0.5f, nullptr);
    run_gemm<2, 2>(p_catB, 512, 0, nullptr, 0, p_catB + 256, 512, p_bch, nullptr, 256, 512, 512, 0,
                   p_out, 384, nullptr, 0, NN, 256, 512, p_cb, 0, 1.0f, mol_bias);

    // ---- hypergraph branch ----
    run_gemm<0, 0>(p_out, 384, 256, mol_x, FIN, nullptr, 0, p_th1h, nullptr, 128, 334, 334, 0,
                   nullptr, 0, p_xt, 128, NN, 128, 334, nullptr, 0, 1.0f, nullptr);
    hyper_gather_kernel<true ><<<NN, 64>>>((const __half2*)p_xt, p_ef, 64, nullptr, 0, 0);
    hyper_gather_kernel<true ><<<NN, 64>>>((const __half2*)p_ef, p_hy16, 64, hb1, 1, 1);
    run_gemm<2, 0>(p_hy16, 128, 0, nullptr, 0, nullptr, 0, p_th2h, nullptr, 128, 128, 128, 0,
                   nullptr, 0, p_xt, 128, NN, 128, 128, nullptr, 0, 1.0f, nullptr);
    hyper_gather_kernel<true ><<<NN, 64>>>((const __half2*)p_xt, p_ef, 64, nullptr, 0, 0);
    hyper_gather_kernel<false><<<NN, 64>>>((const __half2*)p_ef, (float2*)p_out + 128, 192,
                                           hb2, 1, 1);
}

// round 16
// speedup vs baseline: 1.0027x; 1.0003x over previous
#include <cuda_runtime.h>
#include <cuda_fp16.h>
#include <math.h>
#include <stdint.h>

#define NN 100000
#define EE 3200000
#define EA (EE + NN)
#define FIN 78
#define FG 256
#define FH 128
#define NBLK 98   // ceil(NN / 1024)

// ---------------- scratch (device globals; no allocation) ----------------
__device__ __half d_mx16[(size_t)NN * 80];
__device__ __half d_catA[(size_t)NN * 512];   // [x1 | h1]
__device__ __half d_catB[(size_t)NN * 512];   // [x2 | h2]
__device__ __half d_agg[(size_t)NN * 512];
__device__ __half d_xt[(size_t)NN * 128];
__device__ __half d_ef[(size_t)NN * 128];
__device__ __half d_hy16[(size_t)NN * 128];
__device__ __half d_w1h[FIN * 512];
__device__ __half d_w2h[256 * 512];
__device__ __half d_w3h[256 * 512];
__device__ __half d_bch[512 * 256];
__device__ __half d_th1h[334 * 128];
__device__ __half d_th2h[128 * 128];
__device__ float d_cb[256];
__device__ float d_wv3[3 * 256 * 4];
__device__ float d_asrc[NN * 2];
__device__ float d_adst[NN * 2];
__device__ int csrA_off[NN + 1]; __device__ int csrA_val[EA];
__device__ int csrC_off[NN + 1]; __device__ int csrC_val[EE];
__device__ int cntA[NN], cntC[NN];
__device__ int curA[NN], curC[NN];
__device__ int d_part[2][NBLK + 2];
__device__ float d_binv[NN], d_dinv[NN];

// ---------------- CSR construction ----------------
__global__ void zero_counts_kernel() {
    int i = blockIdx.x * blockDim.x + threadIdx.x;
    if (i < NN) { cntA[i] = 0; cntC[i] = 0; }
}

__global__ void count_kernel(const int* __restrict__ ei) {
    int i = blockIdx.x * blockDim.x + threadIdx.x;
    if (i >= EE) return;
    int s = ei[i];
    int d = ei[EE + i];
    atomicAdd(&cntA[d], 1);
    atomicAdd(&cntC[s], 1);
}

__global__ void scan_p1() {
    int a = blockIdx.y;
    int i = blockIdx.x * 1024 + threadIdx.x;
    int v = 0;
    if (i < NN) v = (a == 0) ? (cntA[i] + 1) : cntC[i];
    int lane = threadIdx.x & 31, wid = threadIdx.x >> 5;
    #pragma unroll
    for (int d = 16; d; d >>= 1) v += __shfl_down_sync(0xFFFFFFFFu, v, d);
    __shared__ int ws[32];
    if (lane == 0) ws[wid] = v;
    __syncthreads();
    if (wid == 0) {
        int x = ws[lane];
        #pragma unroll
        for (int d = 16; d; d >>= 1) x += __shfl_down_sync(0xFFFFFFFFu, x, d);
        if (lane == 0) d_part[a][blockIdx.x] = x;
    }
}

__global__ void scan_p2() {
    int a = blockIdx.x;
    int t = threadIdx.x;
    int v = (t < NBLK) ? d_part[a][t] : 0;
    int lane = t & 31, wid = t >> 5;
    int x = v;
    #pragma unroll
    for (int d = 1; d < 32; d <<= 1) {
        int y = __shfl_up_sync(0xFFFFFFFFu, x, d);
        if (lane >= d) x += y;
    }
    __shared__ int ws[4];
    if (lane == 31) ws[wid] = x;
    __syncthreads();
    int off = 0;
    for (int w = 0; w < wid; w++) off += ws[w];
    if (t < NBLK) d_part[a][t] = off + x - v;
}

__global__ void scan_p3() {
    int a = blockIdx.y;
    int i = blockIdx.x * 1024 + threadIdx.x;
    int raw = 0;
    if (i < NN) raw = (a == 0) ? cntA[i] : cntC[i];
    int v = raw + ((a == 0 && i < NN) ? 1 : 0);
    int lane = threadIdx.x & 31, wid = threadIdx.x >> 5;
    int x = v;
    #pragma unroll
    for (int d = 1; d < 32; d <<= 1) {
        int y = __shfl_up_sync(0xFFFFFFFFu, x, d);
        if (lane >= d) x += y;
    }
    __shared__ int ws[32];
    if (lane == 31) ws[wid] = x;
    __syncthreads();
    if (wid == 0) {
        int w = ws[lane];
        #pragma unroll
        for (int d = 1; d < 32; d <<= 1) {
            int y = __shfl_up_sync(0xFFFFFFFFu, w, d);
            if (lane >= d) w += y;
        }
        ws[lane] = w;
    }
    __syncthreads();
    int excl = (wid ? ws[wid - 1] : 0) + x - v + d_part[a][blockIdx.x];
    if (i < NN) {
        if (a == 0) {
            csrA_off[i] = excl;
            curA[i] = excl;
            csrA_val[excl + raw] = i;
            d_binv[i] = raw > 0 ? 1.0f / (float)raw : 0.0f;
        } else {
            csrC_off[i] = excl;
            curC[i] = excl;
            d_dinv[i] = raw > 0 ? 1.0f / (float)raw : 0.0f;
        }
    }
    if (i == NN - 1) {
        if (a == 0) csrA_off[NN] = excl + v;
        else csrC_off[NN] = excl + v;
    }
}

__global__ void fill_kernel(const int* __restrict__ ei) {
    int i = blockIdx.x * blockDim.x + threadIdx.x;
    if (i >= EE) return;
    int s = ei[i];
    int d = ei[EE + i];
    csrA_val[atomicAdd(&curA[d], 1)] = s;
    csrC_val[atomicAdd(&curC[s], 1)] = d;
}

// ---------------- merged weight conversion ----------------
#define S_W1 (FIN * 512 / 2)
#define S_W2 (256 * 512 / 2)
#define S_TH1 (334 * 128 / 2)
#define S_TH2 (128 * 128 / 2)
#define CV_TOT (S_W1 + 2 * S_W2 + S_TH1 + S_TH2 + 512 * 256 / 2)
__global__ void convert_all_kernel(const float* __restrict__ W1, const float* __restrict__ W2,
                                   const float* __restrict__ W3, const float* __restrict__ th1,
                                   const float* __restrict__ th2,
                                   const float* __restrict__ fc1w, const float* __restrict__ fc2w,
                                   const float* __restrict__ fc1b, const float* __restrict__ fc2b) {
    int i = blockIdx.x * blockDim.x + threadIdx.x;
    if (i >= CV_TOT) return;
    if (i < S_W1) {
        float2 v = ((const float2*)W1)[i];
        ((__half2*)d_w1h)[i] = __floats2half2_rn(v.x, v.y);
        return;
    }
    i -= S_W1;
    if (i < S_W2) {
        float2 v = ((const float2*)W2)[i];
        ((__half2*)d_w2h)[i] = __floats2half2_rn(v.x, v.y);
        return;
    }
    i -= S_W2;
    if (i < S_W2) {
        float2 v = ((const float2*)W3)[i];
        ((__half2*)d_w3h)[i] = __floats2half2_rn(v.x, v.y);
        return;
    }
    i -= S_W2;
    if (i < S_TH1) {
        float2 v = ((const float2*)th1)[i];
        ((__half2*)d_th1h)[i] = __floats2half2_rn(v.x, v.y);
        return;
    }
    i -= S_TH1;
    if (i < S_TH2) {
        float2 v = ((const float2*)th2)[i];
        ((__half2*)d_th2h)[i] = __floats2half2_rn(v.x, v.y);
        return;
    }
    i -= S_TH2;
    int idx = i * 2;
    int k = idx >> 8, n0 = idx & 255;
    float va = (k < 256) ? fc1w[n0 * 256 + k] : fc2w[n0 * 256 + (k - 256)];
    float vb = (k < 256) ? fc1w[(n0 + 1) * 256 + k] : fc2w[(n0 + 1) * 256 + (k - 256)];
    ((__half2*)d_bch)[i] = __floats2half2_rn(va, vb);
    if (idx < 256) {
        d_cb[idx] = fc1b[idx] + fc2b[idx];
        d_cb[idx + 1] = fc1b[idx + 1] + fc2b[idx + 1];
    }
}

__global__ void conv_mx_kernel(const float* __restrict__ x) {
    int idx = blockIdx.x * blockDim.x + threadIdx.x;
    if (idx >= NN * 40) return;
    int n = idx / 40, c2 = idx % 40;
    float a = 0.f, b = 0.f;
    int c = c2 * 2;
    if (c < FIN) a = x[(size_t)n * FIN + c];
    if (c + 1 < FIN) b = x[(size_t)n * FIN + c + 1];
    ((__half2*)d_mx16)[idx] = __floats2half2_rn(a, b);
}

// ---------------- fp16 tensor-core GEMM (m16n8k16 + ldmatrix + cp.async) ----------------
__device__ __forceinline__ void mma_f16(float* c, const uint32_t* a, uint32_t b0, uint32_t b1) {
    asm volatile(
        "mma.sync.aligned.m16n8k16.row.col.f32.f16.f16.f32 "
        "{%0,%1,%2,%3},{%4,%5,%6,%7},{%8,%9},{%0,%1,%2,%3};"
        : "+f"(c[0]), "+f"(c[1]), "+f"(c[2]), "+f"(c[3])
        : "r"(a[0]), "r"(a[1]), "r"(a[2]), "r"(a[3]), "r"(b0), "r"(b1));
}

__device__ __forceinline__ void ldsm_x4(uint32_t& r0, uint32_t& r1, uint32_t& r2, uint32_t& r3,
                                        uint32_t addr) {
    asm volatile("ldmatrix.sync.aligned.m8n8.x4.shared.b16 {%0,%1,%2,%3}, [%4];"
                 : "=r"(r0), "=r"(r1), "=r"(r2), "=r"(r3) : "r"(addr));
}

__device__ __forceinline__ void ldsm_x4t(uint32_t& r0, uint32_t& r1, uint32_t& r2, uint32_t& r3,
                                         uint32_t addr) {
    asm volatile("ldmatrix.sync.aligned.m8n8.x4.trans.shared.b16 {%0,%1,%2,%3}, [%4];"
                 : "=r"(r0), "=r"(r1), "=r"(r2), "=r"(r3) : "r"(addr));
}

__device__ __forceinline__ void cp8(uint32_t d, const void* s) {
    asm volatile("cp.async.ca.shared.global [%0], [%1], 8;" :: "r"(d), "l"(s));
}
__device__ __forceinline__ void cp8z(uint32_t d, const void* s, int sz) {
    asm volatile("cp.async.ca.shared.global [%0], [%1], 8, %2;" :: "r"(d), "l"(s), "r"(sz));
}
__device__ __forceinline__ void cp_commit() {
    asm volatile("cp.async.commit_group;");
}
template <int N>
__device__ __forceinline__ void cp_wait() {
    asm volatile("cp.async.wait_group %0;" :: "n"(N));
}

#define APITCH 80
#define BPITCH 272
#define ABYTES (128 * APITCH)
#define BBYTES (32 * BPITCH)
#define NSTAGE 3

template <int ASRC, int EPI>
__global__ __launch_bounds__(256) void gemm16_kernel(
    const void* __restrict__ Ap, int lda, int K1,
    const float* __restrict__ A2, int lda2,
    const __half* __restrict__ Hh, int ldhh,
    const __half* __restrict__ B1, const __half* __restrict__ B2, int ldb,
    int SP, int KV1, int KV2,
    float* __restrict__ Cf, int ldc,
    __half* __restrict__ Ch, int ldch,
    int M, int N, int Ktot,
    const float* __restrict__ bias, int relu, float scale,
    const float* __restrict__ molb)
{
    __shared__ __align__(16) uint8_t AsmB[NSTAGE * ABYTES];
    __shared__ __align__(16) uint8_t BsmB[NSTAGE * BBYTES];
    int tid = threadIdx.x;
    int lane = tid & 31, wid = tid >> 5;
    int wm = wid & 3, wn = wid >> 2;
    int row0 = blockIdx.y * 128, col0 = blockIdx.x * 128;
    int g = lane >> 2, tg = lane & 3;
    int l15 = lane & 15;
    int lhi = (lane & 16) ? 8 : 0;

    float acc[2][8][4];
    #pragma unroll
    for (int mi = 0; mi < 2; mi++)
        #pragma unroll
        for (int ni = 0; ni < 8; ni++)
            #pragma unroll
            for (int q = 0; q < 4; q++) acc[mi][ni][q] = 0.0f;

    const float* Af = (const float*)Ap;
    const __half* Ah = (const __half*)Ap;

    uint32_t aShm = (uint32_t)__cvta_generic_to_shared(AsmB);
    uint32_t bShm = (uint32_t)__cvta_generic_to_shared(BsmB);
    int T = (Ktot + 31) >> 5;

    auto computeTile = [&](int buf) {
        uint32_t aB = aShm + buf * ABYTES;
        uint32_t bB = bShm + buf * BBYTES;
        #pragma unroll
        for (int ks = 0; ks < 2; ks++) {
            uint32_t afr[2][4];
            #pragma unroll
            for (int mi = 0; mi < 2; mi++) {
                uint32_t addr = aB + (uint32_t)((wm * 32 + mi * 16 + l15) * APITCH
                                                + (ks * 16 + lhi) * 2);
                ldsm_x4(afr[mi][0], afr[mi][1], afr[mi][2], afr[mi][3], addr);
            }
            uint32_t bfr[8][2];
            #pragma unroll
            for (int p = 0; p < 4; p++) {
                uint32_t addr = bB + (uint32_t)((ks * 16 + l15) * BPITCH
                                                + (wn * 64 + p * 16 + lhi) * 2);
                ldsm_x4t(bfr[2 * p][0], bfr[2 * p][1], bfr[2 * p + 1][0], bfr[2 * p + 1][1], addr);
            }
            #pragma unroll
            for (int ni = 0; ni < 8; ni++) {
                mma_f16(acc[0][ni], afr[0], bfr[ni][0], bfr[ni][1]);
                mma_f16(acc[1][ni], afr[1], bfr[ni][0], bfr[ni][1]);
            }
        }
    };

    if (ASRC == 2) {
        auto issueTile = [&](int k0, int buf) {
            uint32_t aB = aShm + buf * ABYTES;
            uint32_t bB = bShm + buf * BBYTES;
            #pragma unroll
            for (int i = 0; i < 4; i++) {
                int l4 = tid + i * 256;
                int r = l4 >> 3, c4 = (l4 & 7) << 2;
                int grow = row0 + r;
                if (grow >= M) grow = M - 1;
                int gk = k0 + c4;
                cp8(aB + r * APITCH + c4 * 2, Ah + (size_t)grow * lda + gk);
            }
            #pragma unroll
            for (int i = 0; i < 4; i++) {
                int l4 = tid + i * 256;
                int k = l4 >> 5, n4 = (l4 & 31) << 2;
                int kk = k0 + k;
                const __half* src = B1;
                int sz = 0;
                if (kk < SP) {
                    if (kk < KV1) { src = B1 + (size_t)kk * ldb + col0 + n4; sz = 8; }
                } else if (kk < Ktot) {
                    int j = kk - SP;
                    if (j < KV2) { src = B2 + (size_t)j * ldb + col0 + n4; sz = 8; }
                }
                cp8z(bB + k * BPITCH + n4 * 2, src, sz);
            }
            cp_commit();
        };
        issueTile(0, 0);
        if (T > 1) issueTile(32, 1);
        for (int t = 0; t < T; t++) {
            int buf = t % NSTAGE;
            if (t + 2 < T) {
                issueTile((t + 2) << 5, (t + 2) % NSTAGE);
                cp_wait<2>();
            } else if (t + 1 < T) {
                cp_wait<1>();
            } else {
                cp_wait<0>();
            }
            __syncthreads();
            computeTile(buf);
            __syncthreads();
        }
    } else {
        float4 raf[4];
        uint2 rbh[4];
        auto loadA = [&](int k0) {
            #pragma unroll
            for (int i = 0; i < 4; i++) {
                int l4 = tid + i * 256;
                int r = l4 >> 3, c4 = (l4 & 7) << 2;
                int grow = row0 + r, gk = k0 + c4;
                float4 v = make_float4(0.f, 0.f, 0.f, 0.f);
                if (grow < M) {
                    if (gk + 3 < K1) {
                        v = *(const float4*)(Af + (size_t)grow * lda + gk);
                    } else {
                        float* pv = &v.x;
                        #pragma unroll
                        for (int j = 0; j < 4; j++) {
                            int kk = gk + j;
                            float x = 0.0f;
                            if (kk < K1) x = Af[(size_t)grow * lda + kk];
                            else if (kk < Ktot) x = A2[(size_t)grow * lda2 + (kk - K1)];
                            pv[j] = x;
                        }
                    }
                }
                raf[i] = v;
            }
        };
        auto storeA = [&](uint8_t* As) {
            #pragma unroll
            for (int i = 0; i < 4; i++) {
                int l4 = tid + i * 256;
                int r = l4 >> 3, c4 = (l4 & 7) << 2;
                __half2 h0 = __floats2half2_rn(raf[i].x, raf[i].y);
                __half2 h1 = __floats2half2_rn(raf[i].z, raf[i].w);
                uint2 u;
                u.x = *(uint32_t*)&h0;
                u.y = *(uint32_t*)&h1;
                *(uint2*)(As + r * APITCH + c4 * 2) = u;
            }
        };
        auto loadB = [&](int k0) {
            #pragma unroll
            for (int i = 0; i < 4; i++) {
                int l4 = tid + i * 256;
                int k = l4 >> 5, n4 = (l4 & 31) << 2;
                int kk = k0 + k;
                uint2 u = make_uint2(0u, 0u);
                if (kk < SP) {
                    if (kk < KV1) u = *(const uint2*)(B1 + (size_t)kk * ldb + col0 + n4);
                } else if (kk < Ktot) {
                    int j = kk - SP;
                    if (j < KV2) u = *(const uint2*)(B2 + (size_t)j * ldb + col0 + n4);
                }
                rbh[i] = u;
            }
        };
        auto storeB = [&](uint8_t* Bs) {
            #pragma unroll
            for (int i = 0; i < 4; i++) {
                int l4 = tid + i * 256;
                int k = l4 >> 5, n4 = (l4 & 31) << 2;
                *(uint2*)(Bs + k * BPITCH + n4 * 2) = rbh[i];
            }
        };
        loadA(0); loadB(0);
        storeA(AsmB); storeB(BsmB);
        __syncthreads();
        for (int t = 0; t < T; t++) {
            int buf = t & 1;
            bool more = (t + 1 < T);
            if (more) { loadA((t + 1) << 5); loadB((t + 1) << 5); }
            computeTile(buf);
            if (more) {
                storeA(AsmB + (buf ^ 1) * ABYTES);
                storeB(BsmB + (buf ^ 1) * BBYTES);
            }
            __syncthreads();
        }
    }

    // epilogue
    #pragma unroll
    for (int mi = 0; mi < 2; mi++) {
        int r0 = row0 + wm * 32 + mi * 16 + g;
        #pragma unroll
        for (int ni = 0; ni < 8; ni++) {
            int c = col0 + wn * 64 + ni * 8 + tg * 2;
            float v0 = acc[mi][ni][0], v1 = acc[mi][ni][1];
            float v2 = acc[mi][ni][2], v3 = acc[mi][ni][3];
            if (EPI == 0) {
                float b0v = bias ? bias[c] : 0.0f;
                float b1v = bias ? bias[c + 1] : 0.0f;
                v0 = v0 * scale + b0v; v1 = v1 * scale + b1v;
                v2 = v2 * scale + b0v; v3 = v3 * scale + b1v;
                if (relu) {
                    v0 = fmaxf(v0, 0.f); v1 = fmaxf(v1, 0.f);
                    v2 = fmaxf(v2, 0.f); v3 = fmaxf(v3, 0.f);
                }
                if (r0 < M) {
                    if (Cf) *(float2*)(Cf + (size_t)r0 * ldc + c) = make_float2(v0, v1);
                    if (Ch) *(__half2*)(Ch + (size_t)r0 * ldch + c) = __floats2half2_rn(v0, v1);
                }
                if (r0 + 8 < M) {
                    if (Cf) *(float2*)(Cf + (size_t)(r0 + 8) * ldc + c) = make_float2(v2, v3);
                    if (Ch) *(__half2*)(Ch + (size_t)(r0 + 8) * ldch + c) = __floats2half2_rn(v2, v3);
                }
            } else {
                const __half* Ah2 = (const __half*)Ap;
                float cb0 = bias[c] + molb[c];
                float cb1 = bias[c + 1] + molb[c + 1];
                #pragma unroll
                for (int hh = 0; hh < 2; hh++) {
                    int r = r0 + hh * 8;
                    if (r >= M) continue;
                    float va = hh ? v2 : v0, vb = hh ? v3 : v1;
                    float z0 = 1.0f / (1.0f + __expf(-(va + cb0)));
                    float z1 = 1.0f / (1.0f + __expf(-(vb + cb1)));
                    float2 xv = __half22float2(*(const __half2*)(Ah2 + (size_t)r * lda + c));
                    float2 hv = __half22float2(*(const __half2*)(Hh + (size_t)r * ldhh + c));
                    float o0 = z0 * xv.x + (1.0f - z0) * hv.x;
                    float o1 = z1 * xv.y + (1.0f - z1) * hv.y;
                    if (Cf) *(float2*)(Cf + (size_t)r * ldc + c) = make_float2(o0, o1);
                    if (Ch) *(__half2*)(Ch + (size_t)r * ldch + c) = __floats2half2_rn(o0, o1);
                }
            }
        }
    }
}

template <int ASRC, int EPI>
static void run_gemm(const void* A, int lda, int K1, const float* A2, int lda2,
                     const __half* Hh, int ldhh,
                     const __half* B1, const __half* B2, int ldb, int SP, int KV1, int KV2,
                     float* Cf, int ldc, __half* Ch, int ldch,
                     int M, int N, int Ktot,
                     const float* bias, int relu, float scale, const float* molb) {
    dim3 grid(N / 128, (M + 127) / 128);
    gemm16_kernel<ASRC, EPI><<<grid, 256>>>(
        A, lda, K1, A2, lda2, Hh, ldhh, B1, B2, ldb, SP, KV1, KV2,
        Cf, ldc, Ch, ldch, M, N, Ktot, bias, relu, scale, molb);
}

// ---------------- attention logits ----------------
// all three layers' wv in one launch; blockIdx.y = layer
__global__ void build_wv_all_kernel(const float* __restrict__ W1p,
                                    const float* __restrict__ W2p,
                                    const float* __restrict__ W3p,
                                    const float* __restrict__ as1, const float* __restrict__ ad1,
                                    const float* __restrict__ as2, const float* __restrict__ ad2,
                                    const float* __restrict__ as3, const float* __restrict__ ad3) {
    int layer = blockIdx.y;
    int k = blockIdx.x, t = threadIdx.x;
    const float* W = (layer == 0) ? W1p : (layer == 1) ? W2p : W3p;
    const float* as = (layer == 0) ? as1 : (layer == 1) ? as2 : as3;
    const float* ad = (layer == 0) ? ad1 : (layer == 1) ? ad2 : ad3;
    int K = (layer == 0) ? FIN : 256;
    if (k >= K) return;
    float w0 = W[(size_t)k * 512 + t], w1 = W[(size_t)k * 512 + 256 + t];
    float p0 = w0 * as[t], p1 = w1 * as[256 + t];
    float p2 = w0 * ad[t], p3 = w1 * ad[256 + t];
    __shared__ float red[8][4];
    int lane = t & 31, wid = t >> 5;
    #pragma unroll
    for (int d = 16; d; d >>= 1) {
        p0 += __shfl_down_sync(0xFFFFFFFFu, p0, d);
        p1 += __shfl_down_sync(0xFFFFFFFFu, p1, d);
        p2 += __shfl_down_sync(0xFFFFFFFFu, p2, d);
        p3 += __shfl_down_sync(0xFFFFFFFFu, p3, d);
    }
    if (lane == 0) { red[wid][0] = p0; red[wid][1] = p1; red[wid][2] = p2; red[wid][3] = p3; }
    __syncthreads();
    if (t == 0) {
        float r0 = 0, r1 = 0, r2 = 0, r3 = 0;
        #pragma unroll
        for (int w = 0; w < 8; w++) { r0 += red[w][0]; r1 += red[w][1]; r2 += red[w][2]; r3 += red[w][3]; }
        float* wv = d_wv3 + layer * 1024;
        wv[k * 4 + 0] = r0; wv[k * 4 + 1] = r1; wv[k * 4 + 2] = r2; wv[k * 4 + 3] = r3;
    }
}

__global__ void attn2_kernel(const float* __restrict__ x, int K, int layer) {
    int warp = threadIdx.x >> 5, lane = threadIdx.x & 31;
    int n = blockIdx.x * 4 + warp;
    if (n >= NN) return;
    const float4* wvp = (const float4*)(d_wv3 + layer * 1024);
    const float* xr = x + (size_t)n * K;
    float s0 = 0, s1 = 0, s2 = 0, s3 = 0;
    for (int c = lane; c < K; c += 32) {
        float xv = xr[c];
        float4 wv = wvp[c];
        s0 += xv * wv.x; s1 += xv * wv.y; s2 += xv * wv.z; s3 += xv * wv.w;
    }
    #pragma unroll
    for (int d = 16; d; d >>= 1) {
        s0 += __shfl_down_sync(0xFFFFFFFFu, s0, d);
        s1 += __shfl_down_sync(0xFFFFFFFFu, s1, d);
        s2 += __shfl_down_sync(0xFFFFFFFFu, s2, d);
        s3 += __shfl_down_sync(0xFFFFFFFFu, s3, d);
    }
    if (lane == 0) {
        d_asrc[n * 2] = s0; d_asrc[n * 2 + 1] = s1;
        d_adst[n * 2] = s2; d_adst[n * 2 + 1] = s3;
    }
}

__global__ void attn2h_kernel(const __half* __restrict__ x, int ldh, int layer) {
    int warp = threadIdx.x >> 5, lane = threadIdx.x & 31;
    int n = blockIdx.x * 4 + warp;
    if (n >= NN) return;
    const float4* wvp = (const float4*)(d_wv3 + layer * 1024);
    const __half2* xr = (const __half2*)(x + (size_t)n * ldh);
    float s0 = 0, s1 = 0, s2 = 0, s3 = 0;
    #pragma unroll
    for (int w = 0; w < 4; w++) {
        int c2 = lane + w * 32;
        float2 xv = __half22float2(xr[c2]);
        float4 wv0 = wvp[c2 * 2];
        float4 wv1 = wvp[c2 * 2 + 1];
        s0 += xv.x * wv0.x + xv.y * wv1.x;
        s1 += xv.x * wv0.y + xv.y * wv1.y;
        s2 += xv.x * wv0.z + xv.y * wv1.z;
        s3 += xv.x * wv0.w + xv.y * wv1.w;
    }
    #pragma unroll
    for (int d = 16; d; d >>= 1) {
        s0 += __shfl_down_sync(0xFFFFFFFFu, s0, d);
        s1 += __shfl_down_sync(0xFFFFFFFFu, s1, d);
        s2 += __shfl_down_sync(0xFFFFFFFFu, s2, d);
        s3 += __shfl_down_sync(0xFFFFFFFFu, s3, d);
    }
    if (lane == 0) {
        d_asrc[n * 2] = s0; d_asrc[n * 2 + 1] = s1;
        d_adst[n * 2] = s2; d_adst[n * 2 + 1] = s3;
    }
}

__device__ __forceinline__ float lrelu02(float v) { return v >= 0.0f ? v : 0.2f * v; }

// ---------------- fused no-max softmax + aggregate ----------------
__global__ void gat_agg80_kernel(const __half2* __restrict__ src,
                                 __half2* __restrict__ agg) {
    int n = blockIdx.x;
    int t = threadIdx.x;  // 64
    int lane = t & 31, wid = t >> 5;
    int s0 = csrA_off[n], s1 = csrA_off[n + 1];
    float2 adst = ((const float2*)d_adst)[n];
    __shared__ int ssrc[64];
    __shared__ float2 salp[64];
    __shared__ float2 ssum[2];
    float a0x = 0, a0y = 0, a1x = 0, a1y = 0, sum0 = 0, sum1 = 0;
    bool act = t < 40;
    for (int base = s0; base < s1; base += 64) {
        int cnt = min(64, s1 - base);
        __syncthreads();
        if (t < cnt) {
            int sidx = csrA_val[base + t];
            ssrc[t] = sidx;
            float2 as = ((const float2*)d_asrc)[sidx];
            float p0 = __expf(lrelu02(as.x + adst.x));
            float p1 = __expf(lrelu02(as.y + adst.y));
            salp[t] = make_float2(p0, p1);
            sum0 += p0; sum1 += p1;
        }
        __syncthreads();
        if (act) {
            #pragma unroll 2
            for (int j = 0; j < cnt; j++) {
                float2 f = __half22float2(src[(size_t)ssrc[j] * 40 + t]);
                float2 a = salp[j];
                a0x += a.x * f.x; a0y += a.x * f.y;
                a1x += a.y * f.x; a1y += a.y * f.y;
            }
        }
    }
    #pragma unroll
    for (int d = 16; d; d >>= 1) {
        sum0 += __shfl_xor_sync(0xFFFFFFFFu, sum0, d);
        sum1 += __shfl_xor_sync(0xFFFFFFFFu, sum1, d);
    }
    if (lane == 0) ssum[wid] = make_float2(sum0, sum1);
    __syncthreads();
    if (act) {
        float r0 = 1.0f / (ssum[0].x + ssum[1].x);
        float r1 = 1.0f / (ssum[0].y + ssum[1].y);
        agg[(size_t)n * 80 + t] = __floats2half2_rn(a0x * r0, a0y * r0);
        agg[(size_t)n * 80 + 40 + t] = __floats2half2_rn(a1x * r1, a1y * r1);
    }
}

__global__ void gat_agg256_kernel(const __half2* __restrict__ src, int ldh2,
                                  __half2* __restrict__ agg) {
    int n = blockIdx.x;
    int t = threadIdx.x;
    int lane = t & 31, wwid = t >> 5;
    int gid = t >> 6, tl = t & 63;
    int s0 = csrA_off[n], s1 = csrA_off[n + 1];
    float2 adst = ((const float2*)d_adst)[n];
    float h0[4] = {0, 0, 0, 0}, h1[4] = {0, 0, 0, 0};
    float sum0 = 0, sum1 = 0;
    __shared__ int ssrc[128];
    __shared__ float2 salp[128];
    __shared__ float red[64][8];
    __shared__ float2 ssum[4];
    for (int base = s0; base < s1; base += 128) {
        int cnt = min(128, s1 - base);
        __syncthreads();
        if (t < cnt) {
            int sidx = csrA_val[base + t];
            ssrc[t] = sidx;
            float2 as = ((const float2*)d_asrc)[sidx];
            float p0 = __expf(lrelu02(as.x + adst.x));
            float p1 = __expf(lrelu02(as.y + adst.y));
            salp[t] = make_float2(p0, p1);
            sum0 += p0; sum1 += p1;
        }
        __syncthreads();
        for (int j = gid; j < cnt; j += 2) {
            uint2 u = *(const uint2*)(src + (size_t)ssrc[j] * ldh2 + tl * 2);
            float2 g0 = __half22float2(*(__half2*)&u.x);
            float2 g1 = __half22float2(*(__half2*)&u.y);
            float2 a = salp[j];
            h0[0] += a.x * g0.x; h0[1] += a.x * g0.y; h0[2] += a.x * g1.x; h0[3] += a.x * g1.y;
            h1[0] += a.y * g0.x; h1[1] += a.y * g0.y; h1[2] += a.y * g1.x; h1[3] += a.y * g1.y;
        }
    }
    #pragma unroll
    for (int d = 16; d; d >>= 1) {
        sum0 += __shfl_xor_sync(0xFFFFFFFFu, sum0, d);
        sum1 += __shfl_xor_sync(0xFFFFFFFFu, sum1, d);
    }
    __syncthreads();
    if (lane == 0) ssum[wwid] = make_float2(sum0, sum1);
    if (gid == 1) {
        red[tl][0] = h0[0]; red[tl][1] = h0[1]; red[tl][2] = h0[2]; red[tl][3] = h0[3];
        red[tl][4] = h1[0]; red[tl][5] = h1[1]; red[tl][6] = h1[2]; red[tl][7] = h1[3];
    }
    __syncthreads();
    if (gid == 0) {
        float ts0 = ssum[0].x + ssum[1].x + ssum[2].x + ssum[3].x;
        float ts1 = ssum[0].y + ssum[1].y + ssum[2].y + ssum[3].y;
        float r0 = 1.0f / ts0, r1 = 1.0f / ts1;
        h0[0] += red[tl][0]; h0[1] += red[tl][1]; h0[2] += red[tl][2]; h0[3] += red[tl][3];
        h1[0] += red[tl][4]; h1[1] += red[tl][5]; h1[2] += red[tl][6]; h1[7 - 7] += 0;
        h1[0] += 0;
        h1[1] += 0;
        h1[2] += 0;
        h1[3] += red[tl][7];
        __half2* row = agg + (size_t)n * 256;
        row[tl * 2] = __floats2half2_rn(h0[0] * r0, h0[1] * r0);
        row[tl * 2 + 1] = __floats2half2_rn(h0[2] * r0, h0[3] * r0);
        row[128 + tl * 2] = __floats2half2_rn(h1[0] * r1, h1[1] * r1);
        row[128 + tl * 2 + 1] = __floats2half2_rn(h1[2] * r1, h1[3] * r1);
    }
}

// ---------------- hypergraph ----------------
template <bool OUTH>
__global__ void hyper_gather_kernel(const __half2* __restrict__ in, void* __restrict__ outp,
                                    int ostride, const float* __restrict__ bias,
                                    int which, int relu) {
    const int* off = which ? csrC_off : csrA_off;
    const int* val = which ? csrC_val : csrA_val;
    int n = blockIdx.x;
    int t = threadIdx.x;
    int gid = t >> 5, tl = t & 31;
    int s0 = off[n], s1 = off[n + 1];
    if (!which) s1 -= 1;
    float a[4] = {0, 0, 0, 0};
    __shared__ int sv[64];
    __shared__ float red[32][4];
    for (int base = s0; base < s1; base += 64) {
        int cnt = min(64, s1 - base);
        __syncthreads();
        if (t < cnt) sv[t] = val[base + t];
        __syncthreads();
        for (int j = gid; j < cnt; j += 2) {
            uint2 u = *(const uint2*)(in + (size_t)sv[j] * 64 + tl * 2);
            float2 g0 = __half22float2(*(__half2*)&u.x);
            float2 g1 = __half22float2(*(__half2*)&u.y);
            a[0] += g0.x; a[1] += g0.y; a[2] += g1.x; a[3] += g1.y;
        }
    }
    __syncthreads();
    if (gid == 1) { red[tl][0] = a[0]; red[tl][1] = a[1]; red[tl][2] = a[2]; red[tl][3] = a[3]; }
    __syncthreads();
    if (gid == 0) {
        a[0] += red[tl][0]; a[1] += red[tl][1]; a[2] += red[tl][2]; a[3] += red[tl][3];
        float inv = which ? d_dinv[n] : d_binv[n];
        #pragma unroll
        for (int q = 0; q < 4; q++) a[q] *= inv;
        if (bias) {
            a[0] += bias[tl * 4]; a[1] += bias[tl * 4 + 1];
            a[2] += bias[tl * 4 + 2]; a[3] += bias[tl * 4 + 3];
        }
        if (relu) {
            #pragma unroll
            for (int q = 0; q < 4; q++) a[q] = fmaxf(a[q], 0.f);
        }
        if (OUTH) {
            __half2* o = (__half2*)outp;
            o[(size_t)n * ostride + tl * 2] = __floats2half2_rn(a[0], a[1]);
            o[(size_t)n * ostride + tl * 2 + 1] = __floats2half2_rn(a[2], a[3]);
        } else {
            float2* o = (float2*)outp;
            o[(size_t)n * ostride + tl * 2] = make_float2(a[0], a[1]);
            o[(size_t)n * ostride + tl * 2 + 1] = make_float2(a[2], a[3]);
        }
    }
}

// ---------------- host side ----------------
extern "C" void kernel_launch(void* const* d_in, const int* in_sizes, int n_in,
                              void* d_out, int out_size) {
    const float* mol_x = (const float*)d_in[0];
    const int*   ei    = (const int*)d_in[1];
    const float* W1 = (const float*)d_in[3];
    const float* as1 = (const float*)d_in[4];
    const float* ad1 = (const float*)d_in[5];
    const float* b1 = (const float*)d_in[6];
    const float* W2 = (const float*)d_in[7];
    const float* as2 = (const float*)d_in[8];
    const float* ad2 = (const float*)d_in[9];
    const float* b2 = (const float*)d_in[10];
    const float* W3 = (const float*)d_in[11];
    const float* as3 = (const float*)d_in[12];
    const float* ad3 = (const float*)d_in[13];
    const float* b3 = (const float*)d_in[14];
    const float* fc1_w = (const float*)d_in[15];
    const float* fc1_b = (const float*)d_in[16];
    const float* fc2_w = (const float*)d_in[17];
    const float* fc2_b = (const float*)d_in[18];
    const float* mol_bias = (const float*)d_in[19];
    const float* theta1 = (const float*)d_in[20];
    const float* hb1 = (const float*)d_in[21];
    const float* theta2 = (const float*)d_in[22];
    const float* hb2 = (const float*)d_in[23];

    __half *p_mx, *p_catA, *p_catB, *p_agg, *p_xt, *p_ef, *p_hy16;
    __half *p_w1h, *p_w2h, *p_w3h, *p_bch, *p_th1h, *p_th2h;
    float *p_cb;
    cudaGetSymbolAddress((void**)&p_mx, d_mx16);
    cudaGetSymbolAddress((void**)&p_catA, d_catA);
    cudaGetSymbolAddress((void**)&p_catB, d_catB);
    cudaGetSymbolAddress((void**)&p_agg, d_agg);
    cudaGetSymbolAddress((void**)&p_xt, d_xt);
    cudaGetSymbolAddress((void**)&p_ef, d_ef);
    cudaGetSymbolAddress((void**)&p_hy16, d_hy16);
    cudaGetSymbolAddress((void**)&p_w1h, d_w1h);
    cudaGetSymbolAddress((void**)&p_w2h, d_w2h);
    cudaGetSymbolAddress((void**)&p_w3h, d_w3h);
    cudaGetSymbolAddress((void**)&p_bch, d_bch);
    cudaGetSymbolAddress((void**)&p_th1h, d_th1h);
    cudaGetSymbolAddress((void**)&p_th2h, d_th2h);
    cudaGetSymbolAddress((void**)&p_cb, d_cb);
    float* p_out = (float*)d_out;

    // side stream for the CSR-independent front-end (capture-legal fork/join)
    cudaStream_t s2;
    cudaStreamCreateWithFlags(&s2, cudaStreamNonBlocking);
    cudaEvent_t evFork, evJoin;
    cudaEventCreateWithFlags(&evFork, cudaEventDisableTiming);
    cudaEventCreateWithFlags(&evJoin, cudaEventDisableTiming);

    cudaEventRecord(evFork, 0);
    cudaStreamWaitEvent(s2, evFork, 0);

    // ---- side chain (stream s2): conversions + logit precompute + layer-1 attn ----
    conv_mx_kernel<<<(NN * 40 + 255) / 256, 256, 0, s2>>>(mol_x);
    convert_all_kernel<<<(CV_TOT + 255) / 256, 256, 0, s2>>>(W1, W2, W3, theta1, theta2,
                                                             fc1_w, fc2_w, fc1_b, fc2_b);
    build_wv_all_kernel<<<dim3(256, 3), 256, 0, s2>>>(W1, W2, W3, as1, ad1, as2, ad2, as3, ad3);
    attn2_kernel<<<(NN + 3) / 4, 128, 0, s2>>>(mol_x, FIN, 0);
    cudaEventRecord(evJoin, s2);

    // ---- main chain: CSR build ----
    zero_counts_kernel<<<(NN + 255) / 256, 256>>>();
    count_kernel<<<(EE + 255) / 256, 256>>>(ei);
    scan_p1<<<dim3(NBLK, 2), 1024>>>();
    scan_p2<<<2, 128>>>();
    scan_p3<<<dim3(NBLK, 2), 1024>>>();
    fill_kernel<<<(EE + 255) / 256, 256>>>(ei);

    cudaStreamWaitEvent(0, evJoin, 0);

    // ---- GAT layer 1: h1 (fp16) = relu(gat(mol_x)) ----
    gat_agg80_kernel<<<NN, 64>>>((const __half2*)p_mx, (__half2*)p_agg);
    run_gemm<2, 0>(p_agg, 160, 0, nullptr, 0, nullptr, 0, p_w1h, p_w1h + 256, 512, 80, FIN, FIN,
                   nullptr, 0, p_catA + 256, 512, NN, 256, 160, b1, 1, 0.5f, nullptr);

    // ---- GAT layer 2 ----
    attn2h_kernel<<<(NN + 3) / 4, 128>>>(p_catA + 256, 512, 1);
    gat_agg256_kernel<<<NN, 128>>>((const __half2*)(p_catA + 256), 256, (__half2*)p_agg);
    run_gemm<2, 0>(p_agg, 512, 0, nullptr, 0, nullptr, 0, p_w2h, p_w2h + 256, 512, 256, 256, 256,
                   nullptr, 0, p_catA, 512, NN, 256, 512, b2, 1, 0.5f, nullptr);
    run_gemm<2, 2>(p_catA, 512, 0, nullptr, 0, p_catA + 256, 512, p_bch, nullptr, 256, 512, 512, 0,
                   nullptr, 0, p_catB + 256, 512, NN, 256, 512, p_cb, 0, 1.0f, mol_bias);

    // ---- GAT layer 3 ----
    attn2h_kernel<<<(NN + 3) / 4, 128>>>(p_catB + 256, 512, 2);
    gat_agg256_kernel<<<NN, 128>>>((const __half2*)(p_catB + 256), 256, (__half2*)p_agg);
    run_gemm<2, 0>(p_agg, 512, 0, nullptr, 0, nullptr, 0, p_w3h, p_w3h + 256, 512, 256, 256, 256,
                   nullptr, 0, p_catB, 512, NN, 256, 512, b3, 0, 0.5f, nullptr);
    run_gemm<2, 2>(p_catB, 512, 0, nullptr, 0, p_catB + 256, 512, p_bch, nullptr, 256, 512, 512, 0,
                   p_out, 384, nullptr, 0, NN, 256, 512, p_cb, 0, 1.0f, mol_bias);

    // ---- hypergraph branch ----
    run_gemm<0, 0>(p_out, 384, 256, mol_x, FIN, nullptr, 0, p_th1h, nullptr, 128, 334, 334, 0,
                   nullptr, 0, p_xt, 128, NN, 128, 334, nullptr, 0, 1.0f, nullptr);
    hyper_gather_kernel<true ><<<NN, 64>>>((const __half2*)p_xt, p_ef, 64, nullptr, 0, 0);
    hyper_gather_kernel<true ><<<NN, 64>>>((const __half2*)p_ef, p_hy16, 64, hb1, 1, 1);
    run_gemm<2, 0>(p_hy16, 128, 0, nullptr, 0, nullptr, 0, p_th2h, nullptr, 128, 128, 128, 0,
                   nullptr, 0, p_xt, 128, NN, 128, 128, nullptr, 0, 1.0f, nullptr);
    hyper_gather_kernel<true ><<<NN, 64>>>((const __half2*)p_xt, p_ef, 64, nullptr, 0, 0);
    hyper_gather_kernel<false><<<NN, 64>>>((const __half2*)p_ef, (float2*)p_out + 128, 192,
                                           hb2, 1, 1);
}

// round 17
// speedup vs baseline: 1.0028x; 1.0001x over previous
#include <cuda_runtime.h>
#include <cuda_fp16.h>
#include <math.h>
#include <stdint.h>

#define NN 100000
#define EE 3200000
#define EA (EE + NN)
#define FIN 78
#define FG 256
#define FH 128
#define NBLK 98   // ceil(NN / 1024)

// ---------------- scratch (device globals; no allocation) ----------------
__device__ __half d_mx16[(size_t)NN * 80];
__device__ __half d_catA[(size_t)NN * 512];   // [x1 | h1]
__device__ __half d_catB[(size_t)NN * 512];   // [x2 | h2]
__device__ __half d_agg[(size_t)NN * 512];
__device__ __half d_xt[(size_t)NN * 128];
__device__ __half d_ef[(size_t)NN * 128];
__device__ __half d_hy16[(size_t)NN * 128];
__device__ __half d_w1h[FIN * 512];
__device__ __half d_w2h[256 * 512];
__device__ __half d_w3h[256 * 512];
__device__ __half d_bch[512 * 256];
__device__ __half d_th1h[334 * 128];
__device__ __half d_th2h[128 * 128];
__device__ float d_cb[256];
__device__ float d_wv3[3 * 256 * 4];
__device__ float d_asrc[NN * 2];
__device__ float d_adst[NN * 2];
__device__ int csrA_off[NN + 1]; __device__ int csrA_val[EA];
__device__ int csrC_off[NN + 1]; __device__ int csrC_val[EE];
__device__ int cntA[NN], cntC[NN];
__device__ int curA[NN], curC[NN];
__device__ int d_part[2][NBLK + 2];
__device__ float d_binv[NN], d_dinv[NN];

// ---------------- CSR construction ----------------
__global__ void zero_counts_kernel() {
    int i = blockIdx.x * blockDim.x + threadIdx.x;
    if (i < NN) { cntA[i] = 0; cntC[i] = 0; }
}

__global__ void count_kernel(const int* __restrict__ ei) {
    int i = blockIdx.x * blockDim.x + threadIdx.x;
    if (i >= EE) return;
    int s = ei[i];
    int d = ei[EE + i];
    atomicAdd(&cntA[d], 1);
    atomicAdd(&cntC[s], 1);
}

__global__ void scan_p1() {
    int a = blockIdx.y;
    int i = blockIdx.x * 1024 + threadIdx.x;
    int v = 0;
    if (i < NN) v = (a == 0) ? (cntA[i] + 1) : cntC[i];
    int lane = threadIdx.x & 31, wid = threadIdx.x >> 5;
    #pragma unroll
    for (int d = 16; d; d >>= 1) v += __shfl_down_sync(0xFFFFFFFFu, v, d);
    __shared__ int ws[32];
    if (lane == 0) ws[wid] = v;
    __syncthreads();
    if (wid == 0) {
        int x = ws[lane];
        #pragma unroll
        for (int d = 16; d; d >>= 1) x += __shfl_down_sync(0xFFFFFFFFu, x, d);
        if (lane == 0) d_part[a][blockIdx.x] = x;
    }
}

__global__ void scan_p2() {
    int a = blockIdx.x;
    int t = threadIdx.x;
    int v = (t < NBLK) ? d_part[a][t] : 0;
    int lane = t & 31, wid = t >> 5;
    int x = v;
    #pragma unroll
    for (int d = 1; d < 32; d <<= 1) {
        int y = __shfl_up_sync(0xFFFFFFFFu, x, d);
        if (lane >= d) x += y;
    }
    __shared__ int ws[4];
    if (lane == 31) ws[wid] = x;
    __syncthreads();
    int off = 0;
    for (int w = 0; w < wid; w++) off += ws[w];
    if (t < NBLK) d_part[a][t] = off + x - v;
}

__global__ void scan_p3() {
    int a = blockIdx.y;
    int i = blockIdx.x * 1024 + threadIdx.x;
    int raw = 0;
    if (i < NN) raw = (a == 0) ? cntA[i] : cntC[i];
    int v = raw + ((a == 0 && i < NN) ? 1 : 0);
    int lane = threadIdx.x & 31, wid = threadIdx.x >> 5;
    int x = v;
    #pragma unroll
    for (int d = 1; d < 32; d <<= 1) {
        int y = __shfl_up_sync(0xFFFFFFFFu, x, d);
        if (lane >= d) x += y;
    }
    __shared__ int ws[32];
    if (lane == 31) ws[wid] = x;
    __syncthreads();
    if (wid == 0) {
        int w = ws[lane];
        #pragma unroll
        for (int d = 1; d < 32; d <<= 1) {
            int y = __shfl_up_sync(0xFFFFFFFFu, w, d);
            if (lane >= d) w += y;
        }
        ws[lane] = w;
    }
    __syncthreads();
    int excl = (wid ? ws[wid - 1] : 0) + x - v + d_part[a][blockIdx.x];
    if (i < NN) {
        if (a == 0) {
            csrA_off[i] = excl;
            curA[i] = excl;
            csrA_val[excl + raw] = i;
            d_binv[i] = raw > 0 ? 1.0f / (float)raw : 0.0f;
        } else {
            csrC_off[i] = excl;
            curC[i] = excl;
            d_dinv[i] = raw > 0 ? 1.0f / (float)raw : 0.0f;
        }
    }
    if (i == NN - 1) {
        if (a == 0) csrA_off[NN] = excl + v;
        else csrC_off[NN] = excl + v;
    }
}

__global__ void fill_kernel(const int* __restrict__ ei) {
    int i = blockIdx.x * blockDim.x + threadIdx.x;
    if (i >= EE) return;
    int s = ei[i];
    int d = ei[EE + i];
    csrA_val[atomicAdd(&curA[d], 1)] = s;
    csrC_val[atomicAdd(&curC[s], 1)] = d;
}

// ---------------- merged weight conversion ----------------
#define S_W1 (FIN * 512 / 2)
#define S_W2 (256 * 512 / 2)
#define S_TH1 (334 * 128 / 2)
#define S_TH2 (128 * 128 / 2)
#define CV_TOT (S_W1 + 2 * S_W2 + S_TH1 + S_TH2 + 512 * 256 / 2)
__global__ void convert_all_kernel(const float* __restrict__ W1, const float* __restrict__ W2,
                                   const float* __restrict__ W3, const float* __restrict__ th1,
                                   const float* __restrict__ th2,
                                   const float* __restrict__ fc1w, const float* __restrict__ fc2w,
                                   const float* __restrict__ fc1b, const float* __restrict__ fc2b) {
    int i = blockIdx.x * blockDim.x + threadIdx.x;
    if (i >= CV_TOT) return;
    if (i < S_W1) {
        float2 v = ((const float2*)W1)[i];
        ((__half2*)d_w1h)[i] = __floats2half2_rn(v.x, v.y);
        return;
    }
    i -= S_W1;
    if (i < S_W2) {
        float2 v = ((const float2*)W2)[i];
        ((__half2*)d_w2h)[i] = __floats2half2_rn(v.x, v.y);
        return;
    }
    i -= S_W2;
    if (i < S_W2) {
        float2 v = ((const float2*)W3)[i];
        ((__half2*)d_w3h)[i] = __floats2half2_rn(v.x, v.y);
        return;
    }
    i -= S_W2;
    if (i < S_TH1) {
        float2 v = ((const float2*)th1)[i];
        ((__half2*)d_th1h)[i] = __floats2half2_rn(v.x, v.y);
        return;
    }
    i -= S_TH1;
    if (i < S_TH2) {
        float2 v = ((const float2*)th2)[i];
        ((__half2*)d_th2h)[i] = __floats2half2_rn(v.x, v.y);
        return;
    }
    i -= S_TH2;
    int idx = i * 2;
    int k = idx >> 8, n0 = idx & 255;
    float va = (k < 256) ? fc1w[n0 * 256 + k] : fc2w[n0 * 256 + (k - 256)];
    float vb = (k < 256) ? fc1w[(n0 + 1) * 256 + k] : fc2w[(n0 + 1) * 256 + (k - 256)];
    ((__half2*)d_bch)[i] = __floats2half2_rn(va, vb);
    if (idx < 256) {
        d_cb[idx] = fc1b[idx] + fc2b[idx];
        d_cb[idx + 1] = fc1b[idx + 1] + fc2b[idx + 1];
    }
}

__global__ void conv_mx_kernel(const float* __restrict__ x) {
    int idx = blockIdx.x * blockDim.x + threadIdx.x;
    if (idx >= NN * 40) return;
    int n = idx / 40, c2 = idx % 40;
    float a = 0.f, b = 0.f;
    int c = c2 * 2;
    if (c < FIN) a = x[(size_t)n * FIN + c];
    if (c + 1 < FIN) b = x[(size_t)n * FIN + c + 1];
    ((__half2*)d_mx16)[idx] = __floats2half2_rn(a, b);
}

// ---------------- fp16 tensor-core GEMM (m16n8k16 + ldmatrix + cp.async) ----------------
__device__ __forceinline__ void mma_f16(float* c, const uint32_t* a, uint32_t b0, uint32_t b1) {
    asm volatile(
        "mma.sync.aligned.m16n8k16.row.col.f32.f16.f16.f32 "
        "{%0,%1,%2,%3},{%4,%5,%6,%7},{%8,%9},{%0,%1,%2,%3};"
        : "+f"(c[0]), "+f"(c[1]), "+f"(c[2]), "+f"(c[3])
        : "r"(a[0]), "r"(a[1]), "r"(a[2]), "r"(a[3]), "r"(b0), "r"(b1));
}

__device__ __forceinline__ void ldsm_x4(uint32_t& r0, uint32_t& r1, uint32_t& r2, uint32_t& r3,
                                        uint32_t addr) {
    asm volatile("ldmatrix.sync.aligned.m8n8.x4.shared.b16 {%0,%1,%2,%3}, [%4];"
                 : "=r"(r0), "=r"(r1), "=r"(r2), "=r"(r3) : "r"(addr));
}

__device__ __forceinline__ void ldsm_x4t(uint32_t& r0, uint32_t& r1, uint32_t& r2, uint32_t& r3,
                                         uint32_t addr) {
    asm volatile("ldmatrix.sync.aligned.m8n8.x4.trans.shared.b16 {%0,%1,%2,%3}, [%4];"
                 : "=r"(r0), "=r"(r1), "=r"(r2), "=r"(r3) : "r"(addr));
}

__device__ __forceinline__ void cp8(uint32_t d, const void* s) {
    asm volatile("cp.async.ca.shared.global [%0], [%1], 8;" :: "r"(d), "l"(s));
}
__device__ __forceinline__ void cp8z(uint32_t d, const void* s, int sz) {
    asm volatile("cp.async.ca.shared.global [%0], [%1], 8, %2;" :: "r"(d), "l"(s), "r"(sz));
}
__device__ __forceinline__ void cp_commit() {
    asm volatile("cp.async.commit_group;");
}
template <int N>
__device__ __forceinline__ void cp_wait() {
    asm volatile("cp.async.wait_group %0;" :: "n"(N));
}

#define APITCH 80
#define BPITCH 272
#define ABYTES (128 * APITCH)
#define BBYTES (32 * BPITCH)
#define NSTAGE 3

template <int ASRC, int EPI>
__global__ __launch_bounds__(256) void gemm16_kernel(
    const void* __restrict__ Ap, int lda, int K1,
    const float* __restrict__ A2, int lda2,
    const __half* __restrict__ Hh, int ldhh,
    const __half* __restrict__ B1, const __half* __restrict__ B2, int ldb,
    int SP, int KV1, int KV2,
    float* __restrict__ Cf, int ldc,
    __half* __restrict__ Ch, int ldch,
    int M, int N, int Ktot,
    const float* __restrict__ bias, int relu, float scale,
    const float* __restrict__ molb)
{
    __shared__ __align__(16) uint8_t AsmB[NSTAGE * ABYTES];
    __shared__ __align__(16) uint8_t BsmB[NSTAGE * BBYTES];
    int tid = threadIdx.x;
    int lane = tid & 31, wid = tid >> 5;
    int wm = wid & 3, wn = wid >> 2;
    int row0 = blockIdx.y * 128, col0 = blockIdx.x * 128;
    int g = lane >> 2, tg = lane & 3;
    int l15 = lane & 15;
    int lhi = (lane & 16) ? 8 : 0;

    float acc[2][8][4];
    #pragma unroll
    for (int mi = 0; mi < 2; mi++)
        #pragma unroll
        for (int ni = 0; ni < 8; ni++)
            #pragma unroll
            for (int q = 0; q < 4; q++) acc[mi][ni][q] = 0.0f;

    const float* Af = (const float*)Ap;
    const __half* Ah = (const __half*)Ap;

    uint32_t aShm = (uint32_t)__cvta_generic_to_shared(AsmB);
    uint32_t bShm = (uint32_t)__cvta_generic_to_shared(BsmB);
    int T = (Ktot + 31) >> 5;

    auto computeTile = [&](int buf) {
        uint32_t aB = aShm + buf * ABYTES;
        uint32_t bB = bShm + buf * BBYTES;
        #pragma unroll
        for (int ks = 0; ks < 2; ks++) {
            uint32_t afr[2][4];
            #pragma unroll
            for (int mi = 0; mi < 2; mi++) {
                uint32_t addr = aB + (uint32_t)((wm * 32 + mi * 16 + l15) * APITCH
                                                + (ks * 16 + lhi) * 2);
                ldsm_x4(afr[mi][0], afr[mi][1], afr[mi][2], afr[mi][3], addr);
            }
            uint32_t bfr[8][2];
            #pragma unroll
            for (int p = 0; p < 4; p++) {
                uint32_t addr = bB + (uint32_t)((ks * 16 + l15) * BPITCH
                                                + (wn * 64 + p * 16 + lhi) * 2);
                ldsm_x4t(bfr[2 * p][0], bfr[2 * p][1], bfr[2 * p + 1][0], bfr[2 * p + 1][1], addr);
            }
            #pragma unroll
            for (int ni = 0; ni < 8; ni++) {
                mma_f16(acc[0][ni], afr[0], bfr[ni][0], bfr[ni][1]);
                mma_f16(acc[1][ni], afr[1], bfr[ni][0], bfr[ni][1]);
            }
        }
    };

    if (ASRC == 2) {
        auto issueTile = [&](int k0, int buf) {
            uint32_t aB = aShm + buf * ABYTES;
            uint32_t bB = bShm + buf * BBYTES;
            #pragma unroll
            for (int i = 0; i < 4; i++) {
                int l4 = tid + i * 256;
                int r = l4 >> 3, c4 = (l4 & 7) << 2;
                int grow = row0 + r;
                if (grow >= M) grow = M - 1;
                int gk = k0 + c4;
                cp8(aB + r * APITCH + c4 * 2, Ah + (size_t)grow * lda + gk);
            }
            #pragma unroll
            for (int i = 0; i < 4; i++) {
                int l4 = tid + i * 256;
                int k = l4 >> 5, n4 = (l4 & 31) << 2;
                int kk = k0 + k;
                const __half* src = B1;
                int sz = 0;
                if (kk < SP) {
                    if (kk < KV1) { src = B1 + (size_t)kk * ldb + col0 + n4; sz = 8; }
                } else if (kk < Ktot) {
                    int j = kk - SP;
                    if (j < KV2) { src = B2 + (size_t)j * ldb + col0 + n4; sz = 8; }
                }
                cp8z(bB + k * BPITCH + n4 * 2, src, sz);
            }
            cp_commit();
        };
        issueTile(0, 0);
        if (T > 1) issueTile(32, 1);
        for (int t = 0; t < T; t++) {
            int buf = t % NSTAGE;
            if (t + 2 < T) {
                issueTile((t + 2) << 5, (t + 2) % NSTAGE);
                cp_wait<2>();
            } else if (t + 1 < T) {
                cp_wait<1>();
            } else {
                cp_wait<0>();
            }
            __syncthreads();
            computeTile(buf);
            __syncthreads();
        }
    } else {
        float4 raf[4];
        uint2 rbh[4];
        auto loadA = [&](int k0) {
            #pragma unroll
            for (int i = 0; i < 4; i++) {
                int l4 = tid + i * 256;
                int r = l4 >> 3, c4 = (l4 & 7) << 2;
                int grow = row0 + r, gk = k0 + c4;
                float4 v = make_float4(0.f, 0.f, 0.f, 0.f);
                if (grow < M) {
                    if (gk + 3 < K1) {
                        v = *(const float4*)(Af + (size_t)grow * lda + gk);
                    } else {
                        float* pv = &v.x;
                        #pragma unroll
                        for (int j = 0; j < 4; j++) {
                            int kk = gk + j;
                            float x = 0.0f;
                            if (kk < K1) x = Af[(size_t)grow * lda + kk];
                            else if (kk < Ktot) x = A2[(size_t)grow * lda2 + (kk - K1)];
                            pv[j] = x;
                        }
                    }
                }
                raf[i] = v;
            }
        };
        auto storeA = [&](uint8_t* As) {
            #pragma unroll
            for (int i = 0; i < 4; i++) {
                int l4 = tid + i * 256;
                int r = l4 >> 3, c4 = (l4 & 7) << 2;
                __half2 h0 = __floats2half2_rn(raf[i].x, raf[i].y);
                __half2 h1 = __floats2half2_rn(raf[i].z, raf[i].w);
                uint2 u;
                u.x = *(uint32_t*)&h0;
                u.y = *(uint32_t*)&h1;
                *(uint2*)(As + r * APITCH + c4 * 2) = u;
            }
        };
        auto loadB = [&](int k0) {
            #pragma unroll
            for (int i = 0; i < 4; i++) {
                int l4 = tid + i * 256;
                int k = l4 >> 5, n4 = (l4 & 31) << 2;
                int kk = k0 + k;
                uint2 u = make_uint2(0u, 0u);
                if (kk < SP) {
                    if (kk < KV1) u = *(const uint2*)(B1 + (size_t)kk * ldb + col0 + n4);
                } else if (kk < Ktot) {
                    int j = kk - SP;
                    if (j < KV2) u = *(const uint2*)(B2 + (size_t)j * ldb + col0 + n4);
                }
                rbh[i] = u;
            }
        };
        auto storeB = [&](uint8_t* Bs) {
            #pragma unroll
            for (int i = 0; i < 4; i++) {
                int l4 = tid + i * 256;
                int k = l4 >> 5, n4 = (l4 & 31) << 2;
                *(uint2*)(Bs + k * BPITCH + n4 * 2) = rbh[i];
            }
        };
        loadA(0); loadB(0);
        storeA(AsmB); storeB(BsmB);
        __syncthreads();
        for (int t = 0; t < T; t++) {
            int buf = t & 1;
            bool more = (t + 1 < T);
            if (more) { loadA((t + 1) << 5); loadB((t + 1) << 5); }
            computeTile(buf);
            if (more) {
                storeA(AsmB + (buf ^ 1) * ABYTES);
                storeB(BsmB + (buf ^ 1) * BBYTES);
            }
            __syncthreads();
        }
    }

    // epilogue
    #pragma unroll
    for (int mi = 0; mi < 2; mi++) {
        int r0 = row0 + wm * 32 + mi * 16 + g;
        #pragma unroll
        for (int ni = 0; ni < 8; ni++) {
            int c = col0 + wn * 64 + ni * 8 + tg * 2;
            float v0 = acc[mi][ni][0], v1 = acc[mi][ni][1];
            float v2 = acc[mi][ni][2], v3 = acc[mi][ni][3];
            if (EPI == 0) {
                float b0v = bias ? bias[c] : 0.0f;
                float b1v = bias ? bias[c + 1] : 0.0f;
                v0 = v0 * scale + b0v; v1 = v1 * scale + b1v;
                v2 = v2 * scale + b0v; v3 = v3 * scale + b1v;
                if (relu) {
                    v0 = fmaxf(v0, 0.f); v1 = fmaxf(v1, 0.f);
                    v2 = fmaxf(v2, 0.f); v3 = fmaxf(v3, 0.f);
                }
                if (r0 < M) {
                    if (Cf) *(float2*)(Cf + (size_t)r0 * ldc + c) = make_float2(v0, v1);
                    if (Ch) *(__half2*)(Ch + (size_t)r0 * ldch + c) = __floats2half2_rn(v0, v1);
                }
                if (r0 + 8 < M) {
                    if (Cf) *(float2*)(Cf + (size_t)(r0 + 8) * ldc + c) = make_float2(v2, v3);
                    if (Ch) *(__half2*)(Ch + (size_t)(r0 + 8) * ldch + c) = __floats2half2_rn(v2, v3);
                }
            } else {
                const __half* Ah2 = (const __half*)Ap;
                float cb0 = bias[c] + molb[c];
                float cb1 = bias[c + 1] + molb[c + 1];
                #pragma unroll
                for (int hh = 0; hh < 2; hh++) {
                    int r = r0 + hh * 8;
                    if (r >= M) continue;
                    float va = hh ? v2 : v0, vb = hh ? v3 : v1;
                    float z0 = 1.0f / (1.0f + __expf(-(va + cb0)));
                    float z1 = 1.0f / (1.0f + __expf(-(vb + cb1)));
                    float2 xv = __half22float2(*(const __half2*)(Ah2 + (size_t)r * lda + c));
                    float2 hv = __half22float2(*(const __half2*)(Hh + (size_t)r * ldhh + c));
                    float o0 = z0 * xv.x + (1.0f - z0) * hv.x;
                    float o1 = z1 * xv.y + (1.0f - z1) * hv.y;
                    if (Cf) *(float2*)(Cf + (size_t)r * ldc + c) = make_float2(o0, o1);
                    if (Ch) *(__half2*)(Ch + (size_t)r * ldch + c) = __floats2half2_rn(o0, o1);
                }
            }
        }
    }
}

template <int ASRC, int EPI>
static void run_gemm(const void* A, int lda, int K1, const float* A2, int lda2,
                     const __half* Hh, int ldhh,
                     const __half* B1, const __half* B2, int ldb, int SP, int KV1, int KV2,
                     float* Cf, int ldc, __half* Ch, int ldch,
                     int M, int N, int Ktot,
                     const float* bias, int relu, float scale, const float* molb) {
    dim3 grid(N / 128, (M + 127) / 128);
    gemm16_kernel<ASRC, EPI><<<grid, 256>>>(
        A, lda, K1, A2, lda2, Hh, ldhh, B1, B2, ldb, SP, KV1, KV2,
        Cf, ldc, Ch, ldch, M, N, Ktot, bias, relu, scale, molb);
}

// ---------------- attention logits ----------------
// all three layers' wv in one launch; blockIdx.y = layer
__global__ void build_wv_all_kernel(const float* __restrict__ W1p,
                                    const float* __restrict__ W2p,
                                    const float* __restrict__ W3p,
                                    const float* __restrict__ as1, const float* __restrict__ ad1,
                                    const float* __restrict__ as2, const float* __restrict__ ad2,
                                    const float* __restrict__ as3, const float* __restrict__ ad3) {
    int layer = blockIdx.y;
    int k = blockIdx.x, t = threadIdx.x;
    const float* W = (layer == 0) ? W1p : (layer == 1) ? W2p : W3p;
    const float* as = (layer == 0) ? as1 : (layer == 1) ? as2 : as3;
    const float* ad = (layer == 0) ? ad1 : (layer == 1) ? ad2 : ad3;
    int K = (layer == 0) ? FIN : 256;
    if (k >= K) return;
    float w0 = W[(size_t)k * 512 + t], w1 = W[(size_t)k * 512 + 256 + t];
    float p0 = w0 * as[t], p1 = w1 * as[256 + t];
    float p2 = w0 * ad[t], p3 = w1 * ad[256 + t];
    __shared__ float red[8][4];
    int lane = t & 31, wid = t >> 5;
    #pragma unroll
    for (int d = 16; d; d >>= 1) {
        p0 += __shfl_down_sync(0xFFFFFFFFu, p0, d);
        p1 += __shfl_down_sync(0xFFFFFFFFu, p1, d);
        p2 += __shfl_down_sync(0xFFFFFFFFu, p2, d);
        p3 += __shfl_down_sync(0xFFFFFFFFu, p3, d);
    }
    if (lane == 0) { red[wid][0] = p0; red[wid][1] = p1; red[wid][2] = p2; red[wid][3] = p3; }
    __syncthreads();
    if (t == 0) {
        float r0 = 0, r1 = 0, r2 = 0, r3 = 0;
        #pragma unroll
        for (int w = 0; w < 8; w++) { r0 += red[w][0]; r1 += red[w][1]; r2 += red[w][2]; r3 += red[w][3]; }
        float* wv = d_wv3 + layer * 1024;
        wv[k * 4 + 0] = r0; wv[k * 4 + 1] = r1; wv[k * 4 + 2] = r2; wv[k * 4 + 3] = r3;
    }
}

__global__ void attn2_kernel(const float* __restrict__ x, int K, int layer) {
    int warp = threadIdx.x >> 5, lane = threadIdx.x & 31;
    int n = blockIdx.x * 4 + warp;
    if (n >= NN) return;
    const float4* wvp = (const float4*)(d_wv3 + layer * 1024);
    const float* xr = x + (size_t)n * K;
    float s0 = 0, s1 = 0, s2 = 0, s3 = 0;
    for (int c = lane; c < K; c += 32) {
        float xv = xr[c];
        float4 wv = wvp[c];
        s0 += xv * wv.x; s1 += xv * wv.y; s2 += xv * wv.z; s3 += xv * wv.w;
    }
    #pragma unroll
    for (int d = 16; d; d >>= 1) {
        s0 += __shfl_down_sync(0xFFFFFFFFu, s0, d);
        s1 += __shfl_down_sync(0xFFFFFFFFu, s1, d);
        s2 += __shfl_down_sync(0xFFFFFFFFu, s2, d);
        s3 += __shfl_down_sync(0xFFFFFFFFu, s3, d);
    }
    if (lane == 0) {
        d_asrc[n * 2] = s0; d_asrc[n * 2 + 1] = s1;
        d_adst[n * 2] = s2; d_adst[n * 2 + 1] = s3;
    }
}

__global__ void attn2h_kernel(const __half* __restrict__ x, int ldh, int layer) {
    int warp = threadIdx.x >> 5, lane = threadIdx.x & 31;
    int n = blockIdx.x * 4 + warp;
    if (n >= NN) return;
    const float4* wvp = (const float4*)(d_wv3 + layer * 1024);
    const __half2* xr = (const __half2*)(x + (size_t)n * ldh);
    float s0 = 0, s1 = 0, s2 = 0, s3 = 0;
    #pragma unroll
    for (int w = 0; w < 4; w++) {
        int c2 = lane + w * 32;
        float2 xv = __half22float2(xr[c2]);
        float4 wv0 = wvp[c2 * 2];
        float4 wv1 = wvp[c2 * 2 + 1];
        s0 += xv.x * wv0.x + xv.y * wv1.x;
        s1 += xv.x * wv0.y + xv.y * wv1.y;
        s2 += xv.x * wv0.z + xv.y * wv1.z;
        s3 += xv.x * wv0.w + xv.y * wv1.w;
    }
    #pragma unroll
    for (int d = 16; d; d >>= 1) {
        s0 += __shfl_down_sync(0xFFFFFFFFu, s0, d);
        s1 += __shfl_down_sync(0xFFFFFFFFu, s1, d);
        s2 += __shfl_down_sync(0xFFFFFFFFu, s2, d);
        s3 += __shfl_down_sync(0xFFFFFFFFu, s3, d);
    }
    if (lane == 0) {
        d_asrc[n * 2] = s0; d_asrc[n * 2 + 1] = s1;
        d_adst[n * 2] = s2; d_adst[n * 2 + 1] = s3;
    }
}

__device__ __forceinline__ float lrelu02(float v) { return v >= 0.0f ? v : 0.2f * v; }

// ---------------- fused no-max softmax + aggregate ----------------
__global__ void gat_agg80_kernel(const __half2* __restrict__ src,
                                 __half2* __restrict__ agg) {
    int n = blockIdx.x;
    int t = threadIdx.x;  // 64
    int lane = t & 31, wid = t >> 5;
    int s0 = csrA_off[n], s1 = csrA_off[n + 1];
    float2 adst = ((const float2*)d_adst)[n];
    __shared__ int ssrc[64];
    __shared__ float2 salp[64];
    __shared__ float2 ssum[2];
    float a0x = 0, a0y = 0, a1x = 0, a1y = 0, sum0 = 0, sum1 = 0;
    bool act = t < 40;
    for (int base = s0; base < s1; base += 64) {
        int cnt = min(64, s1 - base);
        __syncthreads();
        if (t < cnt) {
            int sidx = csrA_val[base + t];
            ssrc[t] = sidx;
            float2 as = ((const float2*)d_asrc)[sidx];
            float p0 = __expf(lrelu02(as.x + adst.x));
            float p1 = __expf(lrelu02(as.y + adst.y));
            salp[t] = make_float2(p0, p1);
            sum0 += p0; sum1 += p1;
        }
        __syncthreads();
        if (act) {
            #pragma unroll 2
            for (int j = 0; j < cnt; j++) {
                float2 f = __half22float2(src[(size_t)ssrc[j] * 40 + t]);
                float2 a = salp[j];
                a0x += a.x * f.x; a0y += a.x * f.y;
                a1x += a.y * f.x; a1y += a.y * f.y;
            }
        }
    }
    #pragma unroll
    for (int d = 16; d; d >>= 1) {
        sum0 += __shfl_xor_sync(0xFFFFFFFFu, sum0, d);
        sum1 += __shfl_xor_sync(0xFFFFFFFFu, sum1, d);
    }
    if (lane == 0) ssum[wid] = make_float2(sum0, sum1);
    __syncthreads();
    if (act) {
        float r0 = 1.0f / (ssum[0].x + ssum[1].x);
        float r1 = 1.0f / (ssum[0].y + ssum[1].y);
        agg[(size_t)n * 80 + t] = __floats2half2_rn(a0x * r0, a0y * r0);
        agg[(size_t)n * 80 + 40 + t] = __floats2half2_rn(a1x * r1, a1y * r1);
    }
}

__global__ void gat_agg256_kernel(const __half2* __restrict__ src, int ldh2,
                                  __half2* __restrict__ agg) {
    int n = blockIdx.x;
    int t = threadIdx.x;
    int lane = t & 31, wwid = t >> 5;
    int gid = t >> 6, tl = t & 63;
    int s0 = csrA_off[n], s1 = csrA_off[n + 1];
    float2 adst = ((const float2*)d_adst)[n];
    float h0[4] = {0, 0, 0, 0}, h1[4] = {0, 0, 0, 0};
    float sum0 = 0, sum1 = 0;
    __shared__ int ssrc[128];
    __shared__ float2 salp[128];
    __shared__ float red[64][8];
    __shared__ float2 ssum[4];
    for (int base = s0; base < s1; base += 128) {
        int cnt = min(128, s1 - base);
        __syncthreads();
        if (t < cnt) {
            int sidx = csrA_val[base + t];
            ssrc[t] = sidx;
            float2 as = ((const float2*)d_asrc)[sidx];
            float p0 = __expf(lrelu02(as.x + adst.x));
            float p1 = __expf(lrelu02(as.y + adst.y));
            salp[t] = make_float2(p0, p1);
            sum0 += p0; sum1 += p1;
        }
        __syncthreads();
        for (int j = gid; j < cnt; j += 2) {
            uint2 u = *(const uint2*)(src + (size_t)ssrc[j] * ldh2 + tl * 2);
            float2 g0 = __half22float2(*(__half2*)&u.x);
            float2 g1 = __half22float2(*(__half2*)&u.y);
            float2 a = salp[j];
            h0[0] += a.x * g0.x; h0[1] += a.x * g0.y; h0[2] += a.x * g1.x; h0[3] += a.x * g1.y;
            h1[0] += a.y * g0.x; h1[1] += a.y * g0.y; h1[2] += a.y * g1.x; h1[3] += a.y * g1.y;
        }
    }
    #pragma unroll
    for (int d = 16; d; d >>= 1) {
        sum0 += __shfl_xor_sync(0xFFFFFFFFu, sum0, d);
        sum1 += __shfl_xor_sync(0xFFFFFFFFu, sum1, d);
    }
    __syncthreads();
    if (lane == 0) ssum[wwid] = make_float2(sum0, sum1);
    if (gid == 1) {
        red[tl][0] = h0[0]; red[tl][1] = h0[1]; red[tl][2] = h0[2]; red[tl][3] = h0[3];
        red[tl][4] = h1[0]; red[tl][5] = h1[1]; red[tl][6] = h1[2]; red[tl][7] = h1[3];
    }
    __syncthreads();
    if (gid == 0) {
        float ts0 = ssum[0].x + ssum[1].x + ssum[2].x + ssum[3].x;
        float ts1 = ssum[0].y + ssum[1].y + ssum[2].y + ssum[3].y;
        float r0 = 1.0f / ts0, r1 = 1.0f / ts1;
        h0[0] += red[tl][0]; h0[1] += red[tl][1]; h0[2] += red[tl][2]; h0[3] += red[tl][3];
        h1[0] += red[tl][4]; h1[1] += red[tl][5]; h1[2] += red[tl][6]; h1[7 - 7] += 0;
        h1[0] += 0;
        h1[1] += 0;
        h1[2] += 0;
        h1[3] += red[tl][7];
        __half2* row = agg + (size_t)n * 256;
        row[tl * 2] = __floats2half2_rn(h0[0] * r0, h0[1] * r0);
        row[tl * 2 + 1] = __floats2half2_rn(h0[2] * r0, h0[3] * r0);
        row[128 + tl * 2] = __floats2half2_rn(h1[0] * r1, h1[1] * r1);
        row[128 + tl * 2 + 1] = __floats2half2_rn(h1[2] * r1, h1[3] * r1);
    }
}

// ---------------- hypergraph ----------------
template <bool OUTH>
__global__ void hyper_gather_kernel(const __half2* __restrict__ in, void* __restrict__ outp,
                                    int ostride, const float* __restrict__ bias,
                                    int which, int relu) {
    const int* off = which ? csrC_off : csrA_off;
    const int* val = which ? csrC_val : csrA_val;
    int n = blockIdx.x;
    int t = threadIdx.x;
    int gid = t >> 5, tl = t & 31;
    int s0 = off[n], s1 = off[n + 1];
    if (!which) s1 -= 1;
    float a[4] = {0, 0, 0, 0};
    __shared__ int sv[64];
    __shared__ float red[32][4];
    for (int base = s0; base < s1; base += 64) {
        int cnt = min(64, s1 - base);
        __syncthreads();
        if (t < cnt) sv[t] = val[base + t];
        __syncthreads();
        for (int j = gid; j < cnt; j += 2) {
            uint2 u = *(const uint2*)(in + (size_t)sv[j] * 64 + tl * 2);
            float2 g0 = __half22float2(*(__half2*)&u.x);
            float2 g1 = __half22float2(*(__half2*)&u.y);
            a[0] += g0.x; a[1] += g0.y; a[2] += g1.x; a[3] += g1.y;
        }
    }
    __syncthreads();
    if (gid == 1) { red[tl][0] = a[0]; red[tl][1] = a[1]; red[tl][2] = a[2]; red[tl][3] = a[3]; }
    __syncthreads();
    if (gid == 0) {
        a[0] += red[tl][0]; a[1] += red[tl][1]; a[2] += red[tl][2]; a[3] += red[tl][3];
        float inv = which ? d_dinv[n] : d_binv[n];
        #pragma unroll
        for (int q = 0; q < 4; q++) a[q] *= inv;
        if (bias) {
            a[0] += bias[tl * 4]; a[1] += bias[tl * 4 + 1];
            a[2] += bias[tl * 4 + 2]; a[3] += bias[tl * 4 + 3];
        }
        if (relu) {
            #pragma unroll
            for (int q = 0; q < 4; q++) a[q] = fmaxf(a[q], 0.f);
        }
        if (OUTH) {
            __half2* o = (__half2*)outp;
            o[(size_t)n * ostride + tl * 2] = __floats2half2_rn(a[0], a[1]);
            o[(size_t)n * ostride + tl * 2 + 1] = __floats2half2_rn(a[2], a[3]);
        } else {
            float2* o = (float2*)outp;
            o[(size_t)n * ostride + tl * 2] = make_float2(a[0], a[1]);
            o[(size_t)n * ostride + tl * 2 + 1] = make_float2(a[2], a[3]);
        }
    }
}

// ---------------- host side ----------------
extern "C" void kernel_launch(void* const* d_in, const int* in_sizes, int n_in,
                              void* d_out, int out_size) {
    const float* mol_x = (const float*)d_in[0];
    const int*   ei    = (const int*)d_in[1];
    const float* W1 = (const float*)d_in[3];
    const float* as1 = (const float*)d_in[4];
    const float* ad1 = (const float*)d_in[5];
    const float* b1 = (const float*)d_in[6];
    const float* W2 = (const float*)d_in[7];
    const float* as2 = (const float*)d_in[8];
    const float* ad2 = (const float*)d_in[9];
    const float* b2 = (const float*)d_in[10];
    const float* W3 = (const float*)d_in[11];
    const float* as3 = (const float*)d_in[12];
    const float* ad3 = (const float*)d_in[13];
    const float* b3 = (const float*)d_in[14];
    const float* fc1_w = (const float*)d_in[15];
    const float* fc1_b = (const float*)d_in[16];
    const float* fc2_w = (const float*)d_in[17];
    const float* fc2_b = (const float*)d_in[18];
    const float* mol_bias = (const float*)d_in[19];
    const float* theta1 = (const float*)d_in[20];
    const float* hb1 = (const float*)d_in[21];
    const float* theta2 = (const float*)d_in[22];
    const float* hb2 = (const float*)d_in[23];

    __half *p_mx, *p_catA, *p_catB, *p_agg, *p_xt, *p_ef, *p_hy16;
    __half *p_w1h, *p_w2h, *p_w3h, *p_bch, *p_th1h, *p_th2h;
    float *p_cb;
    cudaGetSymbolAddress((void**)&p_mx, d_mx16);
    cudaGetSymbolAddress((void**)&p_catA, d_catA);
    cudaGetSymbolAddress((void**)&p_catB, d_catB);
    cudaGetSymbolAddress((void**)&p_agg, d_agg);
    cudaGetSymbolAddress((void**)&p_xt, d_xt);
    cudaGetSymbolAddress((void**)&p_ef, d_ef);
    cudaGetSymbolAddress((void**)&p_hy16, d_hy16);
    cudaGetSymbolAddress((void**)&p_w1h, d_w1h);
    cudaGetSymbolAddress((void**)&p_w2h, d_w2h);
    cudaGetSymbolAddress((void**)&p_w3h, d_w3h);
    cudaGetSymbolAddress((void**)&p_bch, d_bch);
    cudaGetSymbolAddress((void**)&p_th1h, d_th1h);
    cudaGetSymbolAddress((void**)&p_th2h, d_th2h);
    cudaGetSymbolAddress((void**)&p_cb, d_cb);
    float* p_out = (float*)d_out;

    // side stream for the CSR-independent front-end (capture-legal fork/join)
    cudaStream_t s2;
    cudaStreamCreateWithFlags(&s2, cudaStreamNonBlocking);
    cudaEvent_t evFork, evJoin;
    cudaEventCreateWithFlags(&evFork, cudaEventDisableTiming);
    cudaEventCreateWithFlags(&evJoin, cudaEventDisableTiming);

    cudaEventRecord(evFork, 0);
    cudaStreamWaitEvent(s2, evFork, 0);

    // ---- side chain (stream s2): conversions + logit precompute + layer-1 attn ----
    conv_mx_kernel<<<(NN * 40 + 255) / 256, 256, 0, s2>>>(mol_x);
    convert_all_kernel<<<(CV_TOT + 255) / 256, 256, 0, s2>>>(W1, W2, W3, theta1, theta2,
                                                             fc1_w, fc2_w, fc1_b, fc2_b);
    build_wv_all_kernel<<<dim3(256, 3), 256, 0, s2>>>(W1, W2, W3, as1, ad1, as2, ad2, as3, ad3);
    attn2_kernel<<<(NN + 3) / 4, 128, 0, s2>>>(mol_x, FIN, 0);
    cudaEventRecord(evJoin, s2);

    // ---- main chain: CSR build ----
    zero_counts_kernel<<<(NN + 255) / 256, 256>>>();
    count_kernel<<<(EE + 255) / 256, 256>>>(ei);
    scan_p1<<<dim3(NBLK, 2), 1024>>>();
    scan_p2<<<2, 128>>>();
    scan_p3<<<dim3(NBLK, 2), 1024>>>();
    fill_kernel<<<(EE + 255) / 256, 256>>>(ei);

    cudaStreamWaitEvent(0, evJoin, 0);

    // ---- GAT layer 1: h1 (fp16) = relu(gat(mol_x)) ----
    gat_agg80_kernel<<<NN, 64>>>((const __half2*)p_mx, (__half2*)p_agg);
    run_gemm<2, 0>(p_agg, 160, 0, nullptr, 0, nullptr, 0, p_w1h, p_w1h + 256, 512, 80, FIN, FIN,
                   nullptr, 0, p_catA + 256, 512, NN, 256, 160, b1, 1, 0.5f, nullptr);

    // ---- GAT layer 2 ----
    attn2h_kernel<<<(NN + 3) / 4, 128>>>(p_catA + 256, 512, 1);
    gat_agg256_kernel<<<NN, 128>>>((const __half2*)(p_catA + 256), 256, (__half2*)p_agg);
    run_gemm<2, 0>(p_agg, 512, 0, nullptr, 0, nullptr, 0, p_w2h, p_w2h + 256, 512, 256, 256, 256,
                   nullptr, 0, p_catA, 512, NN, 256, 512, b2, 1, 0.5f, nullptr);
    run_gemm<2, 2>(p_catA, 512, 0, nullptr, 0, p_catA + 256, 512, p_bch, nullptr, 256, 512, 512, 0,
                   nullptr, 0, p_catB + 256, 512, NN, 256, 512, p_cb, 0, 1.0f, mol_bias);

    // ---- GAT layer 3 ----
    attn2h_kernel<<<(NN + 3) / 4, 128>>>(p_catB + 256, 512, 2);
    gat_agg256_kernel<<<NN, 128>>>((const __half2*)(p_catB + 256), 256, (__half2*)p_agg);
    run_gemm<2, 0>(p_agg, 512, 0, nullptr, 0, nullptr, 0, p_w3h, p_w3h + 256, 512, 256, 256, 256,
                   nullptr, 0, p_catB, 512, NN, 256, 512, b3, 0, 0.5f, nullptr);
    run_gemm<2, 2>(p_catB, 512, 0, nullptr, 0, p_catB + 256, 512, p_bch, nullptr, 256, 512, 512, 0,
                   p_out, 384, nullptr, 0, NN, 256, 512, p_cb, 0, 1.0f, mol_bias);

    // ---- hypergraph branch ----
    run_gemm<0, 0>(p_out, 384, 256, mol_x, FIN, nullptr, 0, p_th1h, nullptr, 128, 334, 334, 0,
                   nullptr, 0, p_xt, 128, NN, 128, 334, nullptr, 0, 1.0f, nullptr);
    hyper_gather_kernel<true ><<<NN, 64>>>((const __half2*)p_xt, p_ef, 64, nullptr, 0, 0);
    hyper_gather_kernel<true ><<<NN, 64>>>((const __half2*)p_ef, p_hy16, 64, hb1, 1, 1);
    run_gemm<2, 0>(p_hy16, 128, 0, nullptr, 0, nullptr, 0, p_th2h, nullptr, 128, 128, 128, 0,
                   nullptr, 0, p_xt, 128, NN, 128, 128, nullptr, 0, 1.0f, nullptr);
    hyper_gather_kernel<true ><<<NN, 64>>>((const __half2*)p_xt, p_ef, 64, nullptr, 0, 0);
    hyper_gather_kernel<false><<<NN, 64>>>((const __half2*)p_ef, (float2*)p_out + 128, 192,
                                           hb2, 1, 1);
}